// round 1
// baseline (speedup 1.0000x reference)
#include <cuda_runtime.h>
#include <math.h>

#define BB   1024
#define TT   133
#define DD   256
#define EE   512
#define SSZ  128
#define MTOT (BB*TT)          /* 136192, divisible by 128 */
#define NUV  (2*EE+SSZ)       /* 1152 */
#define PSTR 136              /* padded P row stride (float4-aligned) */
#define EPSV 1e-5f
#define INV_SQRT_S 0.08838834764831845f  /* 1/sqrt(128) */

/* -------- scratch (device globals; no allocation calls allowed) -------- */
__device__ float g_s[MTOT];                       /* per-token norm scale   */
__device__ float g_u[(size_t)MTOT * EE];          /* u                      */
__device__ float g_v[(size_t)MTOT * EE];          /* v                      */
__device__ float g_q[(size_t)MTOT * SSZ];         /* q                      */
__device__ float g_k[(size_t)MTOT * SSZ];         /* k                      */
__device__ float g_p[(size_t)BB * TT * PSTR];     /* relu(scores)^2, padded */
__device__ float g_w[(size_t)MTOT * EE];          /* u * attn               */

/* ===================== K0: per-token norm scale ===================== */
__global__ void k_norm(const float* __restrict__ x, const float* __restrict__ g)
{
    const int token = blockIdx.x * 8 + (threadIdx.x >> 5);
    const int lane  = threadIdx.x & 31;
    const float* xp = x + (size_t)token * DD;
    float sum = 0.f;
    #pragma unroll
    for (int i = lane; i < DD; i += 32) { float v = xp[i]; sum = fmaf(v, v, sum); }
    #pragma unroll
    for (int o = 16; o; o >>= 1) sum += __shfl_xor_sync(0xFFFFFFFFu, sum, o);
    if (lane == 0) {
        float norm = sqrtf(sum * (1.f / (float)DD));
        g_s[token] = g[0] / fmaxf(norm, EPSV);
    }
}

/* ===================== K1: uv = silu(xn @ W_uv^T), split u/v/q/k =====
 * GEMM M=136192, N=1152, K=256.  128x128x8 tiles, 256 thr, 8x8 microtile. */
__global__ __launch_bounds__(256) void k_uv(
    const float* __restrict__ x, const float* __restrict__ W,
    const float* __restrict__ gamma, const float* __restrict__ beta)
{
    __shared__ float As[8][128];
    __shared__ float Bs[8][128];
    const int m0 = blockIdx.x * 128, n0 = blockIdx.y * 128;
    const int tid  = threadIdx.x;
    const int rowL = tid >> 1, colL = (tid & 1) << 2;
    const float sA = g_s[m0 + rowL];
    const float* Ap = x + (size_t)(m0 + rowL) * DD + colL;
    const float* Bp = W + (size_t)(n0 + rowL) * DD + colL;
    const int tr = (tid >> 4) << 3, tc = (tid & 15) << 3;
    float acc[8][8] = {};

    for (int kt = 0; kt < DD; kt += 8) {
        float4 a = *(const float4*)(Ap + kt);
        float4 b = *(const float4*)(Bp + kt);
        As[colL + 0][rowL] = a.x * sA; As[colL + 1][rowL] = a.y * sA;
        As[colL + 2][rowL] = a.z * sA; As[colL + 3][rowL] = a.w * sA;
        Bs[colL + 0][rowL] = b.x;      Bs[colL + 1][rowL] = b.y;
        Bs[colL + 2][rowL] = b.z;      Bs[colL + 3][rowL] = b.w;
        __syncthreads();
        #pragma unroll
        for (int kk = 0; kk < 8; kk++) {
            float rm[8], rn[8];
            #pragma unroll
            for (int i = 0; i < 8; i++) rm[i] = As[kk][tr + i];
            #pragma unroll
            for (int j = 0; j < 8; j++) rn[j] = Bs[kk][tc + j];
            #pragma unroll
            for (int i = 0; i < 8; i++)
                #pragma unroll
                for (int j = 0; j < 8; j++)
                    acc[i][j] = fmaf(rm[i], rn[j], acc[i][j]);
        }
        __syncthreads();
    }

    #pragma unroll
    for (int i = 0; i < 8; i++) {
        const size_t m = (size_t)(m0 + tr + i);
        #pragma unroll
        for (int j = 0; j < 8; j++) {
            const int n = n0 + tc + j;
            float val = acc[i][j];
            val = val / (1.f + __expf(-val));          /* silu */
            if (n < EE)            g_u[m * EE + n] = val;
            else if (n < 2 * EE)   g_v[m * EE + (n - EE)] = val;
            else {
                const int s = n - 2 * EE;
                g_q[m * SSZ + s] = fmaf(val, gamma[s],       beta[s]);
                g_k[m * SSZ + s] = fmaf(val, gamma[SSZ + s], beta[SSZ + s]);
            }
        }
    }
}

/* ===================== K2: P = relu(q k^T / sqrt(S))^2  (batched) =====
 * Per batch: 133x133x128.  64x64x16 tiles, 256 thr, 4x4 microtile. */
__global__ __launch_bounds__(256) void k_scores()
{
    __shared__ float As[16][64];
    __shared__ float Bs[16][64];
    const int b  = blockIdx.z;
    const int i0 = blockIdx.y * 64, j0 = blockIdx.x * 64;
    const int tid  = threadIdx.x;
    const int rowL = tid >> 2, colL = (tid & 3) << 2;
    const size_t base = (size_t)b * TT * SSZ;
    const int tr = (tid >> 4) << 2, tc = (tid & 15) << 2;
    float acc[4][4] = {};

    for (int kt = 0; kt < SSZ; kt += 16) {
        float4 a = (i0 + rowL < TT)
            ? *(const float4*)(g_q + base + (size_t)(i0 + rowL) * SSZ + kt + colL)
            : make_float4(0, 0, 0, 0);
        float4 bb = (j0 + rowL < TT)
            ? *(const float4*)(g_k + base + (size_t)(j0 + rowL) * SSZ + kt + colL)
            : make_float4(0, 0, 0, 0);
        As[colL + 0][rowL] = a.x;  As[colL + 1][rowL] = a.y;
        As[colL + 2][rowL] = a.z;  As[colL + 3][rowL] = a.w;
        Bs[colL + 0][rowL] = bb.x; Bs[colL + 1][rowL] = bb.y;
        Bs[colL + 2][rowL] = bb.z; Bs[colL + 3][rowL] = bb.w;
        __syncthreads();
        #pragma unroll
        for (int kk = 0; kk < 16; kk++) {
            float rm[4], rn[4];
            #pragma unroll
            for (int i = 0; i < 4; i++) rm[i] = As[kk][tr + i];
            #pragma unroll
            for (int j = 0; j < 4; j++) rn[j] = Bs[kk][tc + j];
            #pragma unroll
            for (int i = 0; i < 4; i++)
                #pragma unroll
                for (int j = 0; j < 4; j++)
                    acc[i][j] = fmaf(rm[i], rn[j], acc[i][j]);
        }
        __syncthreads();
    }

    #pragma unroll
    for (int ii = 0; ii < 4; ii++) {
        const int i = i0 + tr + ii;
        if (i >= TT) continue;
        #pragma unroll
        for (int jj = 0; jj < 4; jj++) {
            const int j = j0 + tc + jj;
            if (j >= PSTR) continue;               /* pad cols 133..135 get 0 */
            float sc = fmaxf(acc[ii][jj] * INV_SQRT_S, 0.f);
            g_p[((size_t)b * TT + i) * PSTR + j] = sc * sc;
        }
    }
}

/* ===================== K3: w = u * (P @ v)  (batched) =====
 * Per batch: 133x512x133.  64x64x16 tiles. */
__global__ __launch_bounds__(256) void k_attn()
{
    __shared__ float As[16][64];
    __shared__ float Bs[16][64];
    const int b  = blockIdx.z;
    const int e0 = blockIdx.x * 64, i0 = blockIdx.y * 64;
    const int tid  = threadIdx.x;
    const int rowA = tid >> 2,  colA = (tid & 3) << 2;     /* A: 64 x 16 */
    const int rowB = tid >> 4,  colB = (tid & 15) << 2;    /* B: 16 x 64 */
    const size_t pbase = (size_t)b * TT * PSTR;
    const size_t vbase = (size_t)b * TT * EE;
    const int tr = (tid >> 4) << 2, tc = (tid & 15) << 2;
    float acc[4][4] = {};

    for (int kt = 0; kt < TT; kt += 16) {
        /* pad cols of P are zeros; over-read past col 136 is multiplied by
           zero v rows (j >= 133) and stays inside the allocation. */
        float4 a = (i0 + rowA < TT)
            ? *(const float4*)(g_p + pbase + (size_t)(i0 + rowA) * PSTR + kt + colA)
            : make_float4(0, 0, 0, 0);
        float4 bb = (kt + rowB < TT)
            ? *(const float4*)(g_v + vbase + (size_t)(kt + rowB) * EE + e0 + colB)
            : make_float4(0, 0, 0, 0);
        As[colA + 0][rowA] = a.x; As[colA + 1][rowA] = a.y;
        As[colA + 2][rowA] = a.z; As[colA + 3][rowA] = a.w;
        Bs[rowB][colB + 0] = bb.x; Bs[rowB][colB + 1] = bb.y;
        Bs[rowB][colB + 2] = bb.z; Bs[rowB][colB + 3] = bb.w;
        __syncthreads();
        #pragma unroll
        for (int kk = 0; kk < 16; kk++) {
            float rm[4], rn[4];
            #pragma unroll
            for (int i = 0; i < 4; i++) rm[i] = As[kk][tr + i];
            #pragma unroll
            for (int j = 0; j < 4; j++) rn[j] = Bs[kk][tc + j];
            #pragma unroll
            for (int i = 0; i < 4; i++)
                #pragma unroll
                for (int j = 0; j < 4; j++)
                    acc[i][j] = fmaf(rm[i], rn[j], acc[i][j]);
        }
        __syncthreads();
    }

    #pragma unroll
    for (int ii = 0; ii < 4; ii++) {
        const int i = i0 + tr + ii;
        if (i >= TT) continue;
        const size_t m = (size_t)b * TT + i;
        #pragma unroll
        for (int jj = 0; jj < 4; jj++) {
            const int e = e0 + tc + jj;
            g_w[m * EE + e] = g_u[m * EE + e] * acc[ii][jj];
        }
    }
}

/* ===================== K4: out = w @ W_o^T + x * res_scale =====
 * GEMM M=136192, N=256, K=512.  Same structure as K1. */
__global__ __launch_bounds__(256) void k_out(
    const float* __restrict__ x, const float* __restrict__ Wo,
    const float* __restrict__ res_scale, float* __restrict__ out)
{
    __shared__ float As[8][128];
    __shared__ float Bs[8][128];
    const int m0 = blockIdx.x * 128, n0 = blockIdx.y * 128;
    const int tid  = threadIdx.x;
    const int rowL = tid >> 1, colL = (tid & 1) << 2;
    const float* Ap = g_w + (size_t)(m0 + rowL) * EE + colL;
    const float* Bp = Wo  + (size_t)(n0 + rowL) * EE + colL;
    const int tr = (tid >> 4) << 3, tc = (tid & 15) << 3;
    float acc[8][8] = {};

    for (int kt = 0; kt < EE; kt += 8) {
        float4 a = *(const float4*)(Ap + kt);
        float4 b = *(const float4*)(Bp + kt);
        As[colL + 0][rowL] = a.x; As[colL + 1][rowL] = a.y;
        As[colL + 2][rowL] = a.z; As[colL + 3][rowL] = a.w;
        Bs[colL + 0][rowL] = b.x; Bs[colL + 1][rowL] = b.y;
        Bs[colL + 2][rowL] = b.z; Bs[colL + 3][rowL] = b.w;
        __syncthreads();
        #pragma unroll
        for (int kk = 0; kk < 8; kk++) {
            float rm[8], rn[8];
            #pragma unroll
            for (int i = 0; i < 8; i++) rm[i] = As[kk][tr + i];
            #pragma unroll
            for (int j = 0; j < 8; j++) rn[j] = Bs[kk][tc + j];
            #pragma unroll
            for (int i = 0; i < 8; i++)
                #pragma unroll
                for (int j = 0; j < 8; j++)
                    acc[i][j] = fmaf(rm[i], rn[j], acc[i][j]);
        }
        __syncthreads();
    }

    #pragma unroll
    for (int i = 0; i < 8; i++) {
        const size_t m = (size_t)(m0 + tr + i);
        #pragma unroll
        for (int j = 0; j < 8; j++) {
            const int n = n0 + tc + j;
            out[m * DD + n] = fmaf(x[m * DD + n], res_scale[n], acc[i][j]);
        }
    }
}

/* ===================== launch ===================== */
extern "C" void kernel_launch(void* const* d_in, const int* in_sizes, int n_in,
                              void* d_out, int out_size)
{
    const float* x         = (const float*)d_in[0];
    const float* W_uv      = (const float*)d_in[1];
    const float* W_o       = (const float*)d_in[2];
    const float* gamma     = (const float*)d_in[3];
    const float* beta      = (const float*)d_in[4];
    const float* g         = (const float*)d_in[5];
    const float* res_scale = (const float*)d_in[6];
    float* out = (float*)d_out;

    k_norm  <<<MTOT / 8, 256>>>(x, g);
    k_uv    <<<dim3(MTOT / 128, NUV / 128), 256>>>(x, W_uv, gamma, beta);
    k_scores<<<dim3(3, 3, BB), 256>>>();
    k_attn  <<<dim3(EE / 64, 3, BB), 256>>>();
    k_out   <<<dim3(MTOT / 128, DD / 128), 256>>>(x, W_o, res_scale, out);
}

// round 6
// speedup vs baseline: 1.8259x; 1.8259x over previous
#include <cuda_runtime.h>
#include <cuda_fp16.h>
#include <cstdint>
#include <math.h>

#define BB   1024
#define TT   133
#define DD   256
#define EE   512
#define SSZ  128
#define MTOT (BB*TT)          /* 136192 */
#define PSTR 136
#define EPSV 1e-5f
#define INV_SQRT_S 0.08838834764831845f

/* -------- scratch (device globals, 16B-aligned) -------- */
__device__ __align__(16) float  g_u[(size_t)MTOT * EE];
__device__ __align__(16) float  g_v[(size_t)MTOT * EE];
__device__ __align__(16) float  g_q[(size_t)MTOT * SSZ];
__device__ __align__(16) float  g_k[(size_t)MTOT * SSZ];
__device__ __align__(16) float  g_p[(size_t)BB * TT * PSTR];
__device__ __align__(16) __half g_xh[(size_t)MTOT * DD];
__device__ __align__(16) __half g_xl[(size_t)MTOT * DD];
__device__ __align__(16) __half g_wwh[(size_t)MTOT * EE];
__device__ __align__(16) __half g_wwl[(size_t)MTOT * EE];
__device__ __align__(16) __half g_wuvh[1152 * DD];
__device__ __align__(16) __half g_wuvl[1152 * DD];
__device__ __align__(16) __half g_woh[DD * EE];
__device__ __align__(16) __half g_wol[DD * EE];

/* ================= helpers ================= */
__device__ __forceinline__ uint32_t smem_u32(const void* p) {
    uint32_t a;
    asm("{ .reg .u64 t; cvta.to.shared.u64 t, %1; cvt.u32.u64 %0, t; }" : "=r"(a) : "l"(p));
    return a;
}
#define CPA16(dst, src) asm volatile("cp.async.cg.shared.global [%0], [%1], 16;" \
    :: "r"(dst), "l"(__cvta_generic_to_global(src)))
#define CPC()  asm volatile("cp.async.commit_group;")
#define CPW1() asm volatile("cp.async.wait_group 1;")
#define CPW0() asm volatile("cp.async.wait_group 0;")

__device__ __forceinline__ void ldsm4(uint32_t* r, uint32_t addr) {
    asm volatile("ldmatrix.sync.aligned.m8n8.x4.shared.b16 {%0,%1,%2,%3}, [%4];"
                 : "=r"(r[0]), "=r"(r[1]), "=r"(r[2]), "=r"(r[3]) : "r"(addr));
}
__device__ __forceinline__ void mma16816(float* d, const uint32_t* a,
                                         uint32_t b0, uint32_t b1) {
    asm volatile("mma.sync.aligned.m16n8k16.row.col.f32.f16.f16.f32 "
                 "{%0,%1,%2,%3}, {%4,%5,%6,%7}, {%8,%9}, {%0,%1,%2,%3};"
                 : "+f"(d[0]), "+f"(d[1]), "+f"(d[2]), "+f"(d[3])
                 : "r"(a[0]), "r"(a[1]), "r"(a[2]), "r"(a[3]), "r"(b0), "r"(b1));
}
__device__ __forceinline__ float silu(float v) { return v / (1.f + __expf(-v)); }

__device__ __forceinline__ uint32_t fsplit2(float a, float b, uint32_t& lo) {
    __half ha = __float2half(a), hb = __float2half(b);
    __half la = __float2half(a - __half2float(ha));
    __half lb = __float2half(b - __half2float(hb));
    __half2 hh = __halves2half2(ha, hb);
    __half2 ll = __halves2half2(la, lb);
    lo = reinterpret_cast<uint32_t&>(ll);
    return reinterpret_cast<uint32_t&>(hh);
}

/* smem: one stage = Ah|Al|Bh|Bl, each 128 rows x 16 halves (32B/row) = 4096B.
 * Stage = 16KB, double buffered = 32KB static shared. */
#define TILE16 4096
struct SmemStage { char Ah[TILE16]; char Al[TILE16]; char Bh[TILE16]; char Bl[TILE16]; };

/* ===================== generic fp16-split GEMM core =====================
 * 128x128 CTA tile, 8 warps (2m x 4n), each warp 64x32, BK=16, double buf. */
template<int NCH>
__device__ __forceinline__ void gemm_core(
    const __half* gAh, const __half* gAl, const __half* gBh, const __half* gBl,
    int lda, int ldb, SmemStage* stg, float acc[4][4][4])
{
    const int tid = threadIdx.x, wid = tid >> 5, lane = tid & 31;
    const int wm = (wid >> 2) * 64, wn = (wid & 3) * 32;
    const int r = tid >> 1, hb = (tid & 1) * 16;   /* byte 0/16 within row */
    const uint32_t s0 = smem_u32(&stg[0]);
    const uint32_t s1 = smem_u32(&stg[1]);

    auto load = [&](int kc, int s) {
        const uint32_t da = (s ? s1 : s0) + r * 32 + hb;
        const int kofs = kc * 16 + (hb >> 1);
        CPA16(da,             gAh + (size_t)r * lda + kofs);
        CPA16(da + TILE16,    gAl + (size_t)r * lda + kofs);
        CPA16(da + 2*TILE16,  gBh + (size_t)r * ldb + kofs);
        CPA16(da + 3*TILE16,  gBl + (size_t)r * ldb + kofs);
    };

    load(0, 0); CPC();

    #pragma unroll 1
    for (int c = 0; c < NCH; c++) {
        const int s = c & 1;
        if (c + 1 < NCH) { load(c + 1, 1 - s); CPC(); CPW1(); }
        else             { CPW0(); }
        __syncthreads();

        const uint32_t base = s ? s1 : s0;
        const uint32_t boff = base + 2 * TILE16;

        uint32_t bh[8], bl[8];
        const int brow = wn + ((lane >> 4) & 1) * 8 + (lane & 7);
        const int bcolb = ((lane >> 3) & 1) * 16;
        const uint32_t ba0 = boff + brow * 32 + bcolb;
        const uint32_t ba1 = ba0 + 16 * 32;
        ldsm4(bh,     ba0);          ldsm4(bh + 4, ba1);
        ldsm4(bl,     ba0 + TILE16); ldsm4(bl + 4, ba1 + TILE16);

        const int arow = wm + (lane & 15);
        const uint32_t acolb = (lane >> 4) * 16;
        #pragma unroll
        for (int mi = 0; mi < 4; mi++) {
            uint32_t ah[4], al[4];
            const uint32_t aa = base + (arow + mi * 16) * 32 + acolb;
            ldsm4(ah, aa); ldsm4(al, aa + TILE16);
            #pragma unroll
            for (int ni = 0; ni < 4; ni++) {
                mma16816(acc[mi][ni], ah, bh[2 * ni], bh[2 * ni + 1]);
                mma16816(acc[mi][ni], ah, bl[2 * ni], bl[2 * ni + 1]);
                mma16816(acc[mi][ni], al, bh[2 * ni], bh[2 * ni + 1]);
            }
        }
        __syncthreads();
    }
}

/* ===================== K0: fused norm + fp16 split of xn ===================== */
__global__ __launch_bounds__(256) void k_norm_cvt(
    const float* __restrict__ x, const float* __restrict__ g)
{
    const int token = blockIdx.x * 8 + (threadIdx.x >> 5);
    const int lane  = threadIdx.x & 31;
    const float4* xp = (const float4*)(x + (size_t)token * DD);
    float4 v0 = xp[lane], v1 = xp[lane + 32];
    float sum = v0.x * v0.x + v0.y * v0.y + v0.z * v0.z + v0.w * v0.w
              + v1.x * v1.x + v1.y * v1.y + v1.z * v1.z + v1.w * v1.w;
    #pragma unroll
    for (int o = 16; o; o >>= 1) sum += __shfl_xor_sync(0xFFFFFFFFu, sum, o);
    float norm = sqrtf(sum * (1.f / (float)DD));
    float s = g[0] / fmaxf(norm, EPSV);

    uint2 h0, l0, h1, l1;
    h0.x = fsplit2(v0.x * s, v0.y * s, l0.x);
    h0.y = fsplit2(v0.z * s, v0.w * s, l0.y);
    h1.x = fsplit2(v1.x * s, v1.y * s, l1.x);
    h1.y = fsplit2(v1.z * s, v1.w * s, l1.y);
    const size_t base = (size_t)token * DD + lane * 4;
    *(uint2*)(g_xh + base)       = h0;
    *(uint2*)(g_xl + base)       = l0;
    *(uint2*)(g_xh + base + 128) = h1;
    *(uint2*)(g_xl + base + 128) = l1;
}

/* ===================== weight fp16 split =====================
 * FIX: destination arrays selected IN DEVICE CODE (never pass __device__
 * symbols as kernel arguments from host — on GB300/ATS those host shadow
 * addresses are silently writable host memory, not the device arrays). */
__global__ __launch_bounds__(256) void k_cvt_sel(
    const float* __restrict__ src, int which, int n4)
{
    __half* hi; __half* lo;
    if (which == 0) { hi = g_wuvh; lo = g_wuvl; }
    else            { hi = g_woh;  lo = g_wol;  }
    const int i = blockIdx.x * 256 + threadIdx.x;
    if (i >= n4) return;
    float4 v = ((const float4*)src)[i];
    uint2 h, l;
    h.x = fsplit2(v.x, v.y, l.x);
    h.y = fsplit2(v.z, v.w, l.y);
    *(uint2*)(hi + (size_t)i * 4) = h;
    *(uint2*)(lo + (size_t)i * 4) = l;
}

/* ===================== K1: uv GEMM (M x 1152 x 256) ===================== */
__global__ __launch_bounds__(256) void k_uv_mma(
    const float* __restrict__ gamma, const float* __restrict__ beta)
{
    __shared__ SmemStage stg[2];
    const int m0 = blockIdx.x * 128, by = blockIdx.y;
    float acc[4][4][4] = {};
    gemm_core<16>(g_xh + (size_t)m0 * DD, g_xl + (size_t)m0 * DD,
                  g_wuvh + (size_t)by * 128 * DD, g_wuvl + (size_t)by * 128 * DD,
                  DD, DD, stg, acc);

    const int tid = threadIdx.x, wid = tid >> 5, lane = tid & 31;
    const int wm = (wid >> 2) * 64, wn = (wid & 3) * 32;
    const int gid2 = lane >> 2, tig = lane & 3;
    #pragma unroll
    for (int mi = 0; mi < 4; mi++) {
        #pragma unroll
        for (int ni = 0; ni < 4; ni++) {
            const float* a = acc[mi][ni];
            const int nl = wn + ni * 8 + tig * 2;
            const int mr = m0 + wm + mi * 16 + gid2;
            if (by < 8) {
                float* dst; int col;
                if (by < 4) { dst = g_u; col = by * 128 + nl; }
                else        { dst = g_v; col = (by - 4) * 128 + nl; }
                float2 o0 = {silu(a[0]), silu(a[1])};
                float2 o1 = {silu(a[2]), silu(a[3])};
                *(float2*)(dst + (size_t)mr * EE + col)       = o0;
                *(float2*)(dst + (size_t)(mr + 8) * EE + col) = o1;
            } else {
                const float ga0 = gamma[nl], ga1 = gamma[nl + 1];
                const float gb0 = gamma[SSZ + nl], gb1 = gamma[SSZ + nl + 1];
                const float ba0 = beta[nl],  ba1 = beta[nl + 1];
                const float bb0 = beta[SSZ + nl], bb1 = beta[SSZ + nl + 1];
                float v0 = silu(a[0]), v1 = silu(a[1]);
                float2 q0 = {fmaf(v0, ga0, ba0), fmaf(v1, ga1, ba1)};
                float2 k0 = {fmaf(v0, gb0, bb0), fmaf(v1, gb1, bb1)};
                *(float2*)(g_q + (size_t)mr * SSZ + nl) = q0;
                *(float2*)(g_k + (size_t)mr * SSZ + nl) = k0;
                float v2 = silu(a[2]), v3 = silu(a[3]);
                float2 q1 = {fmaf(v2, ga0, ba0), fmaf(v3, ga1, ba1)};
                float2 k1 = {fmaf(v2, gb0, bb0), fmaf(v3, gb1, bb1)};
                *(float2*)(g_q + (size_t)(mr + 8) * SSZ + nl) = q1;
                *(float2*)(g_k + (size_t)(mr + 8) * SSZ + nl) = k1;
            }
        }
    }
}

/* ===================== K2: P = relu(q k^T / sqrt(S))^2 ===================== */
__global__ __launch_bounds__(256) void k_scores()
{
    __shared__ float As[16][64];
    __shared__ float Bs[16][64];
    const int b  = blockIdx.z;
    const int i0 = blockIdx.y * 64, j0 = blockIdx.x * 64;
    const int tid  = threadIdx.x;
    const int rowL = tid >> 2, colL = (tid & 3) << 2;
    const size_t base = (size_t)b * TT * SSZ;
    const int tr = (tid >> 4) << 2, tc = (tid & 15) << 2;
    float acc[4][4] = {};

    for (int kt = 0; kt < SSZ; kt += 16) {
        float4 a = (i0 + rowL < TT)
            ? *(const float4*)(g_q + base + (size_t)(i0 + rowL) * SSZ + kt + colL)
            : make_float4(0, 0, 0, 0);
        float4 bb = (j0 + rowL < TT)
            ? *(const float4*)(g_k + base + (size_t)(j0 + rowL) * SSZ + kt + colL)
            : make_float4(0, 0, 0, 0);
        As[colL + 0][rowL] = a.x;  As[colL + 1][rowL] = a.y;
        As[colL + 2][rowL] = a.z;  As[colL + 3][rowL] = a.w;
        Bs[colL + 0][rowL] = bb.x; Bs[colL + 1][rowL] = bb.y;
        Bs[colL + 2][rowL] = bb.z; Bs[colL + 3][rowL] = bb.w;
        __syncthreads();
        #pragma unroll
        for (int kk = 0; kk < 16; kk++) {
            float rm[4], rn[4];
            #pragma unroll
            for (int i = 0; i < 4; i++) rm[i] = As[kk][tr + i];
            #pragma unroll
            for (int j = 0; j < 4; j++) rn[j] = Bs[kk][tc + j];
            #pragma unroll
            for (int i = 0; i < 4; i++)
                #pragma unroll
                for (int j = 0; j < 4; j++)
                    acc[i][j] = fmaf(rm[i], rn[j], acc[i][j]);
        }
        __syncthreads();
    }

    #pragma unroll
    for (int ii = 0; ii < 4; ii++) {
        const int i = i0 + tr + ii;
        if (i >= TT) continue;
        #pragma unroll
        for (int jj = 0; jj < 4; jj++) {
            const int j = j0 + tc + jj;
            if (j >= PSTR) continue;
            float sc = fmaxf(acc[ii][jj] * INV_SQRT_S, 0.f);
            g_p[((size_t)b * TT + i) * PSTR + j] = sc * sc;
        }
    }
}

/* ===================== K3: w = u * (P @ v) -> fp16 hi/lo ===================== */
__global__ __launch_bounds__(256) void k_attn()
{
    __shared__ float As[16][64];
    __shared__ float Bs[16][64];
    const int b  = blockIdx.z;
    const int e0 = blockIdx.x * 64, i0 = blockIdx.y * 64;
    const int tid  = threadIdx.x;
    const int rowA = tid >> 2,  colA = (tid & 3) << 2;
    const int rowB = tid >> 4,  colB = (tid & 15) << 2;
    const size_t pbase = (size_t)b * TT * PSTR;
    const size_t vbase = (size_t)b * TT * EE;
    const int tr = (tid >> 4) << 2, tc = (tid & 15) << 2;
    float acc[4][4] = {};

    for (int kt = 0; kt < TT; kt += 16) {
        float4 a = (i0 + rowA < TT)
            ? *(const float4*)(g_p + pbase + (size_t)(i0 + rowA) * PSTR + kt + colA)
            : make_float4(0, 0, 0, 0);
        float4 bb = (kt + rowB < TT)
            ? *(const float4*)(g_v + vbase + (size_t)(kt + rowB) * EE + e0 + colB)
            : make_float4(0, 0, 0, 0);
        As[colA + 0][rowA] = a.x; As[colA + 1][rowA] = a.y;
        As[colA + 2][rowA] = a.z; As[colA + 3][rowA] = a.w;
        Bs[rowB][colB + 0] = bb.x; Bs[rowB][colB + 1] = bb.y;
        Bs[rowB][colB + 2] = bb.z; Bs[rowB][colB + 3] = bb.w;
        __syncthreads();
        #pragma unroll
        for (int kk = 0; kk < 16; kk++) {
            float rm[4], rn[4];
            #pragma unroll
            for (int i = 0; i < 4; i++) rm[i] = As[kk][tr + i];
            #pragma unroll
            for (int j = 0; j < 4; j++) rn[j] = Bs[kk][tc + j];
            #pragma unroll
            for (int i = 0; i < 4; i++)
                #pragma unroll
                for (int j = 0; j < 4; j++)
                    acc[i][j] = fmaf(rm[i], rn[j], acc[i][j]);
        }
        __syncthreads();
    }

    #pragma unroll
    for (int ii = 0; ii < 4; ii++) {
        const int i = i0 + tr + ii;
        if (i >= TT) continue;
        const size_t m = (size_t)b * TT + i;
        #pragma unroll
        for (int jj = 0; jj < 4; jj++) {
            const int e = e0 + tc + jj;
            float wv = g_u[m * EE + e] * acc[ii][jj];
            __half h = __float2half(wv);
            __half l = __float2half(wv - __half2float(h));
            g_wwh[m * EE + e] = h;
            g_wwl[m * EE + e] = l;
        }
    }
}

/* ===================== K4: out GEMM (M x 256 x 512) + residual ============ */
__global__ __launch_bounds__(256) void k_out_mma(
    const float* __restrict__ x, const float* __restrict__ res_scale,
    float* __restrict__ out)
{
    __shared__ SmemStage stg[2];
    const int m0 = blockIdx.x * 128, by = blockIdx.y;
    float acc[4][4][4] = {};
    gemm_core<32>(g_wwh + (size_t)m0 * EE, g_wwl + (size_t)m0 * EE,
                  g_woh + (size_t)by * 128 * EE, g_wol + (size_t)by * 128 * EE,
                  EE, EE, stg, acc);

    const int tid = threadIdx.x, wid = tid >> 5, lane = tid & 31;
    const int wm = (wid >> 2) * 64, wn = (wid & 3) * 32;
    const int gid2 = lane >> 2, tig = lane & 3;
    #pragma unroll
    for (int mi = 0; mi < 4; mi++) {
        #pragma unroll
        for (int ni = 0; ni < 4; ni++) {
            const float* a = acc[mi][ni];
            const int col = by * 128 + wn + ni * 8 + tig * 2;
            const int mr = m0 + wm + mi * 16 + gid2;
            float2 rv = *(const float2*)(res_scale + col);
            float2 x0 = *(const float2*)(x + (size_t)mr * DD + col);
            float2 x1 = *(const float2*)(x + (size_t)(mr + 8) * DD + col);
            float2 o0 = {fmaf(x0.x, rv.x, a[0]), fmaf(x0.y, rv.y, a[1])};
            float2 o1 = {fmaf(x1.x, rv.x, a[2]), fmaf(x1.y, rv.y, a[3])};
            *(float2*)(out + (size_t)mr * DD + col)       = o0;
            *(float2*)(out + (size_t)(mr + 8) * DD + col) = o1;
        }
    }
}

/* ===================== launch ===================== */
extern "C" void kernel_launch(void* const* d_in, const int* in_sizes, int n_in,
                              void* d_out, int out_size)
{
    const float* x         = (const float*)d_in[0];
    const float* W_uv      = (const float*)d_in[1];
    const float* W_o       = (const float*)d_in[2];
    const float* gamma     = (const float*)d_in[3];
    const float* beta      = (const float*)d_in[4];
    const float* g         = (const float*)d_in[5];
    const float* res_scale = (const float*)d_in[6];
    float* out = (float*)d_out;

    k_norm_cvt<<<MTOT / 8, 256>>>(x, g);
    k_cvt_sel<<<(1152 * DD / 4 + 255) / 256, 256>>>(W_uv, 0, 1152 * DD / 4);
    k_cvt_sel<<<(DD * EE / 4 + 255) / 256, 256>>>(W_o, 1, DD * EE / 4);
    k_uv_mma<<<dim3(MTOT / 128, 9), 256>>>(gamma, beta);
    k_scores<<<dim3(3, 3, BB), 256>>>();
    k_attn<<<dim3(EE / 64, 3, BB), 256>>>();
    k_out_mma<<<dim3(MTOT / 128, 2), 256>>>(x, res_scale, out);
}

// round 7
// speedup vs baseline: 2.1880x; 1.1983x over previous
#include <cuda_runtime.h>
#include <cuda_fp16.h>
#include <cstdint>
#include <math.h>

#define BB   1024
#define TT   133
#define DD   256
#define EE   512
#define SSZ  128
#define MTOT (BB*TT)          /* 136192 */
#define MP   160              /* i-row padding (10x16) */
#define NP   192              /* j-col padding (24x8, 12x16) */
#define EPSV 1e-5f
#define INV_SQRT_S 0.08838834764831845f

/* -------- scratch (device globals, 16B-aligned). Pad regions are never
 * written -> stay BSS-zero across graph replays (deterministic). -------- */
__device__ __align__(16) float  g_u[(size_t)MTOT * EE];
__device__ __align__(16) __half g_xh[(size_t)MTOT * DD];
__device__ __align__(16) __half g_xl[(size_t)MTOT * DD];
__device__ __align__(16) __half g_wwh[(size_t)MTOT * EE];
__device__ __align__(16) __half g_wwl[(size_t)MTOT * EE];
__device__ __align__(16) __half g_wuvh[1152 * DD];
__device__ __align__(16) __half g_wuvl[1152 * DD];
__device__ __align__(16) __half g_woh[DD * EE];
__device__ __align__(16) __half g_wol[DD * EE];
/* attention operands as fp16 limbs, padded per-batch frames */
__device__ __align__(16) __half g_qh[(size_t)BB * MP * SSZ];
__device__ __align__(16) __half g_ql[(size_t)BB * MP * SSZ];
__device__ __align__(16) __half g_kh[(size_t)BB * NP * SSZ];
__device__ __align__(16) __half g_kl[(size_t)BB * NP * SSZ];
__device__ __align__(16) __half g_vh[(size_t)BB * NP * EE];
__device__ __align__(16) __half g_vl[(size_t)BB * NP * EE];
__device__ __align__(16) __half g_ph[(size_t)BB * MP * NP];
__device__ __align__(16) __half g_pl[(size_t)BB * MP * NP];

/* ================= helpers ================= */
__device__ __forceinline__ uint32_t smem_u32(const void* p) {
    uint32_t a;
    asm("{ .reg .u64 t; cvta.to.shared.u64 t, %1; cvt.u32.u64 %0, t; }" : "=r"(a) : "l"(p));
    return a;
}
#define CPA16(dst, src) asm volatile("cp.async.cg.shared.global [%0], [%1], 16;" \
    :: "r"(dst), "l"(__cvta_generic_to_global(src)))
#define CPC()  asm volatile("cp.async.commit_group;")
#define CPW1() asm volatile("cp.async.wait_group 1;")
#define CPW0() asm volatile("cp.async.wait_group 0;")

__device__ __forceinline__ void ldsm4(uint32_t* r, uint32_t addr) {
    asm volatile("ldmatrix.sync.aligned.m8n8.x4.shared.b16 {%0,%1,%2,%3}, [%4];"
                 : "=r"(r[0]), "=r"(r[1]), "=r"(r[2]), "=r"(r[3]) : "r"(addr));
}
__device__ __forceinline__ void ldsm2t(uint32_t* r, uint32_t addr) {
    asm volatile("ldmatrix.sync.aligned.m8n8.x2.trans.shared.b16 {%0,%1}, [%2];"
                 : "=r"(r[0]), "=r"(r[1]) : "r"(addr));
}
__device__ __forceinline__ void mma16816(float* d, const uint32_t* a,
                                         uint32_t b0, uint32_t b1) {
    asm volatile("mma.sync.aligned.m16n8k16.row.col.f32.f16.f16.f32 "
                 "{%0,%1,%2,%3}, {%4,%5,%6,%7}, {%8,%9}, {%0,%1,%2,%3};"
                 : "+f"(d[0]), "+f"(d[1]), "+f"(d[2]), "+f"(d[3])
                 : "r"(a[0]), "r"(a[1]), "r"(a[2]), "r"(a[3]), "r"(b0), "r"(b1));
}
__device__ __forceinline__ float silu(float v) { return v / (1.f + __expf(-v)); }

__device__ __forceinline__ uint32_t fsplit2(float a, float b, uint32_t& lo) {
    __half ha = __float2half(a), hb = __float2half(b);
    __half la = __float2half(a - __half2float(ha));
    __half lb = __float2half(b - __half2float(hb));
    __half2 hh = __halves2half2(ha, hb);
    __half2 ll = __halves2half2(la, lb);
    lo = reinterpret_cast<uint32_t&>(ll);
    return reinterpret_cast<uint32_t&>(hh);
}

/* ===================== dense GEMM core (verified R6) ===================== */
#define TILE16 4096
struct SmemStage { char Ah[TILE16]; char Al[TILE16]; char Bh[TILE16]; char Bl[TILE16]; };

template<int NCH>
__device__ __forceinline__ void gemm_core(
    const __half* gAh, const __half* gAl, const __half* gBh, const __half* gBl,
    int lda, int ldb, SmemStage* stg, float acc[4][4][4])
{
    const int tid = threadIdx.x, wid = tid >> 5, lane = tid & 31;
    const int wm = (wid >> 2) * 64, wn = (wid & 3) * 32;
    const int r = tid >> 1, hb = (tid & 1) * 16;
    const uint32_t s0 = smem_u32(&stg[0]);
    const uint32_t s1 = smem_u32(&stg[1]);

    auto load = [&](int kc, int s) {
        const uint32_t da = (s ? s1 : s0) + r * 32 + hb;
        const int kofs = kc * 16 + (hb >> 1);
        CPA16(da,             gAh + (size_t)r * lda + kofs);
        CPA16(da + TILE16,    gAl + (size_t)r * lda + kofs);
        CPA16(da + 2*TILE16,  gBh + (size_t)r * ldb + kofs);
        CPA16(da + 3*TILE16,  gBl + (size_t)r * ldb + kofs);
    };

    load(0, 0); CPC();

    #pragma unroll 1
    for (int c = 0; c < NCH; c++) {
        const int s = c & 1;
        if (c + 1 < NCH) { load(c + 1, 1 - s); CPC(); CPW1(); }
        else             { CPW0(); }
        __syncthreads();

        const uint32_t base = s ? s1 : s0;
        const uint32_t boff = base + 2 * TILE16;

        uint32_t bh[8], bl[8];
        const int brow = wn + ((lane >> 4) & 1) * 8 + (lane & 7);
        const int bcolb = ((lane >> 3) & 1) * 16;
        const uint32_t ba0 = boff + brow * 32 + bcolb;
        const uint32_t ba1 = ba0 + 16 * 32;
        ldsm4(bh,     ba0);          ldsm4(bh + 4, ba1);
        ldsm4(bl,     ba0 + TILE16); ldsm4(bl + 4, ba1 + TILE16);

        const int arow = wm + (lane & 15);
        const uint32_t acolb = (lane >> 4) * 16;
        #pragma unroll
        for (int mi = 0; mi < 4; mi++) {
            uint32_t ah[4], al[4];
            const uint32_t aa = base + (arow + mi * 16) * 32 + acolb;
            ldsm4(ah, aa); ldsm4(al, aa + TILE16);
            #pragma unroll
            for (int ni = 0; ni < 4; ni++) {
                mma16816(acc[mi][ni], ah, bh[2 * ni], bh[2 * ni + 1]);
                mma16816(acc[mi][ni], ah, bl[2 * ni], bl[2 * ni + 1]);
                mma16816(acc[mi][ni], al, bh[2 * ni], bh[2 * ni + 1]);
            }
        }
        __syncthreads();
    }
}

/* ===================== K0: fused norm + fp16 split of xn ===================== */
__global__ __launch_bounds__(256) void k_norm_cvt(
    const float* __restrict__ x, const float* __restrict__ g)
{
    const int token = blockIdx.x * 8 + (threadIdx.x >> 5);
    const int lane  = threadIdx.x & 31;
    const float4* xp = (const float4*)(x + (size_t)token * DD);
    float4 v0 = xp[lane], v1 = xp[lane + 32];
    float sum = v0.x * v0.x + v0.y * v0.y + v0.z * v0.z + v0.w * v0.w
              + v1.x * v1.x + v1.y * v1.y + v1.z * v1.z + v1.w * v1.w;
    #pragma unroll
    for (int o = 16; o; o >>= 1) sum += __shfl_xor_sync(0xFFFFFFFFu, sum, o);
    float norm = sqrtf(sum * (1.f / (float)DD));
    float s = g[0] / fmaxf(norm, EPSV);

    uint2 h0, l0, h1, l1;
    h0.x = fsplit2(v0.x * s, v0.y * s, l0.x);
    h0.y = fsplit2(v0.z * s, v0.w * s, l0.y);
    h1.x = fsplit2(v1.x * s, v1.y * s, l1.x);
    h1.y = fsplit2(v1.z * s, v1.w * s, l1.y);
    const size_t base = (size_t)token * DD + lane * 4;
    *(uint2*)(g_xh + base)       = h0;
    *(uint2*)(g_xl + base)       = l0;
    *(uint2*)(g_xh + base + 128) = h1;
    *(uint2*)(g_xl + base + 128) = l1;
}

/* ===================== weight fp16 split (device-side dest select) ======== */
__global__ __launch_bounds__(256) void k_cvt_sel(
    const float* __restrict__ src, int which, int n4)
{
    __half* hi; __half* lo;
    if (which == 0) { hi = g_wuvh; lo = g_wuvl; }
    else            { hi = g_woh;  lo = g_wol;  }
    const int i = blockIdx.x * 256 + threadIdx.x;
    if (i >= n4) return;
    float4 v = ((const float4*)src)[i];
    uint2 h, l;
    h.x = fsplit2(v.x, v.y, l.x);
    h.y = fsplit2(v.z, v.w, l.y);
    *(uint2*)(hi + (size_t)i * 4) = h;
    *(uint2*)(lo + (size_t)i * 4) = l;
}

/* ===================== K1: uv GEMM; epilogue emits u fp32, v/q/k limbs ==== */
__global__ __launch_bounds__(256) void k_uv_mma(
    const float* __restrict__ gamma, const float* __restrict__ beta)
{
    __shared__ SmemStage stg[2];
    const int m0 = blockIdx.x * 128, by = blockIdx.y;
    float acc[4][4][4] = {};
    gemm_core<16>(g_xh + (size_t)m0 * DD, g_xl + (size_t)m0 * DD,
                  g_wuvh + (size_t)by * 128 * DD, g_wuvl + (size_t)by * 128 * DD,
                  DD, DD, stg, acc);

    const int tid = threadIdx.x, wid = tid >> 5, lane = tid & 31;
    const int wm = (wid >> 2) * 64, wn = (wid & 3) * 32;
    const int gid2 = lane >> 2, tig = lane & 3;
    #pragma unroll
    for (int mi = 0; mi < 4; mi++) {
        #pragma unroll
        for (int ni = 0; ni < 4; ni++) {
            const float* a = acc[mi][ni];
            const int nl = wn + ni * 8 + tig * 2;
            #pragma unroll
            for (int rr = 0; rr < 2; rr++) {
                const int mr = m0 + wm + mi * 16 + gid2 + rr * 8;
                const float sv0 = silu(a[rr * 2]), sv1 = silu(a[rr * 2 + 1]);
                const int b = mr / TT, t = mr - b * TT;
                if (by < 4) {
                    float2 o = {sv0, sv1};
                    *(float2*)(g_u + (size_t)mr * EE + by * 128 + nl) = o;
                } else if (by < 8) {
                    const int col = (by - 4) * 128 + nl;
                    uint32_t lo, hi = fsplit2(sv0, sv1, lo);
                    const size_t vofs = ((size_t)b * NP + t) * EE + col;
                    *(uint32_t*)(g_vh + vofs) = hi;
                    *(uint32_t*)(g_vl + vofs) = lo;
                } else {
                    const float q0 = fmaf(sv0, gamma[nl],     beta[nl]);
                    const float q1 = fmaf(sv1, gamma[nl + 1], beta[nl + 1]);
                    const float k0 = fmaf(sv0, gamma[SSZ + nl],     beta[SSZ + nl]);
                    const float k1 = fmaf(sv1, gamma[SSZ + nl + 1], beta[SSZ + nl + 1]);
                    uint32_t lo, hi;
                    hi = fsplit2(q0, q1, lo);
                    const size_t qofs = ((size_t)b * MP + t) * SSZ + nl;
                    *(uint32_t*)(g_qh + qofs) = hi;
                    *(uint32_t*)(g_ql + qofs) = lo;
                    hi = fsplit2(k0, k1, lo);
                    const size_t kofs = ((size_t)b * NP + t) * SSZ + nl;
                    *(uint32_t*)(g_kh + kofs) = hi;
                    *(uint32_t*)(g_kl + kofs) = lo;
                }
            }
        }
    }
}

/* ===================== K2: scores on HMMA =====================
 * per batch CTA: S[160,192] = q[160,128] k^T; P = relu(S/sqrt(S))^2 -> limbs.
 * warps 2m x 4n: 80 x 48 each; BK=16, 8 chunks, double buffered. */
#define SC_QT  (MP * 32)                 /* 5120 */
#define SC_KT  (NP * 32)                 /* 6144 */
#define SC_STG (2*SC_QT + 2*SC_KT)       /* 22528 */
__global__ __launch_bounds__(256) void k_sc_mma()
{
    __shared__ char ssm[2 * SC_STG];
    const uint32_t sb = smem_u32(ssm);
    const int b = blockIdx.x;
    const int tid = threadIdx.x, wid = tid >> 5, lane = tid & 31;
    const int wm = (wid >> 2) * 80, wn = (wid & 3) * 48;

    auto load = [&](int kc, int s) {
        const uint32_t st = sb + s * SC_STG;
        #pragma unroll
        for (int c = tid; c < 2 * MP; c += 256) {
            const int row = c >> 1, off = c & 1;
            const size_t gofs = ((size_t)b * MP + row) * SSZ + kc * 16 + off * 8;
            CPA16(st + row * 32 + off * 16,         g_qh + gofs);
            CPA16(st + SC_QT + row * 32 + off * 16, g_ql + gofs);
        }
        #pragma unroll
        for (int c = tid; c < 2 * NP; c += 256) {
            const int row = c >> 1, off = c & 1;
            const size_t gofs = ((size_t)b * NP + row) * SSZ + kc * 16 + off * 8;
            CPA16(st + 2*SC_QT + row * 32 + off * 16,         g_kh + gofs);
            CPA16(st + 2*SC_QT + SC_KT + row * 32 + off * 16, g_kl + gofs);
        }
    };

    float acc[5][6][4] = {};
    load(0, 0); CPC();

    #pragma unroll 1
    for (int c = 0; c < 8; c++) {
        const int s = c & 1;
        if (c + 1 < 8) { load(c + 1, 1 - s); CPC(); CPW1(); }
        else           { CPW0(); }
        __syncthreads();

        const uint32_t qb = sb + s * SC_STG;
        const uint32_t qlb = qb + SC_QT;
        const uint32_t kb = qb + 2 * SC_QT;
        const uint32_t klb = kb + SC_KT;

        uint32_t bh[3][4], bl[3][4];
        const uint32_t bcolb = ((lane >> 3) & 1) * 16;
        #pragma unroll
        for (int nj = 0; nj < 3; nj++) {
            const int brow = wn + nj * 16 + ((lane >> 4) & 1) * 8 + (lane & 7);
            ldsm4(bh[nj], kb  + brow * 32 + bcolb);
            ldsm4(bl[nj], klb + brow * 32 + bcolb);
        }
        const int arow = wm + (lane & 15);
        const uint32_t acolb = (lane >> 4) * 16;
        #pragma unroll
        for (int mi = 0; mi < 5; mi++) {
            uint32_t ah[4], al[4];
            const uint32_t aa = qb + (arow + mi * 16) * 32 + acolb;
            ldsm4(ah, aa); ldsm4(al, aa + SC_QT);
            #pragma unroll
            for (int nb = 0; nb < 6; nb++) {
                const uint32_t b0 = bh[nb >> 1][(nb & 1) * 2], b1 = bh[nb >> 1][(nb & 1) * 2 + 1];
                const uint32_t c0 = bl[nb >> 1][(nb & 1) * 2], c1 = bl[nb >> 1][(nb & 1) * 2 + 1];
                mma16816(acc[mi][nb], ah, b0, b1);
                mma16816(acc[mi][nb], ah, c0, c1);
                mma16816(acc[mi][nb], al, b0, b1);
            }
        }
        __syncthreads();
    }

    /* epilogue: P = relu(s * inv_sqrt)^2, split to limbs */
    #pragma unroll
    for (int mi = 0; mi < 5; mi++) {
        #pragma unroll
        for (int nb = 0; nb < 6; nb++) {
            const int j = wn + nb * 8 + (lane & 3) * 2;
            #pragma unroll
            for (int rr = 0; rr < 2; rr++) {
                const int i = wm + mi * 16 + (lane >> 2) + rr * 8;
                float s0 = fmaxf(acc[mi][nb][rr * 2]     * INV_SQRT_S, 0.f);
                float s1 = fmaxf(acc[mi][nb][rr * 2 + 1] * INV_SQRT_S, 0.f);
                s0 *= s0; s1 *= s1;
                uint32_t lo, hi = fsplit2(s0, s1, lo);
                const size_t ofs = ((size_t)b * MP + i) * NP + j;
                *(uint32_t*)(g_ph + ofs) = hi;
                *(uint32_t*)(g_pl + ofs) = lo;
            }
        }
    }
}

/* ===================== K3: attn = u ⊙ (P v) on HMMA =====================
 * grid (4, BB): CTA = M=160 x N=128 (e0), K=192; BK=16, 12 chunks.
 * V loaded [j][e] row-major, B-frags via ldmatrix.x2.trans. */
#define AT_PT  (MP * 32)                 /* 5120 */
#define AT_VT  (16 * 256)                /* 4096 */
#define AT_STG (2*AT_PT + 2*AT_VT)       /* 18432 */
__global__ __launch_bounds__(256) void k_at_mma()
{
    __shared__ char ssm[2 * AT_STG];
    const uint32_t sb = smem_u32(ssm);
    const int b = blockIdx.y, e0 = blockIdx.x * 128;
    const int tid = threadIdx.x, wid = tid >> 5, lane = tid & 31;
    const int wm = (wid >> 2) * 80, wn = (wid & 3) * 32;

    auto load = [&](int kc, int s) {
        const uint32_t st = sb + s * AT_STG;
        #pragma unroll
        for (int c = tid; c < 2 * MP; c += 256) {
            const int row = c >> 1, off = c & 1;
            const size_t gofs = ((size_t)b * MP + row) * NP + kc * 16 + off * 8;
            CPA16(st + row * 32 + off * 16,         g_ph + gofs);
            CPA16(st + AT_PT + row * 32 + off * 16, g_pl + gofs);
        }
        {
            const int c = tid;          /* 256 chunks exactly */
            const int row = c >> 4, col = c & 15;
            const size_t gofs = ((size_t)b * NP + kc * 16 + row) * EE + e0 + col * 8;
            CPA16(st + 2*AT_PT + row * 256 + col * 16,         g_vh + gofs);
            CPA16(st + 2*AT_PT + AT_VT + row * 256 + col * 16, g_vl + gofs);
        }
    };

    float acc[5][4][4] = {};
    load(0, 0); CPC();

    #pragma unroll 1
    for (int c = 0; c < 12; c++) {
        const int s = c & 1;
        if (c + 1 < 12) { load(c + 1, 1 - s); CPC(); CPW1(); }
        else            { CPW0(); }
        __syncthreads();

        const uint32_t pb = sb + s * AT_STG;
        const uint32_t plb = pb + AT_PT;
        const uint32_t vb = pb + 2 * AT_PT;
        const uint32_t vlb = vb + AT_VT;

        uint32_t bh[4][2], bl[4][2];
        const int l16 = lane & 15;
        #pragma unroll
        for (int nb = 0; nb < 4; nb++) {
            const uint32_t va = l16 * 256 + (wn + nb * 8) * 2;
            ldsm2t(bh[nb], vb + va);
            ldsm2t(bl[nb], vlb + va);
        }
        const int arow = wm + (lane & 15);
        const uint32_t acolb = (lane >> 4) * 16;
        #pragma unroll
        for (int mi = 0; mi < 5; mi++) {
            uint32_t ah[4], al[4];
            const uint32_t aa = pb + (arow + mi * 16) * 32 + acolb;
            ldsm4(ah, aa); ldsm4(al, aa + AT_PT);
            #pragma unroll
            for (int nb = 0; nb < 4; nb++) {
                mma16816(acc[mi][nb], ah, bh[nb][0], bh[nb][1]);
                mma16816(acc[mi][nb], ah, bl[nb][0], bl[nb][1]);
                mma16816(acc[mi][nb], al, bh[nb][0], bh[nb][1]);
            }
        }
        __syncthreads();
    }

    /* epilogue: w = u * attn, split to wwh/wwl */
    #pragma unroll
    for (int mi = 0; mi < 5; mi++) {
        #pragma unroll
        for (int nb = 0; nb < 4; nb++) {
            const int e = e0 + wn + nb * 8 + (lane & 3) * 2;
            #pragma unroll
            for (int rr = 0; rr < 2; rr++) {
                const int i = wm + mi * 16 + (lane >> 2) + rr * 8;
                if (i < TT) {
                    const size_t m = (size_t)b * TT + i;
                    float2 uu = *(const float2*)(g_u + m * EE + e);
                    const float w0 = uu.x * acc[mi][nb][rr * 2];
                    const float w1 = uu.y * acc[mi][nb][rr * 2 + 1];
                    uint32_t lo, hi = fsplit2(w0, w1, lo);
                    *(uint32_t*)(g_wwh + m * EE + e) = hi;
                    *(uint32_t*)(g_wwl + m * EE + e) = lo;
                }
            }
        }
    }
}

/* ===================== K4: out GEMM (M x 256 x 512) + residual ============ */
__global__ __launch_bounds__(256) void k_out_mma(
    const float* __restrict__ x, const float* __restrict__ res_scale,
    float* __restrict__ out)
{
    __shared__ SmemStage stg[2];
    const int m0 = blockIdx.x * 128, by = blockIdx.y;
    float acc[4][4][4] = {};
    gemm_core<32>(g_wwh + (size_t)m0 * EE, g_wwl + (size_t)m0 * EE,
                  g_woh + (size_t)by * 128 * EE, g_wol + (size_t)by * 128 * EE,
                  EE, EE, stg, acc);

    const int tid = threadIdx.x, wid = tid >> 5, lane = tid & 31;
    const int wm = (wid >> 2) * 64, wn = (wid & 3) * 32;
    const int gid2 = lane >> 2, tig = lane & 3;
    #pragma unroll
    for (int mi = 0; mi < 4; mi++) {
        #pragma unroll
        for (int ni = 0; ni < 4; ni++) {
            const float* a = acc[mi][ni];
            const int col = by * 128 + wn + ni * 8 + tig * 2;
            const int mr = m0 + wm + mi * 16 + gid2;
            float2 rv = *(const float2*)(res_scale + col);
            float2 x0 = *(const float2*)(x + (size_t)mr * DD + col);
            float2 x1 = *(const float2*)(x + (size_t)(mr + 8) * DD + col);
            float2 o0 = {fmaf(x0.x, rv.x, a[0]), fmaf(x0.y, rv.y, a[1])};
            float2 o1 = {fmaf(x1.x, rv.x, a[2]), fmaf(x1.y, rv.y, a[3])};
            *(float2*)(out + (size_t)mr * DD + col)       = o0;
            *(float2*)(out + (size_t)(mr + 8) * DD + col) = o1;
        }
    }
}

/* ===================== launch ===================== */
extern "C" void kernel_launch(void* const* d_in, const int* in_sizes, int n_in,
                              void* d_out, int out_size)
{
    const float* x         = (const float*)d_in[0];
    const float* W_uv      = (const float*)d_in[1];
    const float* W_o       = (const float*)d_in[2];
    const float* gamma     = (const float*)d_in[3];
    const float* beta      = (const float*)d_in[4];
    const float* g         = (const float*)d_in[5];
    const float* res_scale = (const float*)d_in[6];
    float* out = (float*)d_out;

    k_norm_cvt<<<MTOT / 8, 256>>>(x, g);
    k_cvt_sel<<<(1152 * DD / 4 + 255) / 256, 256>>>(W_uv, 0, 1152 * DD / 4);
    k_cvt_sel<<<(DD * EE / 4 + 255) / 256, 256>>>(W_o, 1, DD * EE / 4);
    k_uv_mma<<<dim3(MTOT / 128, 9), 256>>>(gamma, beta);
    k_sc_mma<<<BB, 256>>>();
    k_at_mma<<<dim3(4, BB), 256>>>();
    k_out_mma<<<dim3(MTOT / 128, 2), 256>>>(x, res_scale, out);
}

// round 8
// speedup vs baseline: 2.2048x; 1.0076x over previous
#include <cuda_runtime.h>
#include <cuda_fp16.h>
#include <cstdint>
#include <math.h>

#define BB   1024
#define TT   133
#define DD   256
#define EE   512
#define SSZ  128
#define MTOT (BB*TT)          /* 136192 */
#define MP   160              /* i-row padding (10x16) */
#define NP   192              /* j-col padding (12x16) */
#define EPSV 1e-5f
#define INV_SQRT_S 0.08838834764831845f

/* -------- scratch (device globals, 16B-aligned). Pad regions stay BSS-zero. */
__device__ __align__(16) float  g_u[(size_t)MTOT * EE];
__device__ __align__(16) __half g_xh[(size_t)MTOT * DD];
__device__ __align__(16) __half g_xl[(size_t)MTOT * DD];
__device__ __align__(16) __half g_wwh[(size_t)MTOT * EE];
__device__ __align__(16) __half g_wwl[(size_t)MTOT * EE];
__device__ __align__(16) __half g_wuvh[1152 * DD];
__device__ __align__(16) __half g_wuvl[1152 * DD];
__device__ __align__(16) __half g_woh[DD * EE];
__device__ __align__(16) __half g_wol[DD * EE];
__device__ __align__(16) __half g_qh[(size_t)BB * MP * SSZ];
__device__ __align__(16) __half g_ql[(size_t)BB * MP * SSZ];
__device__ __align__(16) __half g_kh[(size_t)BB * NP * SSZ];
__device__ __align__(16) __half g_kl[(size_t)BB * NP * SSZ];
__device__ __align__(16) __half g_vh[(size_t)BB * NP * EE];
__device__ __align__(16) __half g_vl[(size_t)BB * NP * EE];
__device__ __align__(16) __half g_ph[(size_t)BB * MP * NP];
__device__ __align__(16) __half g_pl[(size_t)BB * MP * NP];

/* ================= helpers ================= */
__device__ __forceinline__ uint32_t smem_u32(const void* p) {
    uint32_t a;
    asm("{ .reg .u64 t; cvta.to.shared.u64 t, %1; cvt.u32.u64 %0, t; }" : "=r"(a) : "l"(p));
    return a;
}
#define CPA16(dst, src) asm volatile("cp.async.cg.shared.global [%0], [%1], 16;" \
    :: "r"(dst), "l"(__cvta_generic_to_global(src)))
#define CPC()  asm volatile("cp.async.commit_group;")
#define CPW1() asm volatile("cp.async.wait_group 1;")
#define CPW0() asm volatile("cp.async.wait_group 0;")

__device__ __forceinline__ void ldsm4(uint32_t* r, uint32_t addr) {
    asm volatile("ldmatrix.sync.aligned.m8n8.x4.shared.b16 {%0,%1,%2,%3}, [%4];"
                 : "=r"(r[0]), "=r"(r[1]), "=r"(r[2]), "=r"(r[3]) : "r"(addr));
}
__device__ __forceinline__ void ldsm2t(uint32_t* r, uint32_t addr) {
    asm volatile("ldmatrix.sync.aligned.m8n8.x2.trans.shared.b16 {%0,%1}, [%2];"
                 : "=r"(r[0]), "=r"(r[1]) : "r"(addr));
}
__device__ __forceinline__ void mma16816(float* d, const uint32_t* a,
                                         uint32_t b0, uint32_t b1) {
    asm volatile("mma.sync.aligned.m16n8k16.row.col.f32.f16.f16.f32 "
                 "{%0,%1,%2,%3}, {%4,%5,%6,%7}, {%8,%9}, {%0,%1,%2,%3};"
                 : "+f"(d[0]), "+f"(d[1]), "+f"(d[2]), "+f"(d[3])
                 : "r"(a[0]), "r"(a[1]), "r"(a[2]), "r"(a[3]), "r"(b0), "r"(b1));
}
__device__ __forceinline__ float silu(float v) { return v / (1.f + __expf(-v)); }

__device__ __forceinline__ uint32_t fsplit2(float a, float b, uint32_t& lo) {
    __half ha = __float2half(a), hb = __float2half(b);
    __half la = __float2half(a - __half2float(ha));
    __half lb = __float2half(b - __half2float(hb));
    __half2 hh = __halves2half2(ha, hb);
    __half2 ll = __halves2half2(la, lb);
    lo = reinterpret_cast<uint32_t&>(ll);
    return reinterpret_cast<uint32_t&>(hh);
}

/* ===================== dense GEMM core ===================== */
#define TILE16 4096
struct SmemStage { char Ah[TILE16]; char Al[TILE16]; char Bh[TILE16]; char Bl[TILE16]; };

template<int NCH>
__device__ __forceinline__ void gemm_core(
    const __half* gAh, const __half* gAl, const __half* gBh, const __half* gBl,
    int lda, int ldb, SmemStage* stg, float acc[4][4][4])
{
    const int tid = threadIdx.x, wid = tid >> 5, lane = tid & 31;
    const int wm = (wid >> 2) * 64, wn = (wid & 3) * 32;
    const int r = tid >> 1, hb = (tid & 1) * 16;
    const uint32_t s0 = smem_u32(&stg[0]);
    const uint32_t s1 = smem_u32(&stg[1]);

    auto load = [&](int kc, int s) {
        const uint32_t da = (s ? s1 : s0) + r * 32 + hb;
        const int kofs = kc * 16 + (hb >> 1);
        CPA16(da,             gAh + (size_t)r * lda + kofs);
        CPA16(da + TILE16,    gAl + (size_t)r * lda + kofs);
        CPA16(da + 2*TILE16,  gBh + (size_t)r * ldb + kofs);
        CPA16(da + 3*TILE16,  gBl + (size_t)r * ldb + kofs);
    };

    load(0, 0); CPC();

    #pragma unroll 1
    for (int c = 0; c < NCH; c++) {
        const int s = c & 1;
        if (c + 1 < NCH) { load(c + 1, 1 - s); CPC(); CPW1(); }
        else             { CPW0(); }
        __syncthreads();

        const uint32_t base = s ? s1 : s0;
        const uint32_t boff = base + 2 * TILE16;

        uint32_t bh[8], bl[8];
        const int brow = wn + ((lane >> 4) & 1) * 8 + (lane & 7);
        const int bcolb = ((lane >> 3) & 1) * 16;
        const uint32_t ba0 = boff + brow * 32 + bcolb;
        const uint32_t ba1 = ba0 + 16 * 32;
        ldsm4(bh,     ba0);          ldsm4(bh + 4, ba1);
        ldsm4(bl,     ba0 + TILE16); ldsm4(bl + 4, ba1 + TILE16);

        const int arow = wm + (lane & 15);
        const uint32_t acolb = (lane >> 4) * 16;
        #pragma unroll
        for (int mi = 0; mi < 4; mi++) {
            uint32_t ah[4], al[4];
            const uint32_t aa = base + (arow + mi * 16) * 32 + acolb;
            ldsm4(ah, aa); ldsm4(al, aa + TILE16);
            /* term-major order: consecutive MMAs hit different accumulators */
            #pragma unroll
            for (int ni = 0; ni < 4; ni++)
                mma16816(acc[mi][ni], ah, bh[2 * ni], bh[2 * ni + 1]);
            #pragma unroll
            for (int ni = 0; ni < 4; ni++)
                mma16816(acc[mi][ni], ah, bl[2 * ni], bl[2 * ni + 1]);
            #pragma unroll
            for (int ni = 0; ni < 4; ni++)
                mma16816(acc[mi][ni], al, bh[2 * ni], bh[2 * ni + 1]);
        }
        __syncthreads();
    }
}

/* ===================== K0: fused norm + fp16 split of xn ===================== */
__global__ __launch_bounds__(256) void k_norm_cvt(
    const float* __restrict__ x, const float* __restrict__ g)
{
    const int token = blockIdx.x * 8 + (threadIdx.x >> 5);
    const int lane  = threadIdx.x & 31;
    const float4* xp = (const float4*)(x + (size_t)token * DD);
    float4 v0 = xp[lane], v1 = xp[lane + 32];
    float sum = v0.x * v0.x + v0.y * v0.y + v0.z * v0.z + v0.w * v0.w
              + v1.x * v1.x + v1.y * v1.y + v1.z * v1.z + v1.w * v1.w;
    #pragma unroll
    for (int o = 16; o; o >>= 1) sum += __shfl_xor_sync(0xFFFFFFFFu, sum, o);
    float norm = sqrtf(sum * (1.f / (float)DD));
    float s = g[0] / fmaxf(norm, EPSV);

    uint2 h0, l0, h1, l1;
    h0.x = fsplit2(v0.x * s, v0.y * s, l0.x);
    h0.y = fsplit2(v0.z * s, v0.w * s, l0.y);
    h1.x = fsplit2(v1.x * s, v1.y * s, l1.x);
    h1.y = fsplit2(v1.z * s, v1.w * s, l1.y);
    const size_t base = (size_t)token * DD + lane * 4;
    *(uint2*)(g_xh + base)       = h0;
    *(uint2*)(g_xl + base)       = l0;
    *(uint2*)(g_xh + base + 128) = h1;
    *(uint2*)(g_xl + base + 128) = l1;
}

/* ===================== weight fp16 split (device-side dest select) ======== */
__global__ __launch_bounds__(256) void k_cvt_sel(
    const float* __restrict__ src, int which, int n4)
{
    __half* hi; __half* lo;
    if (which == 0) { hi = g_wuvh; lo = g_wuvl; }
    else            { hi = g_woh;  lo = g_wol;  }
    const int i = blockIdx.x * 256 + threadIdx.x;
    if (i >= n4) return;
    float4 v = ((const float4*)src)[i];
    uint2 h, l;
    h.x = fsplit2(v.x, v.y, l.x);
    h.y = fsplit2(v.z, v.w, l.y);
    *(uint2*)(hi + (size_t)i * 4) = h;
    *(uint2*)(lo + (size_t)i * 4) = l;
}

/* ===================== K1: uv GEMM; grid (9, 1064) for A-tile L2 reuse ==== */
__global__ __launch_bounds__(256) void k_uv_mma(
    const float* __restrict__ gamma, const float* __restrict__ beta)
{
    __shared__ SmemStage stg[2];
    const int m0 = blockIdx.y * 128, by = blockIdx.x;
    float acc[4][4][4] = {};
    gemm_core<16>(g_xh + (size_t)m0 * DD, g_xl + (size_t)m0 * DD,
                  g_wuvh + (size_t)by * 128 * DD, g_wuvl + (size_t)by * 128 * DD,
                  DD, DD, stg, acc);

    const int tid = threadIdx.x, wid = tid >> 5, lane = tid & 31;
    const int wm = (wid >> 2) * 64, wn = (wid & 3) * 32;
    const int gid2 = lane >> 2, tig = lane & 3;
    #pragma unroll
    for (int mi = 0; mi < 4; mi++) {
        #pragma unroll
        for (int ni = 0; ni < 4; ni++) {
            const float* a = acc[mi][ni];
            const int nl = wn + ni * 8 + tig * 2;
            #pragma unroll
            for (int rr = 0; rr < 2; rr++) {
                const int mr = m0 + wm + mi * 16 + gid2 + rr * 8;
                const float sv0 = silu(a[rr * 2]), sv1 = silu(a[rr * 2 + 1]);
                const int b = mr / TT, t = mr - b * TT;
                if (by < 4) {
                    float2 o = {sv0, sv1};
                    *(float2*)(g_u + (size_t)mr * EE + by * 128 + nl) = o;
                } else if (by < 8) {
                    const int col = (by - 4) * 128 + nl;
                    uint32_t lo, hi = fsplit2(sv0, sv1, lo);
                    const size_t vofs = ((size_t)b * NP + t) * EE + col;
                    *(uint32_t*)(g_vh + vofs) = hi;
                    *(uint32_t*)(g_vl + vofs) = lo;
                } else {
                    const float q0 = fmaf(sv0, gamma[nl],     beta[nl]);
                    const float q1 = fmaf(sv1, gamma[nl + 1], beta[nl + 1]);
                    const float k0 = fmaf(sv0, gamma[SSZ + nl],     beta[SSZ + nl]);
                    const float k1 = fmaf(sv1, gamma[SSZ + nl + 1], beta[SSZ + nl + 1]);
                    uint32_t lo, hi;
                    hi = fsplit2(q0, q1, lo);
                    const size_t qofs = ((size_t)b * MP + t) * SSZ + nl;
                    *(uint32_t*)(g_qh + qofs) = hi;
                    *(uint32_t*)(g_ql + qofs) = lo;
                    hi = fsplit2(k0, k1, lo);
                    const size_t kofs = ((size_t)b * NP + t) * SSZ + nl;
                    *(uint32_t*)(g_kh + kofs) = hi;
                    *(uint32_t*)(g_kl + kofs) = lo;
                }
            }
        }
    }
}

/* ===================== K2: scores on HMMA ===================== */
#define SC_QT  (MP * 32)
#define SC_KT  (NP * 32)
#define SC_STG (2*SC_QT + 2*SC_KT)
__global__ __launch_bounds__(256) void k_sc_mma()
{
    __shared__ char ssm[2 * SC_STG];
    const uint32_t sb = smem_u32(ssm);
    const int b = blockIdx.x;
    const int tid = threadIdx.x, wid = tid >> 5, lane = tid & 31;
    const int wm = (wid >> 2) * 80, wn = (wid & 3) * 48;

    auto load = [&](int kc, int s) {
        const uint32_t st = sb + s * SC_STG;
        #pragma unroll
        for (int c = tid; c < 2 * MP; c += 256) {
            const int row = c >> 1, off = c & 1;
            const size_t gofs = ((size_t)b * MP + row) * SSZ + kc * 16 + off * 8;
            CPA16(st + row * 32 + off * 16,         g_qh + gofs);
            CPA16(st + SC_QT + row * 32 + off * 16, g_ql + gofs);
        }
        #pragma unroll
        for (int c = tid; c < 2 * NP; c += 256) {
            const int row = c >> 1, off = c & 1;
            const size_t gofs = ((size_t)b * NP + row) * SSZ + kc * 16 + off * 8;
            CPA16(st + 2*SC_QT + row * 32 + off * 16,         g_kh + gofs);
            CPA16(st + 2*SC_QT + SC_KT + row * 32 + off * 16, g_kl + gofs);
        }
    };

    float acc[5][6][4] = {};
    load(0, 0); CPC();

    #pragma unroll 1
    for (int c = 0; c < 8; c++) {
        const int s = c & 1;
        if (c + 1 < 8) { load(c + 1, 1 - s); CPC(); CPW1(); }
        else           { CPW0(); }
        __syncthreads();

        const uint32_t qb = sb + s * SC_STG;
        const uint32_t kb = qb + 2 * SC_QT;
        const uint32_t klb = kb + SC_KT;

        uint32_t bh[3][4], bl[3][4];
        const uint32_t bcolb = ((lane >> 3) & 1) * 16;
        #pragma unroll
        for (int nj = 0; nj < 3; nj++) {
            const int brow = wn + nj * 16 + ((lane >> 4) & 1) * 8 + (lane & 7);
            ldsm4(bh[nj], kb  + brow * 32 + bcolb);
            ldsm4(bl[nj], klb + brow * 32 + bcolb);
        }
        const int arow = wm + (lane & 15);
        const uint32_t acolb = (lane >> 4) * 16;
        #pragma unroll
        for (int mi = 0; mi < 5; mi++) {
            uint32_t ah[4], al[4];
            const uint32_t aa = qb + (arow + mi * 16) * 32 + acolb;
            ldsm4(ah, aa); ldsm4(al, aa + SC_QT);
            #pragma unroll
            for (int nb = 0; nb < 6; nb++)
                mma16816(acc[mi][nb], ah, bh[nb >> 1][(nb & 1) * 2], bh[nb >> 1][(nb & 1) * 2 + 1]);
            #pragma unroll
            for (int nb = 0; nb < 6; nb++)
                mma16816(acc[mi][nb], ah, bl[nb >> 1][(nb & 1) * 2], bl[nb >> 1][(nb & 1) * 2 + 1]);
            #pragma unroll
            for (int nb = 0; nb < 6; nb++)
                mma16816(acc[mi][nb], al, bh[nb >> 1][(nb & 1) * 2], bh[nb >> 1][(nb & 1) * 2 + 1]);
        }
        __syncthreads();
    }

    #pragma unroll
    for (int mi = 0; mi < 5; mi++) {
        #pragma unroll
        for (int nb = 0; nb < 6; nb++) {
            const int j = wn + nb * 8 + (lane & 3) * 2;
            #pragma unroll
            for (int rr = 0; rr < 2; rr++) {
                const int i = wm + mi * 16 + (lane >> 2) + rr * 8;
                float s0 = fmaxf(acc[mi][nb][rr * 2]     * INV_SQRT_S, 0.f);
                float s1 = fmaxf(acc[mi][nb][rr * 2 + 1] * INV_SQRT_S, 0.f);
                s0 *= s0; s1 *= s1;
                uint32_t lo, hi = fsplit2(s0, s1, lo);
                const size_t ofs = ((size_t)b * MP + i) * NP + j;
                *(uint32_t*)(g_ph + ofs) = hi;
                *(uint32_t*)(g_pl + ofs) = lo;
            }
        }
    }
}

/* ===================== K3: attn = u ⊙ (P v) on HMMA ===================== */
#define AT_PT  (MP * 32)
#define AT_VT  (16 * 256)
#define AT_STG (2*AT_PT + 2*AT_VT)
__global__ __launch_bounds__(256) void k_at_mma()
{
    __shared__ char ssm[2 * AT_STG];
    const uint32_t sb = smem_u32(ssm);
    const int b = blockIdx.y, e0 = blockIdx.x * 128;
    const int tid = threadIdx.x, wid = tid >> 5, lane = tid & 31;
    const int wm = (wid >> 2) * 80, wn = (wid & 3) * 32;

    auto load = [&](int kc, int s) {
        const uint32_t st = sb + s * AT_STG;
        #pragma unroll
        for (int c = tid; c < 2 * MP; c += 256) {
            const int row = c >> 1, off = c & 1;
            const size_t gofs = ((size_t)b * MP + row) * NP + kc * 16 + off * 8;
            CPA16(st + row * 32 + off * 16,         g_ph + gofs);
            CPA16(st + AT_PT + row * 32 + off * 16, g_pl + gofs);
        }
        {
            const int c = tid;
            const int row = c >> 4, col = c & 15;
            const size_t gofs = ((size_t)b * NP + kc * 16 + row) * EE + e0 + col * 8;
            CPA16(st + 2*AT_PT + row * 256 + col * 16,         g_vh + gofs);
            CPA16(st + 2*AT_PT + AT_VT + row * 256 + col * 16, g_vl + gofs);
        }
    };

    float acc[5][4][4] = {};
    load(0, 0); CPC();

    #pragma unroll 1
    for (int c = 0; c < 12; c++) {
        const int s = c & 1;
        if (c + 1 < 12) { load(c + 1, 1 - s); CPC(); CPW1(); }
        else            { CPW0(); }
        __syncthreads();

        const uint32_t pb = sb + s * AT_STG;
        const uint32_t vb = pb + 2 * AT_PT;
        const uint32_t vlb = vb + AT_VT;

        uint32_t bh[4][2], bl[4][2];
        const int l16 = lane & 15;
        #pragma unroll
        for (int nb = 0; nb < 4; nb++) {
            const uint32_t va = l16 * 256 + (wn + nb * 8) * 2;
            ldsm2t(bh[nb], vb + va);
            ldsm2t(bl[nb], vlb + va);
        }
        const int arow = wm + (lane & 15);
        const uint32_t acolb = (lane >> 4) * 16;
        #pragma unroll
        for (int mi = 0; mi < 5; mi++) {
            uint32_t ah[4], al[4];
            const uint32_t aa = pb + (arow + mi * 16) * 32 + acolb;
            ldsm4(ah, aa); ldsm4(al, aa + AT_PT);
            #pragma unroll
            for (int nb = 0; nb < 4; nb++)
                mma16816(acc[mi][nb], ah, bh[nb][0], bh[nb][1]);
            #pragma unroll
            for (int nb = 0; nb < 4; nb++)
                mma16816(acc[mi][nb], ah, bl[nb][0], bl[nb][1]);
            #pragma unroll
            for (int nb = 0; nb < 4; nb++)
                mma16816(acc[mi][nb], al, bh[nb][0], bh[nb][1]);
        }
        __syncthreads();
    }

    #pragma unroll
    for (int mi = 0; mi < 5; mi++) {
        #pragma unroll
        for (int nb = 0; nb < 4; nb++) {
            const int e = e0 + wn + nb * 8 + (lane & 3) * 2;
            #pragma unroll
            for (int rr = 0; rr < 2; rr++) {
                const int i = wm + mi * 16 + (lane >> 2) + rr * 8;
                if (i < TT) {
                    const size_t m = (size_t)b * TT + i;
                    float2 uu = *(const float2*)(g_u + m * EE + e);
                    const float w0 = uu.x * acc[mi][nb][rr * 2];
                    const float w1 = uu.y * acc[mi][nb][rr * 2 + 1];
                    uint32_t lo, hi = fsplit2(w0, w1, lo);
                    *(uint32_t*)(g_wwh + m * EE + e) = hi;
                    *(uint32_t*)(g_wwl + m * EE + e) = lo;
                }
            }
        }
    }
}

/* ===================== K4: out GEMM; grid (2, 1064) ===================== */
__global__ __launch_bounds__(256) void k_out_mma(
    const float* __restrict__ x, const float* __restrict__ res_scale,
    float* __restrict__ out)
{
    __shared__ SmemStage stg[2];
    const int m0 = blockIdx.y * 128, by = blockIdx.x;
    float acc[4][4][4] = {};
    gemm_core<32>(g_wwh + (size_t)m0 * EE, g_wwl + (size_t)m0 * EE,
                  g_woh + (size_t)by * 128 * EE, g_wol + (size_t)by * 128 * EE,
                  EE, EE, stg, acc);

    const int tid = threadIdx.x, wid = tid >> 5, lane = tid & 31;
    const int wm = (wid >> 2) * 64, wn = (wid & 3) * 32;
    const int gid2 = lane >> 2, tig = lane & 3;
    #pragma unroll
    for (int mi = 0; mi < 4; mi++) {
        #pragma unroll
        for (int ni = 0; ni < 4; ni++) {
            const float* a = acc[mi][ni];
            const int col = by * 128 + wn + ni * 8 + tig * 2;
            const int mr = m0 + wm + mi * 16 + gid2;
            float2 rv = *(const float2*)(res_scale + col);
            float2 x0 = *(const float2*)(x + (size_t)mr * DD + col);
            float2 x1 = *(const float2*)(x + (size_t)(mr + 8) * DD + col);
            float2 o0 = {fmaf(x0.x, rv.x, a[0]), fmaf(x0.y, rv.y, a[1])};
            float2 o1 = {fmaf(x1.x, rv.x, a[2]), fmaf(x1.y, rv.y, a[3])};
            *(float2*)(out + (size_t)mr * DD + col)       = o0;
            *(float2*)(out + (size_t)(mr + 8) * DD + col) = o1;
        }
    }
}

/* ===================== launch ===================== */
extern "C" void kernel_launch(void* const* d_in, const int* in_sizes, int n_in,
                              void* d_out, int out_size)
{
    const float* x         = (const float*)d_in[0];
    const float* W_uv      = (const float*)d_in[1];
    const float* W_o       = (const float*)d_in[2];
    const float* gamma     = (const float*)d_in[3];
    const float* beta      = (const float*)d_in[4];
    const float* g         = (const float*)d_in[5];
    const float* res_scale = (const float*)d_in[6];
    float* out = (float*)d_out;

    k_norm_cvt<<<MTOT / 8, 256>>>(x, g);
    k_cvt_sel<<<(1152 * DD / 4 + 255) / 256, 256>>>(W_uv, 0, 1152 * DD / 4);
    k_cvt_sel<<<(DD * EE / 4 + 255) / 256, 256>>>(W_o, 1, DD * EE / 4);
    k_uv_mma<<<dim3(9, MTOT / 128), 256>>>(gamma, beta);
    k_sc_mma<<<BB, 256>>>();
    k_at_mma<<<dim3(4, BB), 256>>>();
    k_out_mma<<<dim3(2, MTOT / 128), 256>>>(x, res_scale, out);
}

// round 9
// speedup vs baseline: 2.3273x; 1.0556x over previous
#include <cuda_runtime.h>
#include <cuda_fp16.h>
#include <cstdint>
#include <math.h>

#define BB   1024
#define TT   133
#define DD   256
#define EE   512
#define SSZ  128
#define MTOT (BB*TT)          /* 136192 */
#define MP   160
#define NP   192
#define EPSV 1e-5f
#define INV_SQRT_S 0.08838834764831845f

/* -------- scratch (device globals, 16B-aligned). Pad regions stay BSS-zero. */
__device__ __align__(16) float  g_u[(size_t)MTOT * EE];
__device__ __align__(16) __half g_xh[(size_t)MTOT * DD];
__device__ __align__(16) __half g_xl[(size_t)MTOT * DD];
__device__ __align__(16) __half g_wwh[(size_t)MTOT * EE];
__device__ __align__(16) __half g_wwl[(size_t)MTOT * EE];
__device__ __align__(16) __half g_wuvh[1152 * DD];
__device__ __align__(16) __half g_wuvl[1152 * DD];
__device__ __align__(16) __half g_woh[DD * EE];
__device__ __align__(16) __half g_wol[DD * EE];
__device__ __align__(16) __half g_qh[(size_t)BB * MP * SSZ];
__device__ __align__(16) __half g_ql[(size_t)BB * MP * SSZ];
__device__ __align__(16) __half g_kh[(size_t)BB * NP * SSZ];
__device__ __align__(16) __half g_kl[(size_t)BB * NP * SSZ];
__device__ __align__(16) __half g_vh[(size_t)BB * NP * EE];
__device__ __align__(16) __half g_vl[(size_t)BB * NP * EE];
__device__ __align__(16) __half g_ph[(size_t)BB * MP * NP];
__device__ __align__(16) __half g_pl[(size_t)BB * MP * NP];

/* ================= helpers ================= */
__device__ __forceinline__ uint32_t smem_u32(const void* p) {
    uint32_t a;
    asm("{ .reg .u64 t; cvta.to.shared.u64 t, %1; cvt.u32.u64 %0, t; }" : "=r"(a) : "l"(p));
    return a;
}
#define CPA16(dst, src) asm volatile("cp.async.cg.shared.global [%0], [%1], 16;" \
    :: "r"(dst), "l"(__cvta_generic_to_global(src)))
#define CPC()  asm volatile("cp.async.commit_group;")
#define CPW1() asm volatile("cp.async.wait_group 1;")
#define CPW0() asm volatile("cp.async.wait_group 0;")

__device__ __forceinline__ void ldsm4(uint32_t* r, uint32_t addr) {
    asm volatile("ldmatrix.sync.aligned.m8n8.x4.shared.b16 {%0,%1,%2,%3}, [%4];"
                 : "=r"(r[0]), "=r"(r[1]), "=r"(r[2]), "=r"(r[3]) : "r"(addr));
}
__device__ __forceinline__ void ldsm2t(uint32_t* r, uint32_t addr) {
    asm volatile("ldmatrix.sync.aligned.m8n8.x2.trans.shared.b16 {%0,%1}, [%2];"
                 : "=r"(r[0]), "=r"(r[1]) : "r"(addr));
}
__device__ __forceinline__ void mma16816(float* d, const uint32_t* a,
                                         uint32_t b0, uint32_t b1) {
    asm volatile("mma.sync.aligned.m16n8k16.row.col.f32.f16.f16.f32 "
                 "{%0,%1,%2,%3}, {%4,%5,%6,%7}, {%8,%9}, {%0,%1,%2,%3};"
                 : "+f"(d[0]), "+f"(d[1]), "+f"(d[2]), "+f"(d[3])
                 : "r"(a[0]), "r"(a[1]), "r"(a[2]), "r"(a[3]), "r"(b0), "r"(b1));
}
__device__ __forceinline__ float silu(float v) { return v / (1.f + __expf(-v)); }

__device__ __forceinline__ uint32_t fsplit2(float a, float b, uint32_t& lo) {
    __half ha = __float2half(a), hb = __float2half(b);
    __half la = __float2half(a - __half2float(ha));
    __half lb = __float2half(b - __half2float(hb));
    __half2 hh = __halves2half2(ha, hb);
    __half2 ll = __halves2half2(la, lb);
    lo = reinterpret_cast<uint32_t&>(ll);
    return reinterpret_cast<uint32_t&>(hh);
}

/* ===================== BK=32 dense GEMM core (dynamic smem) =============
 * 128x128 CTA tile, 8 warps (2m x 4n) of 64x32, BK=32, double buffered.
 * Rows padded 64B->80B: r*80 mod 128 cycles all 8 16B slots -> ldsm
 * conflict-free. Stage = 4 limb tiles x 10240B = 40960B; 2 stages = 80KB. */
#define ROWB   80
#define TILEB  10240
#define STAGEB 40960

template<int NCH>
__device__ __forceinline__ void gemm_core32(
    const __half* gAh, const __half* gAl, const __half* gBh, const __half* gBl,
    int lda, int ldb, char* sm, float acc[4][4][4])
{
    const int tid = threadIdx.x, wid = tid >> 5, lane = tid & 31;
    const int wm = (wid >> 2) * 64, wn = (wid & 3) * 32;
    const int r = tid >> 1, qp = (tid & 1) * 2;   /* half-row: cols [qp*8, qp*8+16) */
    const uint32_t s0 = smem_u32(sm);

    auto load = [&](int kc, int s) {
        const uint32_t da = s0 + s * STAGEB + r * ROWB + qp * 16;
        const int kofs = kc * 32 + qp * 8;
        const __half* pa = gAh + (size_t)r * lda + kofs;
        const __half* pl = gAl + (size_t)r * lda + kofs;
        const __half* pb = gBh + (size_t)r * ldb + kofs;
        const __half* pc = gBl + (size_t)r * ldb + kofs;
        CPA16(da,                pa); CPA16(da + 16,                pa + 8);
        CPA16(da + TILEB,        pl); CPA16(da + TILEB + 16,        pl + 8);
        CPA16(da + 2*TILEB,      pb); CPA16(da + 2*TILEB + 16,      pb + 8);
        CPA16(da + 3*TILEB,      pc); CPA16(da + 3*TILEB + 16,      pc + 8);
    };

    load(0, 0); CPC();

    #pragma unroll 1
    for (int c = 0; c < NCH; c++) {
        const int s = c & 1;
        if (c + 1 < NCH) { load(c + 1, 1 - s); CPC(); CPW1(); }
        else             { CPW0(); }
        __syncthreads();

        const uint32_t base = s0 + s * STAGEB;
        const uint32_t boff = base + 2 * TILEB;
        #pragma unroll
        for (int ks = 0; ks < 2; ks++) {
            uint32_t bh[8], bl[8];
            const int brow = wn + ((lane >> 4) & 1) * 8 + (lane & 7);
            const uint32_t bcolb = ks * 32 + ((lane >> 3) & 1) * 16;
            const uint32_t ba0 = boff + brow * ROWB + bcolb;
            const uint32_t ba1 = ba0 + 16 * ROWB;
            ldsm4(bh,     ba0);          ldsm4(bh + 4, ba1);
            ldsm4(bl,     ba0 + TILEB);  ldsm4(bl + 4, ba1 + TILEB);

            const int arow = wm + (lane & 15);
            const uint32_t acolb = ks * 32 + (lane >> 4) * 16;
            #pragma unroll
            for (int mi = 0; mi < 4; mi++) {
                uint32_t ah[4], al[4];
                const uint32_t aa = base + (arow + mi * 16) * ROWB + acolb;
                ldsm4(ah, aa); ldsm4(al, aa + TILEB);
                #pragma unroll
                for (int ni = 0; ni < 4; ni++)
                    mma16816(acc[mi][ni], ah, bh[2 * ni], bh[2 * ni + 1]);
                #pragma unroll
                for (int ni = 0; ni < 4; ni++)
                    mma16816(acc[mi][ni], ah, bl[2 * ni], bl[2 * ni + 1]);
                #pragma unroll
                for (int ni = 0; ni < 4; ni++)
                    mma16816(acc[mi][ni], al, bh[2 * ni], bh[2 * ni + 1]);
            }
        }
        __syncthreads();
    }
}

/* ===================== K0: fused norm + fp16 split of xn ===================== */
__global__ __launch_bounds__(256) void k_norm_cvt(
    const float* __restrict__ x, const float* __restrict__ g)
{
    const int token = blockIdx.x * 8 + (threadIdx.x >> 5);
    const int lane  = threadIdx.x & 31;
    const float4* xp = (const float4*)(x + (size_t)token * DD);
    float4 v0 = xp[lane], v1 = xp[lane + 32];
    float sum = v0.x * v0.x + v0.y * v0.y + v0.z * v0.z + v0.w * v0.w
              + v1.x * v1.x + v1.y * v1.y + v1.z * v1.z + v1.w * v1.w;
    #pragma unroll
    for (int o = 16; o; o >>= 1) sum += __shfl_xor_sync(0xFFFFFFFFu, sum, o);
    float norm = sqrtf(sum * (1.f / (float)DD));
    float s = g[0] / fmaxf(norm, EPSV);

    uint2 h0, l0, h1, l1;
    h0.x = fsplit2(v0.x * s, v0.y * s, l0.x);
    h0.y = fsplit2(v0.z * s, v0.w * s, l0.y);
    h1.x = fsplit2(v1.x * s, v1.y * s, l1.x);
    h1.y = fsplit2(v1.z * s, v1.w * s, l1.y);
    const size_t base = (size_t)token * DD + lane * 4;
    *(uint2*)(g_xh + base)       = h0;
    *(uint2*)(g_xl + base)       = l0;
    *(uint2*)(g_xh + base + 128) = h1;
    *(uint2*)(g_xl + base + 128) = l1;
}

/* ===================== weight fp16 split (device-side dest select) ======== */
__global__ __launch_bounds__(256) void k_cvt_sel(
    const float* __restrict__ src, int which, int n4)
{
    __half* hi; __half* lo;
    if (which == 0) { hi = g_wuvh; lo = g_wuvl; }
    else            { hi = g_woh;  lo = g_wol;  }
    const int i = blockIdx.x * 256 + threadIdx.x;
    if (i >= n4) return;
    float4 v = ((const float4*)src)[i];
    uint2 h, l;
    h.x = fsplit2(v.x, v.y, l.x);
    h.y = fsplit2(v.z, v.w, l.y);
    *(uint2*)(hi + (size_t)i * 4) = h;
    *(uint2*)(lo + (size_t)i * 4) = l;
}

/* ===================== K1: uv GEMM; grid (9, 1064) ===================== */
__global__ __launch_bounds__(256, 2) void k_uv_mma(
    const float* __restrict__ gamma, const float* __restrict__ beta)
{
    extern __shared__ char sm[];
    const int m0 = blockIdx.y * 128, by = blockIdx.x;
    float acc[4][4][4] = {};
    gemm_core32<8>(g_xh + (size_t)m0 * DD, g_xl + (size_t)m0 * DD,
                   g_wuvh + (size_t)by * 128 * DD, g_wuvl + (size_t)by * 128 * DD,
                   DD, DD, sm, acc);

    const int tid = threadIdx.x, wid = tid >> 5, lane = tid & 31;
    const int wm = (wid >> 2) * 64, wn = (wid & 3) * 32;
    const int gid2 = lane >> 2, tig = lane & 3;
    #pragma unroll
    for (int mi = 0; mi < 4; mi++) {
        #pragma unroll
        for (int ni = 0; ni < 4; ni++) {
            const float* a = acc[mi][ni];
            const int nl = wn + ni * 8 + tig * 2;
            #pragma unroll
            for (int rr = 0; rr < 2; rr++) {
                const int mr = m0 + wm + mi * 16 + gid2 + rr * 8;
                const float sv0 = silu(a[rr * 2]), sv1 = silu(a[rr * 2 + 1]);
                const int b = mr / TT, t = mr - b * TT;
                if (by < 4) {
                    float2 o = {sv0, sv1};
                    *(float2*)(g_u + (size_t)mr * EE + by * 128 + nl) = o;
                } else if (by < 8) {
                    const int col = (by - 4) * 128 + nl;
                    uint32_t lo, hi = fsplit2(sv0, sv1, lo);
                    const size_t vofs = ((size_t)b * NP + t) * EE + col;
                    *(uint32_t*)(g_vh + vofs) = hi;
                    *(uint32_t*)(g_vl + vofs) = lo;
                } else {
                    const float q0 = fmaf(sv0, gamma[nl],     beta[nl]);
                    const float q1 = fmaf(sv1, gamma[nl + 1], beta[nl + 1]);
                    const float k0 = fmaf(sv0, gamma[SSZ + nl],     beta[SSZ + nl]);
                    const float k1 = fmaf(sv1, gamma[SSZ + nl + 1], beta[SSZ + nl + 1]);
                    uint32_t lo, hi;
                    hi = fsplit2(q0, q1, lo);
                    const size_t qofs = ((size_t)b * MP + t) * SSZ + nl;
                    *(uint32_t*)(g_qh + qofs) = hi;
                    *(uint32_t*)(g_ql + qofs) = lo;
                    hi = fsplit2(k0, k1, lo);
                    const size_t kofs = ((size_t)b * NP + t) * SSZ + nl;
                    *(uint32_t*)(g_kh + kofs) = hi;
                    *(uint32_t*)(g_kl + kofs) = lo;
                }
            }
        }
    }
}

/* ===================== K2: scores on HMMA (unchanged) ===================== */
#define SC_QT  (MP * 32)
#define SC_KT  (NP * 32)
#define SC_STG (2*SC_QT + 2*SC_KT)
__global__ __launch_bounds__(256) void k_sc_mma()
{
    __shared__ char ssm[2 * SC_STG];
    const uint32_t sb = smem_u32(ssm);
    const int b = blockIdx.x;
    const int tid = threadIdx.x, wid = tid >> 5, lane = tid & 31;
    const int wm = (wid >> 2) * 80, wn = (wid & 3) * 48;

    auto load = [&](int kc, int s) {
        const uint32_t st = sb + s * SC_STG;
        #pragma unroll
        for (int c = tid; c < 2 * MP; c += 256) {
            const int row = c >> 1, off = c & 1;
            const size_t gofs = ((size_t)b * MP + row) * SSZ + kc * 16 + off * 8;
            CPA16(st + row * 32 + off * 16,         g_qh + gofs);
            CPA16(st + SC_QT + row * 32 + off * 16, g_ql + gofs);
        }
        #pragma unroll
        for (int c = tid; c < 2 * NP; c += 256) {
            const int row = c >> 1, off = c & 1;
            const size_t gofs = ((size_t)b * NP + row) * SSZ + kc * 16 + off * 8;
            CPA16(st + 2*SC_QT + row * 32 + off * 16,         g_kh + gofs);
            CPA16(st + 2*SC_QT + SC_KT + row * 32 + off * 16, g_kl + gofs);
        }
    };

    float acc[5][6][4] = {};
    load(0, 0); CPC();

    #pragma unroll 1
    for (int c = 0; c < 8; c++) {
        const int s = c & 1;
        if (c + 1 < 8) { load(c + 1, 1 - s); CPC(); CPW1(); }
        else           { CPW0(); }
        __syncthreads();

        const uint32_t qb = sb + s * SC_STG;
        const uint32_t kb = qb + 2 * SC_QT;
        const uint32_t klb = kb + SC_KT;

        uint32_t bh[3][4], bl[3][4];
        const uint32_t bcolb = ((lane >> 3) & 1) * 16;
        #pragma unroll
        for (int nj = 0; nj < 3; nj++) {
            const int brow = wn + nj * 16 + ((lane >> 4) & 1) * 8 + (lane & 7);
            ldsm4(bh[nj], kb  + brow * 32 + bcolb);
            ldsm4(bl[nj], klb + brow * 32 + bcolb);
        }
        const int arow = wm + (lane & 15);
        const uint32_t acolb = (lane >> 4) * 16;
        #pragma unroll
        for (int mi = 0; mi < 5; mi++) {
            uint32_t ah[4], al[4];
            const uint32_t aa = qb + (arow + mi * 16) * 32 + acolb;
            ldsm4(ah, aa); ldsm4(al, aa + SC_QT);
            #pragma unroll
            for (int nb = 0; nb < 6; nb++)
                mma16816(acc[mi][nb], ah, bh[nb >> 1][(nb & 1) * 2], bh[nb >> 1][(nb & 1) * 2 + 1]);
            #pragma unroll
            for (int nb = 0; nb < 6; nb++)
                mma16816(acc[mi][nb], ah, bl[nb >> 1][(nb & 1) * 2], bl[nb >> 1][(nb & 1) * 2 + 1]);
            #pragma unroll
            for (int nb = 0; nb < 6; nb++)
                mma16816(acc[mi][nb], al, bh[nb >> 1][(nb & 1) * 2], bh[nb >> 1][(nb & 1) * 2 + 1]);
        }
        __syncthreads();
    }

    #pragma unroll
    for (int mi = 0; mi < 5; mi++) {
        #pragma unroll
        for (int nb = 0; nb < 6; nb++) {
            const int j = wn + nb * 8 + (lane & 3) * 2;
            #pragma unroll
            for (int rr = 0; rr < 2; rr++) {
                const int i = wm + mi * 16 + (lane >> 2) + rr * 8;
                float s0 = fmaxf(acc[mi][nb][rr * 2]     * INV_SQRT_S, 0.f);
                float s1 = fmaxf(acc[mi][nb][rr * 2 + 1] * INV_SQRT_S, 0.f);
                s0 *= s0; s1 *= s1;
                uint32_t lo, hi = fsplit2(s0, s1, lo);
                const size_t ofs = ((size_t)b * MP + i) * NP + j;
                *(uint32_t*)(g_ph + ofs) = hi;
                *(uint32_t*)(g_pl + ofs) = lo;
            }
        }
    }
}

/* ===================== K3: attn = u ⊙ (P v) on HMMA (unchanged) ========= */
#define AT_PT  (MP * 32)
#define AT_VT  (16 * 256)
#define AT_STG (2*AT_PT + 2*AT_VT)
__global__ __launch_bounds__(256) void k_at_mma()
{
    __shared__ char ssm[2 * AT_STG];
    const uint32_t sb = smem_u32(ssm);
    const int b = blockIdx.y, e0 = blockIdx.x * 128;
    const int tid = threadIdx.x, wid = tid >> 5, lane = tid & 31;
    const int wm = (wid >> 2) * 80, wn = (wid & 3) * 32;

    auto load = [&](int kc, int s) {
        const uint32_t st = sb + s * AT_STG;
        #pragma unroll
        for (int c = tid; c < 2 * MP; c += 256) {
            const int row = c >> 1, off = c & 1;
            const size_t gofs = ((size_t)b * MP + row) * NP + kc * 16 + off * 8;
            CPA16(st + row * 32 + off * 16,         g_ph + gofs);
            CPA16(st + AT_PT + row * 32 + off * 16, g_pl + gofs);
        }
        {
            const int c = tid;
            const int row = c >> 4, col = c & 15;
            const size_t gofs = ((size_t)b * NP + kc * 16 + row) * EE + e0 + col * 8;
            CPA16(st + 2*AT_PT + row * 256 + col * 16,         g_vh + gofs);
            CPA16(st + 2*AT_PT + AT_VT + row * 256 + col * 16, g_vl + gofs);
        }
    };

    float acc[5][4][4] = {};
    load(0, 0); CPC();

    #pragma unroll 1
    for (int c = 0; c < 12; c++) {
        const int s = c & 1;
        if (c + 1 < 12) { load(c + 1, 1 - s); CPC(); CPW1(); }
        else            { CPW0(); }
        __syncthreads();

        const uint32_t pb = sb + s * AT_STG;
        const uint32_t vb = pb + 2 * AT_PT;
        const uint32_t vlb = vb + AT_VT;

        uint32_t bh[4][2], bl[4][2];
        const int l16 = lane & 15;
        #pragma unroll
        for (int nb = 0; nb < 4; nb++) {
            const uint32_t va = l16 * 256 + (wn + nb * 8) * 2;
            ldsm2t(bh[nb], vb + va);
            ldsm2t(bl[nb], vlb + va);
        }
        const int arow = wm + (lane & 15);
        const uint32_t acolb = (lane >> 4) * 16;
        #pragma unroll
        for (int mi = 0; mi < 5; mi++) {
            uint32_t ah[4], al[4];
            const uint32_t aa = pb + (arow + mi * 16) * 32 + acolb;
            ldsm4(ah, aa); ldsm4(al, aa + AT_PT);
            #pragma unroll
            for (int nb = 0; nb < 4; nb++)
                mma16816(acc[mi][nb], ah, bh[nb][0], bh[nb][1]);
            #pragma unroll
            for (int nb = 0; nb < 4; nb++)
                mma16816(acc[mi][nb], ah, bl[nb][0], bl[nb][1]);
            #pragma unroll
            for (int nb = 0; nb < 4; nb++)
                mma16816(acc[mi][nb], al, bh[nb][0], bh[nb][1]);
        }
        __syncthreads();
    }

    #pragma unroll
    for (int mi = 0; mi < 5; mi++) {
        #pragma unroll
        for (int nb = 0; nb < 4; nb++) {
            const int e = e0 + wn + nb * 8 + (lane & 3) * 2;
            #pragma unroll
            for (int rr = 0; rr < 2; rr++) {
                const int i = wm + mi * 16 + (lane >> 2) + rr * 8;
                if (i < TT) {
                    const size_t m = (size_t)b * TT + i;
                    float2 uu = *(const float2*)(g_u + m * EE + e);
                    const float w0 = uu.x * acc[mi][nb][rr * 2];
                    const float w1 = uu.y * acc[mi][nb][rr * 2 + 1];
                    uint32_t lo, hi = fsplit2(w0, w1, lo);
                    *(uint32_t*)(g_wwh + m * EE + e) = hi;
                    *(uint32_t*)(g_wwl + m * EE + e) = lo;
                }
            }
        }
    }
}

/* ===================== K4: out GEMM; grid (2, 1064) ===================== */
__global__ __launch_bounds__(256, 2) void k_out_mma(
    const float* __restrict__ x, const float* __restrict__ res_scale,
    float* __restrict__ out)
{
    extern __shared__ char sm[];
    const int m0 = blockIdx.y * 128, by = blockIdx.x;
    float acc[4][4][4] = {};
    gemm_core32<16>(g_wwh + (size_t)m0 * EE, g_wwl + (size_t)m0 * EE,
                    g_woh + (size_t)by * 128 * EE, g_wol + (size_t)by * 128 * EE,
                    EE, EE, sm, acc);

    const int tid = threadIdx.x, wid = tid >> 5, lane = tid & 31;
    const int wm = (wid >> 2) * 64, wn = (wid & 3) * 32;
    const int gid2 = lane >> 2, tig = lane & 3;
    #pragma unroll
    for (int mi = 0; mi < 4; mi++) {
        #pragma unroll
        for (int ni = 0; ni < 4; ni++) {
            const float* a = acc[mi][ni];
            const int col = by * 128 + wn + ni * 8 + tig * 2;
            const int mr = m0 + wm + mi * 16 + gid2;
            float2 rv = *(const float2*)(res_scale + col);
            float2 x0 = *(const float2*)(x + (size_t)mr * DD + col);
            float2 x1 = *(const float2*)(x + (size_t)(mr + 8) * DD + col);
            float2 o0 = {fmaf(x0.x, rv.x, a[0]), fmaf(x0.y, rv.y, a[1])};
            float2 o1 = {fmaf(x1.x, rv.x, a[2]), fmaf(x1.y, rv.y, a[3])};
            *(float2*)(out + (size_t)mr * DD + col)       = o0;
            *(float2*)(out + (size_t)(mr + 8) * DD + col) = o1;
        }
    }
}

/* ===================== launch ===================== */
extern "C" void kernel_launch(void* const* d_in, const int* in_sizes, int n_in,
                              void* d_out, int out_size)
{
    const float* x         = (const float*)d_in[0];
    const float* W_uv      = (const float*)d_in[1];
    const float* W_o       = (const float*)d_in[2];
    const float* gamma     = (const float*)d_in[3];
    const float* beta      = (const float*)d_in[4];
    const float* g         = (const float*)d_in[5];
    const float* res_scale = (const float*)d_in[6];
    float* out = (float*)d_out;

    const int gsm = 2 * STAGEB;   /* 81920 */
    cudaFuncSetAttribute(k_uv_mma,  cudaFuncAttributeMaxDynamicSharedMemorySize, gsm);
    cudaFuncSetAttribute(k_out_mma, cudaFuncAttributeMaxDynamicSharedMemorySize, gsm);

    k_norm_cvt<<<MTOT / 8, 256>>>(x, g);
    k_cvt_sel<<<(1152 * DD / 4 + 255) / 256, 256>>>(W_uv, 0, 1152 * DD / 4);
    k_cvt_sel<<<(DD * EE / 4 + 255) / 256, 256>>>(W_o, 1, DD * EE / 4);
    k_uv_mma<<<dim3(9, MTOT / 128), 256, gsm>>>(gamma, beta);
    k_sc_mma<<<BB, 256>>>();
    k_at_mma<<<dim3(4, BB), 256>>>();
    k_out_mma<<<dim3(2, MTOT / 128), 256, gsm>>>(x, res_scale, out);
}

// round 10
// speedup vs baseline: 2.3990x; 1.0308x over previous
#include <cuda_runtime.h>
#include <cuda_fp16.h>
#include <cstdint>
#include <math.h>

#define BB   1024
#define TT   133
#define DD   256
#define EE   512
#define SSZ  128
#define MTOT (BB*TT)          /* 136192 */
#define MP   160
#define NP   192
#define EPSV 1e-5f
#define INV_SQRT_S 0.08838834764831845f

/* -------- scratch (device globals, 16B-aligned). Pad regions stay BSS-zero. */
__device__ __align__(16) float  g_u[(size_t)MTOT * EE];
__device__ __align__(16) __half g_xh[(size_t)MTOT * DD];
__device__ __align__(16) __half g_xl[(size_t)MTOT * DD];
__device__ __align__(16) __half g_wwh[(size_t)MTOT * EE];
__device__ __align__(16) __half g_wwl[(size_t)MTOT * EE];
__device__ __align__(16) __half g_wuvh[1152 * DD];
__device__ __align__(16) __half g_wuvl[1152 * DD];
__device__ __align__(16) __half g_woh[DD * EE];
__device__ __align__(16) __half g_wol[DD * EE];
__device__ __align__(16) __half g_qh[(size_t)BB * MP * SSZ];
__device__ __align__(16) __half g_ql[(size_t)BB * MP * SSZ];
__device__ __align__(16) __half g_kh[(size_t)BB * NP * SSZ];
__device__ __align__(16) __half g_kl[(size_t)BB * NP * SSZ];
__device__ __align__(16) __half g_vh[(size_t)BB * NP * EE];
__device__ __align__(16) __half g_vl[(size_t)BB * NP * EE];

/* ================= helpers ================= */
__device__ __forceinline__ uint32_t smem_u32(const void* p) {
    uint32_t a;
    asm("{ .reg .u64 t; cvta.to.shared.u64 t, %1; cvt.u32.u64 %0, t; }" : "=r"(a) : "l"(p));
    return a;
}
#define CPA16(dst, src) asm volatile("cp.async.cg.shared.global [%0], [%1], 16;" \
    :: "r"(dst), "l"(__cvta_generic_to_global(src)))
#define CPC()  asm volatile("cp.async.commit_group;")
#define CPW1() asm volatile("cp.async.wait_group 1;")
#define CPW0() asm volatile("cp.async.wait_group 0;")

__device__ __forceinline__ void ldsm4(uint32_t* r, uint32_t addr) {
    asm volatile("ldmatrix.sync.aligned.m8n8.x4.shared.b16 {%0,%1,%2,%3}, [%4];"
                 : "=r"(r[0]), "=r"(r[1]), "=r"(r[2]), "=r"(r[3]) : "r"(addr));
}
__device__ __forceinline__ void ldsm2(uint32_t* r, uint32_t addr) {
    asm volatile("ldmatrix.sync.aligned.m8n8.x2.shared.b16 {%0,%1}, [%2];"
                 : "=r"(r[0]), "=r"(r[1]) : "r"(addr));
}
__device__ __forceinline__ void ldsm2t(uint32_t* r, uint32_t addr) {
    asm volatile("ldmatrix.sync.aligned.m8n8.x2.trans.shared.b16 {%0,%1}, [%2];"
                 : "=r"(r[0]), "=r"(r[1]) : "r"(addr));
}
__device__ __forceinline__ void mma16816(float* d, const uint32_t* a,
                                         uint32_t b0, uint32_t b1) {
    asm volatile("mma.sync.aligned.m16n8k16.row.col.f32.f16.f16.f32 "
                 "{%0,%1,%2,%3}, {%4,%5,%6,%7}, {%8,%9}, {%0,%1,%2,%3};"
                 : "+f"(d[0]), "+f"(d[1]), "+f"(d[2]), "+f"(d[3])
                 : "r"(a[0]), "r"(a[1]), "r"(a[2]), "r"(a[3]), "r"(b0), "r"(b1));
}
__device__ __forceinline__ float silu(float v) { return v / (1.f + __expf(-v)); }

__device__ __forceinline__ uint32_t fsplit2(float a, float b, uint32_t& lo) {
    __half ha = __float2half(a), hb = __float2half(b);
    __half la = __float2half(a - __half2float(ha));
    __half lb = __float2half(b - __half2float(hb));
    __half2 hh = __halves2half2(ha, hb);
    __half2 ll = __halves2half2(la, lb);
    lo = reinterpret_cast<uint32_t&>(ll);
    return reinterpret_cast<uint32_t&>(hh);
}

/* ===================== BK=32 dense GEMM core (dynamic smem) ============= */
#define ROWB   80
#define TILEB  10240
#define STAGEB 40960

template<int NCH>
__device__ __forceinline__ void gemm_core32(
    const __half* gAh, const __half* gAl, const __half* gBh, const __half* gBl,
    int lda, int ldb, char* sm, float acc[4][4][4])
{
    const int tid = threadIdx.x, wid = tid >> 5, lane = tid & 31;
    const int wm = (wid >> 2) * 64, wn = (wid & 3) * 32;
    const int r = tid >> 1, qp = (tid & 1) * 2;
    const uint32_t s0 = smem_u32(sm);

    auto load = [&](int kc, int s) {
        const uint32_t da = s0 + s * STAGEB + r * ROWB + qp * 16;
        const int kofs = kc * 32 + qp * 8;
        const __half* pa = gAh + (size_t)r * lda + kofs;
        const __half* pl = gAl + (size_t)r * lda + kofs;
        const __half* pb = gBh + (size_t)r * ldb + kofs;
        const __half* pc = gBl + (size_t)r * ldb + kofs;
        CPA16(da,                pa); CPA16(da + 16,                pa + 8);
        CPA16(da + TILEB,        pl); CPA16(da + TILEB + 16,        pl + 8);
        CPA16(da + 2*TILEB,      pb); CPA16(da + 2*TILEB + 16,      pb + 8);
        CPA16(da + 3*TILEB,      pc); CPA16(da + 3*TILEB + 16,      pc + 8);
    };

    load(0, 0); CPC();

    #pragma unroll 1
    for (int c = 0; c < NCH; c++) {
        const int s = c & 1;
        if (c + 1 < NCH) { load(c + 1, 1 - s); CPC(); CPW1(); }
        else             { CPW0(); }
        __syncthreads();

        const uint32_t base = s0 + s * STAGEB;
        const uint32_t boff = base + 2 * TILEB;
        #pragma unroll
        for (int ks = 0; ks < 2; ks++) {
            uint32_t bh[8], bl[8];
            const int brow = wn + ((lane >> 4) & 1) * 8 + (lane & 7);
            const uint32_t bcolb = ks * 32 + ((lane >> 3) & 1) * 16;
            const uint32_t ba0 = boff + brow * ROWB + bcolb;
            const uint32_t ba1 = ba0 + 16 * ROWB;
            ldsm4(bh,     ba0);          ldsm4(bh + 4, ba1);
            ldsm4(bl,     ba0 + TILEB);  ldsm4(bl + 4, ba1 + TILEB);

            const int arow = wm + (lane & 15);
            const uint32_t acolb = ks * 32 + (lane >> 4) * 16;
            #pragma unroll
            for (int mi = 0; mi < 4; mi++) {
                uint32_t ah[4], al[4];
                const uint32_t aa = base + (arow + mi * 16) * ROWB + acolb;
                ldsm4(ah, aa); ldsm4(al, aa + TILEB);
                #pragma unroll
                for (int ni = 0; ni < 4; ni++)
                    mma16816(acc[mi][ni], ah, bh[2 * ni], bh[2 * ni + 1]);
                #pragma unroll
                for (int ni = 0; ni < 4; ni++)
                    mma16816(acc[mi][ni], ah, bl[2 * ni], bl[2 * ni + 1]);
                #pragma unroll
                for (int ni = 0; ni < 4; ni++)
                    mma16816(acc[mi][ni], al, bh[2 * ni], bh[2 * ni + 1]);
            }
        }
        __syncthreads();
    }
}

/* ===================== K0: fused norm + fp16 split of xn ===================== */
__global__ __launch_bounds__(256) void k_norm_cvt(
    const float* __restrict__ x, const float* __restrict__ g)
{
    const int token = blockIdx.x * 8 + (threadIdx.x >> 5);
    const int lane  = threadIdx.x & 31;
    const float4* xp = (const float4*)(x + (size_t)token * DD);
    float4 v0 = xp[lane], v1 = xp[lane + 32];
    float sum = v0.x * v0.x + v0.y * v0.y + v0.z * v0.z + v0.w * v0.w
              + v1.x * v1.x + v1.y * v1.y + v1.z * v1.z + v1.w * v1.w;
    #pragma unroll
    for (int o = 16; o; o >>= 1) sum += __shfl_xor_sync(0xFFFFFFFFu, sum, o);
    float norm = sqrtf(sum * (1.f / (float)DD));
    float s = g[0] / fmaxf(norm, EPSV);

    uint2 h0, l0, h1, l1;
    h0.x = fsplit2(v0.x * s, v0.y * s, l0.x);
    h0.y = fsplit2(v0.z * s, v0.w * s, l0.y);
    h1.x = fsplit2(v1.x * s, v1.y * s, l1.x);
    h1.y = fsplit2(v1.z * s, v1.w * s, l1.y);
    const size_t base = (size_t)token * DD + lane * 4;
    *(uint2*)(g_xh + base)       = h0;
    *(uint2*)(g_xl + base)       = l0;
    *(uint2*)(g_xh + base + 128) = h1;
    *(uint2*)(g_xl + base + 128) = l1;
}

/* ===================== weight fp16 split (device-side dest select) ======== */
__global__ __launch_bounds__(256) void k_cvt_sel(
    const float* __restrict__ src, int which, int n4)
{
    __half* hi; __half* lo;
    if (which == 0) { hi = g_wuvh; lo = g_wuvl; }
    else            { hi = g_woh;  lo = g_wol;  }
    const int i = blockIdx.x * 256 + threadIdx.x;
    if (i >= n4) return;
    float4 v = ((const float4*)src)[i];
    uint2 h, l;
    h.x = fsplit2(v.x, v.y, l.x);
    h.y = fsplit2(v.z, v.w, l.y);
    *(uint2*)(hi + (size_t)i * 4) = h;
    *(uint2*)(lo + (size_t)i * 4) = l;
}

/* ===================== K1: uv GEMM; grid (9, 1064) ===================== */
__global__ __launch_bounds__(256, 2) void k_uv_mma(
    const float* __restrict__ gamma, const float* __restrict__ beta)
{
    extern __shared__ char sm[];
    const int m0 = blockIdx.y * 128, by = blockIdx.x;
    float acc[4][4][4] = {};
    gemm_core32<8>(g_xh + (size_t)m0 * DD, g_xl + (size_t)m0 * DD,
                   g_wuvh + (size_t)by * 128 * DD, g_wuvl + (size_t)by * 128 * DD,
                   DD, DD, sm, acc);

    const int tid = threadIdx.x, wid = tid >> 5, lane = tid & 31;
    const int wm = (wid >> 2) * 64, wn = (wid & 3) * 32;
    const int gid2 = lane >> 2, tig = lane & 3;
    #pragma unroll
    for (int mi = 0; mi < 4; mi++) {
        #pragma unroll
        for (int ni = 0; ni < 4; ni++) {
            const float* a = acc[mi][ni];
            const int nl = wn + ni * 8 + tig * 2;
            #pragma unroll
            for (int rr = 0; rr < 2; rr++) {
                const int mr = m0 + wm + mi * 16 + gid2 + rr * 8;
                const float sv0 = silu(a[rr * 2]), sv1 = silu(a[rr * 2 + 1]);
                const int b = mr / TT, t = mr - b * TT;
                if (by < 4) {
                    float2 o = {sv0, sv1};
                    *(float2*)(g_u + (size_t)mr * EE + by * 128 + nl) = o;
                } else if (by < 8) {
                    const int col = (by - 4) * 128 + nl;
                    uint32_t lo, hi = fsplit2(sv0, sv1, lo);
                    const size_t vofs = ((size_t)b * NP + t) * EE + col;
                    *(uint32_t*)(g_vh + vofs) = hi;
                    *(uint32_t*)(g_vl + vofs) = lo;
                } else {
                    const float q0 = fmaf(sv0, gamma[nl],     beta[nl]);
                    const float q1 = fmaf(sv1, gamma[nl + 1], beta[nl + 1]);
                    const float k0 = fmaf(sv0, gamma[SSZ + nl],     beta[SSZ + nl]);
                    const float k1 = fmaf(sv1, gamma[SSZ + nl + 1], beta[SSZ + nl + 1]);
                    uint32_t lo, hi;
                    hi = fsplit2(q0, q1, lo);
                    const size_t qofs = ((size_t)b * MP + t) * SSZ + nl;
                    *(uint32_t*)(g_qh + qofs) = hi;
                    *(uint32_t*)(g_ql + qofs) = lo;
                    hi = fsplit2(k0, k1, lo);
                    const size_t kofs = ((size_t)b * NP + t) * SSZ + nl;
                    *(uint32_t*)(g_kh + kofs) = hi;
                    *(uint32_t*)(g_kl + kofs) = lo;
                }
            }
        }
    }
}

/* ===================== K2+K3 fused: per-batch attention =====================
 * Phase 1: S = q k^T (160x192xK128), P = relu(S/sqrt)^2 -> SMEM limbs
 *          (row stride 400B -> conflict-free ldsm).
 * Phase 2: for 4 e-blocks of 128: attn = P @ v (K=192), w = u*attn -> limbs.
 * 512 threads (16 warps), 1 CTA/SM, 173056B dynamic smem. */
#define SC_QT   (MP * 32)               /* 5120  */
#define SC_KT   (NP * 32)               /* 6144  */
#define SC_STG  (2*SC_QT + 2*SC_KT)     /* 22528 */
#define FA_PH   (2 * SC_STG)            /* 45056: Ph offset */
#define FA_PROW 400                     /* P row stride bytes (192*2 + 16) */
#define FA_PSZ  (MP * FA_PROW)          /* 64000 */
#define FA_VROW 272                     /* v tile row stride (128*2 + 16) */
#define FA_VT   (16 * FA_VROW)          /* 4352 */
#define FA_VSTG (2 * FA_VT)             /* 8704 per stage (hi+lo) */
#define FA_SMEM (FA_PH + 2 * FA_PSZ)    /* 173056 */

__global__ __launch_bounds__(512, 1) void k_fa()
{
    extern __shared__ char fsm[];
    const uint32_t sb = smem_u32(fsm);
    const uint32_t P0 = sb + FA_PH;         /* Ph */
    const uint32_t P1 = P0 + FA_PSZ;        /* Pl */
    const int b = blockIdx.x;
    const int tid = threadIdx.x, wid = tid >> 5, lane = tid & 31;

    /* ------------- phase 1: scores ------------- */
    {
        const int wm = (wid >> 3) * 80, wn = (wid & 7) * 24;

        auto load = [&](int kc, int s) {
            const uint32_t st = sb + s * SC_STG;
            if (tid < 2 * MP) {
                const int row = tid >> 1, off = tid & 1;
                const size_t gofs = ((size_t)b * MP + row) * SSZ + kc * 16 + off * 8;
                CPA16(st + row * 32 + off * 16,         g_qh + gofs);
                CPA16(st + SC_QT + row * 32 + off * 16, g_ql + gofs);
            }
            if (tid < 2 * NP) {
                const int row = tid >> 1, off = tid & 1;
                const size_t gofs = ((size_t)b * NP + row) * SSZ + kc * 16 + off * 8;
                CPA16(st + 2*SC_QT + row * 32 + off * 16,         g_kh + gofs);
                CPA16(st + 2*SC_QT + SC_KT + row * 32 + off * 16, g_kl + gofs);
            }
        };

        float acc[5][3][4] = {};
        load(0, 0); CPC();

        #pragma unroll 1
        for (int c = 0; c < 8; c++) {
            const int s = c & 1;
            if (c + 1 < 8) { load(c + 1, 1 - s); CPC(); CPW1(); }
            else           { CPW0(); }
            __syncthreads();

            const uint32_t qb = sb + s * SC_STG;
            const uint32_t kb = qb + 2 * SC_QT, klb = kb + SC_KT;

            uint32_t bh[6], bl[6];
            {
                const int br = wn + ((lane >> 4) & 1) * 8 + (lane & 7);
                const uint32_t bc = ((lane >> 3) & 1) * 16;
                ldsm4(bh, kb  + br * 32 + bc);
                ldsm4(bl, klb + br * 32 + bc);
                const int br2 = wn + 16 + (lane & 7);
                ldsm2(bh + 4, kb  + br2 * 32 + bc);
                ldsm2(bl + 4, klb + br2 * 32 + bc);
            }
            const int arow = wm + (lane & 15);
            const uint32_t acolb = (lane >> 4) * 16;
            #pragma unroll
            for (int mi = 0; mi < 5; mi++) {
                uint32_t ah[4], al[4];
                const uint32_t aa = qb + (arow + mi * 16) * 32 + acolb;
                ldsm4(ah, aa); ldsm4(al, aa + SC_QT);
                #pragma unroll
                for (int nb = 0; nb < 3; nb++)
                    mma16816(acc[mi][nb], ah, bh[2 * nb], bh[2 * nb + 1]);
                #pragma unroll
                for (int nb = 0; nb < 3; nb++)
                    mma16816(acc[mi][nb], ah, bl[2 * nb], bl[2 * nb + 1]);
                #pragma unroll
                for (int nb = 0; nb < 3; nb++)
                    mma16816(acc[mi][nb], al, bh[2 * nb], bh[2 * nb + 1]);
            }
            __syncthreads();
        }

        /* epilogue -> smem P limbs */
        #pragma unroll
        for (int mi = 0; mi < 5; mi++) {
            #pragma unroll
            for (int nb = 0; nb < 3; nb++) {
                const int j = wn + nb * 8 + (lane & 3) * 2;
                #pragma unroll
                for (int rr = 0; rr < 2; rr++) {
                    const int i = wm + mi * 16 + (lane >> 2) + rr * 8;
                    float s0 = fmaxf(acc[mi][nb][rr * 2]     * INV_SQRT_S, 0.f);
                    float s1 = fmaxf(acc[mi][nb][rr * 2 + 1] * INV_SQRT_S, 0.f);
                    s0 *= s0; s1 *= s1;
                    uint32_t lo, hi = fsplit2(s0, s1, lo);
                    const uint32_t po = i * FA_PROW + j * 2;
                    asm volatile("st.shared.b32 [%0], %1;" :: "r"(P0 + po), "r"(hi) : "memory");
                    asm volatile("st.shared.b32 [%0], %1;" :: "r"(P1 + po), "r"(lo) : "memory");
                }
            }
        }
    }
    __syncthreads();

    /* ------------- phase 2: w = u * (P @ v) ------------- */
    {
        const int wm = (wid >> 3) * 80, wn = (wid & 7) * 16;

        #pragma unroll 1
        for (int ep = 0; ep < 4; ep++) {
            const int e0 = ep * 128;

            auto loadv = [&](int kc, int s) {
                const uint32_t st = sb + s * FA_VSTG;
                const int half = tid >> 8;       /* 0: hi, 1: lo */
                const int t = tid & 255;
                const int row = t >> 4, col = t & 15;
                const size_t gofs = ((size_t)b * NP + kc * 16 + row) * EE + e0 + col * 8;
                CPA16(st + half * FA_VT + row * FA_VROW + col * 16,
                      (half ? g_vl : g_vh) + gofs);
            };

            float acc[5][2][4] = {};
            loadv(0, 0); CPC();

            #pragma unroll 1
            for (int c = 0; c < 12; c++) {
                const int s = c & 1;
                if (c + 1 < 12) { loadv(c + 1, 1 - s); CPC(); CPW1(); }
                else            { CPW0(); }
                __syncthreads();

                const uint32_t vbh = sb + s * FA_VSTG, vbl = vbh + FA_VT;
                uint32_t bh[2][2], bl[2][2];
                const int l16 = lane & 15;
                #pragma unroll
                for (int nb = 0; nb < 2; nb++) {
                    const uint32_t va = l16 * FA_VROW + (wn + nb * 8) * 2;
                    ldsm2t(bh[nb], vbh + va);
                    ldsm2t(bl[nb], vbl + va);
                }
                const int arow = wm + (lane & 15);
                const uint32_t ac = (c * 16 + (lane >> 4) * 8) * 2;
                #pragma unroll
                for (int mi = 0; mi < 5; mi++) {
                    uint32_t ah[4], al[4];
                    const uint32_t pa = (arow + mi * 16) * FA_PROW + ac;
                    ldsm4(ah, P0 + pa); ldsm4(al, P1 + pa);
                    #pragma unroll
                    for (int nb = 0; nb < 2; nb++)
                        mma16816(acc[mi][nb], ah, bh[nb][0], bh[nb][1]);
                    #pragma unroll
                    for (int nb = 0; nb < 2; nb++)
                        mma16816(acc[mi][nb], ah, bl[nb][0], bl[nb][1]);
                    #pragma unroll
                    for (int nb = 0; nb < 2; nb++)
                        mma16816(acc[mi][nb], al, bh[nb][0], bh[nb][1]);
                }
                __syncthreads();
            }

            /* epilogue: w = u * attn -> global limbs */
            #pragma unroll
            for (int mi = 0; mi < 5; mi++) {
                #pragma unroll
                for (int nb = 0; nb < 2; nb++) {
                    const int e = e0 + wn + nb * 8 + (lane & 3) * 2;
                    #pragma unroll
                    for (int rr = 0; rr < 2; rr++) {
                        const int i = wm + mi * 16 + (lane >> 2) + rr * 8;
                        if (i < TT) {
                            const size_t m = (size_t)b * TT + i;
                            float2 uu = *(const float2*)(g_u + m * EE + e);
                            const float w0 = uu.x * acc[mi][nb][rr * 2];
                            const float w1 = uu.y * acc[mi][nb][rr * 2 + 1];
                            uint32_t lo, hi = fsplit2(w0, w1, lo);
                            *(uint32_t*)(g_wwh + m * EE + e) = hi;
                            *(uint32_t*)(g_wwl + m * EE + e) = lo;
                        }
                    }
                }
            }
        }
    }
}

/* ===================== K4: out GEMM; grid (2, 1064) ===================== */
__global__ __launch_bounds__(256, 2) void k_out_mma(
    const float* __restrict__ x, const float* __restrict__ res_scale,
    float* __restrict__ out)
{
    extern __shared__ char sm[];
    const int m0 = blockIdx.y * 128, by = blockIdx.x;
    float acc[4][4][4] = {};
    gemm_core32<16>(g_wwh + (size_t)m0 * EE, g_wwl + (size_t)m0 * EE,
                    g_woh + (size_t)by * 128 * EE, g_wol + (size_t)by * 128 * EE,
                    EE, EE, sm, acc);

    const int tid = threadIdx.x, wid = tid >> 5, lane = tid & 31;
    const int wm = (wid >> 2) * 64, wn = (wid & 3) * 32;
    const int gid2 = lane >> 2, tig = lane & 3;
    #pragma unroll
    for (int mi = 0; mi < 4; mi++) {
        #pragma unroll
        for (int ni = 0; ni < 4; ni++) {
            const float* a = acc[mi][ni];
            const int col = by * 128 + wn + ni * 8 + tig * 2;
            const int mr = m0 + wm + mi * 16 + gid2;
            float2 rv = *(const float2*)(res_scale + col);
            float2 x0 = *(const float2*)(x + (size_t)mr * DD + col);
            float2 x1 = *(const float2*)(x + (size_t)(mr + 8) * DD + col);
            float2 o0 = {fmaf(x0.x, rv.x, a[0]), fmaf(x0.y, rv.y, a[1])};
            float2 o1 = {fmaf(x1.x, rv.x, a[2]), fmaf(x1.y, rv.y, a[3])};
            *(float2*)(out + (size_t)mr * DD + col)       = o0;
            *(float2*)(out + (size_t)(mr + 8) * DD + col) = o1;
        }
    }
}

/* ===================== launch ===================== */
extern "C" void kernel_launch(void* const* d_in, const int* in_sizes, int n_in,
                              void* d_out, int out_size)
{
    const float* x         = (const float*)d_in[0];
    const float* W_uv      = (const float*)d_in[1];
    const float* W_o       = (const float*)d_in[2];
    const float* gamma     = (const float*)d_in[3];
    const float* beta      = (const float*)d_in[4];
    const float* g         = (const float*)d_in[5];
    const float* res_scale = (const float*)d_in[6];
    float* out = (float*)d_out;

    const int gsm = 2 * STAGEB;   /* 81920 */
    cudaFuncSetAttribute(k_uv_mma,  cudaFuncAttributeMaxDynamicSharedMemorySize, gsm);
    cudaFuncSetAttribute(k_out_mma, cudaFuncAttributeMaxDynamicSharedMemorySize, gsm);
    cudaFuncSetAttribute(k_fa,      cudaFuncAttributeMaxDynamicSharedMemorySize, FA_SMEM);

    k_norm_cvt<<<MTOT / 8, 256>>>(x, g);
    k_cvt_sel<<<(1152 * DD / 4 + 255) / 256, 256>>>(W_uv, 0, 1152 * DD / 4);
    k_cvt_sel<<<(DD * EE / 4 + 255) / 256, 256>>>(W_o, 1, DD * EE / 4);
    k_uv_mma<<<dim3(9, MTOT / 128), 256, gsm>>>(gamma, beta);
    k_fa<<<BB, 512, FA_SMEM>>>();
    k_out_mma<<<dim3(2, MTOT / 128), 256, gsm>>>(x, res_scale, out);
}

// round 11
// speedup vs baseline: 2.5346x; 1.0565x over previous
#include <cuda_runtime.h>
#include <cuda_fp16.h>
#include <cstdint>
#include <math.h>

#define BB   1024
#define TT   133
#define DD   256
#define EE   512
#define SSZ  128
#define MTOT (BB*TT)          /* 136192 */
#define MP   160
#define NP   192
#define EPSV 1e-5f
#define INV_SQRT_S 0.08838834764831845f

/* -------- scratch (device globals, 16B-aligned). Pad regions stay BSS-zero. */
__device__ __align__(16) float  g_u[(size_t)MTOT * EE];
__device__ __align__(16) __half g_xh[(size_t)MTOT * DD];
__device__ __align__(16) __half g_xl[(size_t)MTOT * DD];
__device__ __align__(16) __half g_wwh[(size_t)MTOT * EE];
__device__ __align__(16) __half g_wwl[(size_t)MTOT * EE];
__device__ __align__(16) __half g_wuvh[1152 * DD];
__device__ __align__(16) __half g_wuvl[1152 * DD];
__device__ __align__(16) __half g_woh[DD * EE];
__device__ __align__(16) __half g_wol[DD * EE];
__device__ __align__(16) __half g_qh[(size_t)BB * MP * SSZ];
__device__ __align__(16) __half g_ql[(size_t)BB * MP * SSZ];
__device__ __align__(16) __half g_kh[(size_t)BB * NP * SSZ];
__device__ __align__(16) __half g_kl[(size_t)BB * NP * SSZ];
__device__ __align__(16) __half g_vh[(size_t)BB * NP * EE];
__device__ __align__(16) __half g_vl[(size_t)BB * NP * EE];

/* ================= helpers ================= */
__device__ __forceinline__ uint32_t smem_u32(const void* p) {
    uint32_t a;
    asm("{ .reg .u64 t; cvta.to.shared.u64 t, %1; cvt.u32.u64 %0, t; }" : "=r"(a) : "l"(p));
    return a;
}
#define CPA16(dst, src) asm volatile("cp.async.cg.shared.global [%0], [%1], 16;" \
    :: "r"(dst), "l"(__cvta_generic_to_global(src)))
#define CPC()  asm volatile("cp.async.commit_group;")
#define CPW1() asm volatile("cp.async.wait_group 1;")
#define CPW0() asm volatile("cp.async.wait_group 0;")

__device__ __forceinline__ void ldsm4(uint32_t* r, uint32_t addr) {
    asm volatile("ldmatrix.sync.aligned.m8n8.x4.shared.b16 {%0,%1,%2,%3}, [%4];"
                 : "=r"(r[0]), "=r"(r[1]), "=r"(r[2]), "=r"(r[3]) : "r"(addr));
}
__device__ __forceinline__ void ldsm2(uint32_t* r, uint32_t addr) {
    asm volatile("ldmatrix.sync.aligned.m8n8.x2.shared.b16 {%0,%1}, [%2];"
                 : "=r"(r[0]), "=r"(r[1]) : "r"(addr));
}
__device__ __forceinline__ void ldsm2t(uint32_t* r, uint32_t addr) {
    asm volatile("ldmatrix.sync.aligned.m8n8.x2.trans.shared.b16 {%0,%1}, [%2];"
                 : "=r"(r[0]), "=r"(r[1]) : "r"(addr));
}
__device__ __forceinline__ void mma16816(float* d, const uint32_t* a,
                                         uint32_t b0, uint32_t b1) {
    asm volatile("mma.sync.aligned.m16n8k16.row.col.f32.f16.f16.f32 "
                 "{%0,%1,%2,%3}, {%4,%5,%6,%7}, {%8,%9}, {%0,%1,%2,%3};"
                 : "+f"(d[0]), "+f"(d[1]), "+f"(d[2]), "+f"(d[3])
                 : "r"(a[0]), "r"(a[1]), "r"(a[2]), "r"(a[3]), "r"(b0), "r"(b1));
}
__device__ __forceinline__ float silu(float v) { return v / (1.f + __expf(-v)); }

__device__ __forceinline__ uint32_t fsplit2(float a, float b, uint32_t& lo) {
    __half ha = __float2half(a), hb = __float2half(b);
    __half la = __float2half(a - __half2float(ha));
    __half lb = __float2half(b - __half2float(hb));
    __half2 hh = __halves2half2(ha, hb);
    __half2 ll = __halves2half2(la, lb);
    lo = reinterpret_cast<uint32_t&>(ll);
    return reinterpret_cast<uint32_t&>(hh);
}

/* ===================== BK=32 dense GEMM core (dynamic smem) ============= */
#define ROWB   80
#define TILEB  10240
#define STAGEB 40960

template<int NCH>
__device__ __forceinline__ void gemm_core32(
    const __half* gAh, const __half* gAl, const __half* gBh, const __half* gBl,
    int lda, int ldb, char* sm, float acc[4][4][4])
{
    const int tid = threadIdx.x, wid = tid >> 5, lane = tid & 31;
    const int wm = (wid >> 2) * 64, wn = (wid & 3) * 32;
    const int r = tid >> 1, qp = (tid & 1) * 2;
    const uint32_t s0 = smem_u32(sm);

    auto load = [&](int kc, int s) {
        const uint32_t da = s0 + s * STAGEB + r * ROWB + qp * 16;
        const int kofs = kc * 32 + qp * 8;
        const __half* pa = gAh + (size_t)r * lda + kofs;
        const __half* pl = gAl + (size_t)r * lda + kofs;
        const __half* pb = gBh + (size_t)r * ldb + kofs;
        const __half* pc = gBl + (size_t)r * ldb + kofs;
        CPA16(da,                pa); CPA16(da + 16,                pa + 8);
        CPA16(da + TILEB,        pl); CPA16(da + TILEB + 16,        pl + 8);
        CPA16(da + 2*TILEB,      pb); CPA16(da + 2*TILEB + 16,      pb + 8);
        CPA16(da + 3*TILEB,      pc); CPA16(da + 3*TILEB + 16,      pc + 8);
    };

    load(0, 0); CPC();

    #pragma unroll 1
    for (int c = 0; c < NCH; c++) {
        const int s = c & 1;
        if (c + 1 < NCH) { load(c + 1, 1 - s); CPC(); CPW1(); }
        else             { CPW0(); }
        __syncthreads();

        const uint32_t base = s0 + s * STAGEB;
        const uint32_t boff = base + 2 * TILEB;
        #pragma unroll
        for (int ks = 0; ks < 2; ks++) {
            uint32_t bh[8], bl[8];
            const int brow = wn + ((lane >> 4) & 1) * 8 + (lane & 7);
            const uint32_t bcolb = ks * 32 + ((lane >> 3) & 1) * 16;
            const uint32_t ba0 = boff + brow * ROWB + bcolb;
            const uint32_t ba1 = ba0 + 16 * ROWB;
            ldsm4(bh,     ba0);          ldsm4(bh + 4, ba1);
            ldsm4(bl,     ba0 + TILEB);  ldsm4(bl + 4, ba1 + TILEB);

            const int arow = wm + (lane & 15);
            const uint32_t acolb = ks * 32 + (lane >> 4) * 16;
            #pragma unroll
            for (int mi = 0; mi < 4; mi++) {
                uint32_t ah[4], al[4];
                const uint32_t aa = base + (arow + mi * 16) * ROWB + acolb;
                ldsm4(ah, aa); ldsm4(al, aa + TILEB);
                #pragma unroll
                for (int ni = 0; ni < 4; ni++)
                    mma16816(acc[mi][ni], ah, bh[2 * ni], bh[2 * ni + 1]);
                #pragma unroll
                for (int ni = 0; ni < 4; ni++)
                    mma16816(acc[mi][ni], ah, bl[2 * ni], bl[2 * ni + 1]);
                #pragma unroll
                for (int ni = 0; ni < 4; ni++)
                    mma16816(acc[mi][ni], al, bh[2 * ni], bh[2 * ni + 1]);
            }
        }
        __syncthreads();
    }
}

/* ===================== K0: fused norm + fp16 split of xn ===================== */
__global__ __launch_bounds__(256) void k_norm_cvt(
    const float* __restrict__ x, const float* __restrict__ g)
{
    const int token = blockIdx.x * 8 + (threadIdx.x >> 5);
    const int lane  = threadIdx.x & 31;
    const float4* xp = (const float4*)(x + (size_t)token * DD);
    float4 v0 = xp[lane], v1 = xp[lane + 32];
    float sum = v0.x * v0.x + v0.y * v0.y + v0.z * v0.z + v0.w * v0.w
              + v1.x * v1.x + v1.y * v1.y + v1.z * v1.z + v1.w * v1.w;
    #pragma unroll
    for (int o = 16; o; o >>= 1) sum += __shfl_xor_sync(0xFFFFFFFFu, sum, o);
    float norm = sqrtf(sum * (1.f / (float)DD));
    float s = g[0] / fmaxf(norm, EPSV);

    uint2 h0, l0, h1, l1;
    h0.x = fsplit2(v0.x * s, v0.y * s, l0.x);
    h0.y = fsplit2(v0.z * s, v0.w * s, l0.y);
    h1.x = fsplit2(v1.x * s, v1.y * s, l1.x);
    h1.y = fsplit2(v1.z * s, v1.w * s, l1.y);
    const size_t base = (size_t)token * DD + lane * 4;
    *(uint2*)(g_xh + base)       = h0;
    *(uint2*)(g_xl + base)       = l0;
    *(uint2*)(g_xh + base + 128) = h1;
    *(uint2*)(g_xl + base + 128) = l1;
}

/* ===================== weight fp16 split (device-side dest select) ======== */
__global__ __launch_bounds__(256) void k_cvt_sel(
    const float* __restrict__ src, int which, int n4)
{
    __half* hi; __half* lo;
    if (which == 0) { hi = g_wuvh; lo = g_wuvl; }
    else            { hi = g_woh;  lo = g_wol;  }
    const int i = blockIdx.x * 256 + threadIdx.x;
    if (i >= n4) return;
    float4 v = ((const float4*)src)[i];
    uint2 h, l;
    h.x = fsplit2(v.x, v.y, l.x);
    h.y = fsplit2(v.z, v.w, l.y);
    *(uint2*)(hi + (size_t)i * 4) = h;
    *(uint2*)(lo + (size_t)i * 4) = l;
}

/* ===================== K1: uv GEMM; grid (9, 1064) ===================== */
__global__ __launch_bounds__(256, 2) void k_uv_mma(
    const float* __restrict__ gamma, const float* __restrict__ beta)
{
    extern __shared__ char sm[];
    const int m0 = blockIdx.y * 128, by = blockIdx.x;
    float acc[4][4][4] = {};
    gemm_core32<8>(g_xh + (size_t)m0 * DD, g_xl + (size_t)m0 * DD,
                   g_wuvh + (size_t)by * 128 * DD, g_wuvl + (size_t)by * 128 * DD,
                   DD, DD, sm, acc);

    const int tid = threadIdx.x, wid = tid >> 5, lane = tid & 31;
    const int wm = (wid >> 2) * 64, wn = (wid & 3) * 32;
    const int gid2 = lane >> 2, tig = lane & 3;
    #pragma unroll
    for (int mi = 0; mi < 4; mi++) {
        #pragma unroll
        for (int ni = 0; ni < 4; ni++) {
            const float* a = acc[mi][ni];
            const int nl = wn + ni * 8 + tig * 2;
            #pragma unroll
            for (int rr = 0; rr < 2; rr++) {
                const int mr = m0 + wm + mi * 16 + gid2 + rr * 8;
                const float sv0 = silu(a[rr * 2]), sv1 = silu(a[rr * 2 + 1]);
                const int b = mr / TT, t = mr - b * TT;
                if (by < 4) {
                    float2 o = {sv0, sv1};
                    *(float2*)(g_u + (size_t)mr * EE + by * 128 + nl) = o;
                } else if (by < 8) {
                    const int col = (by - 4) * 128 + nl;
                    uint32_t lo, hi = fsplit2(sv0, sv1, lo);
                    const size_t vofs = ((size_t)b * NP + t) * EE + col;
                    *(uint32_t*)(g_vh + vofs) = hi;
                    *(uint32_t*)(g_vl + vofs) = lo;
                } else {
                    const float q0 = fmaf(sv0, gamma[nl],     beta[nl]);
                    const float q1 = fmaf(sv1, gamma[nl + 1], beta[nl + 1]);
                    const float k0 = fmaf(sv0, gamma[SSZ + nl],     beta[SSZ + nl]);
                    const float k1 = fmaf(sv1, gamma[SSZ + nl + 1], beta[SSZ + nl + 1]);
                    uint32_t lo, hi;
                    hi = fsplit2(q0, q1, lo);
                    const size_t qofs = ((size_t)b * MP + t) * SSZ + nl;
                    *(uint32_t*)(g_qh + qofs) = hi;
                    *(uint32_t*)(g_ql + qofs) = lo;
                    hi = fsplit2(k0, k1, lo);
                    const size_t kofs = ((size_t)b * NP + t) * SSZ + nl;
                    *(uint32_t*)(g_kh + kofs) = hi;
                    *(uint32_t*)(g_kl + kofs) = lo;
                }
            }
        }
    }
}

/* ===================== K2+K3 fused: per-batch attention =====================
 * Phase 1: S = q k^T (160x192xK128), P = relu(S/sqrt)^2 -> SMEM limbs.
 * Phase 2: 2 passes of N=256: attn = P @ v (K=192), w = u*attn -> limbs.
 *          V double-buffers live in the (dead) phase-1 q/k staging region.
 * 512 threads (16 warps), 1 CTA/SM, 173056B dynamic smem. */
#define SC_QT   (MP * 32)               /* 5120  */
#define SC_KT   (NP * 32)               /* 6144  */
#define SC_STG  (2*SC_QT + 2*SC_KT)     /* 22528 */
#define FA_PH   (2 * SC_STG)            /* 45056: Ph offset */
#define FA_PROW 400                     /* P row stride bytes */
#define FA_PSZ  (MP * FA_PROW)          /* 64000 */
#define FA_VROW 528                     /* v tile row stride (256*2 + 16) */
#define FA_VT   (16 * FA_VROW)          /* 8448 */
#define FA_VSTG (2 * FA_VT)             /* 16896 per stage (hi+lo) */
#define FA_SMEM (FA_PH + 2 * FA_PSZ)    /* 173056 (V stages fit in [0,FA_PH)) */

__global__ __launch_bounds__(512, 1) void k_fa()
{
    extern __shared__ char fsm[];
    const uint32_t sb = smem_u32(fsm);
    const uint32_t P0 = sb + FA_PH;         /* Ph */
    const uint32_t P1 = P0 + FA_PSZ;        /* Pl */
    const int b = blockIdx.x;
    const int tid = threadIdx.x, wid = tid >> 5, lane = tid & 31;

    /* ------------- phase 1: scores ------------- */
    {
        const int wm = (wid >> 3) * 80, wn = (wid & 7) * 24;

        auto load = [&](int kc, int s) {
            const uint32_t st = sb + s * SC_STG;
            if (tid < 2 * MP) {
                const int row = tid >> 1, off = tid & 1;
                const size_t gofs = ((size_t)b * MP + row) * SSZ + kc * 16 + off * 8;
                CPA16(st + row * 32 + off * 16,         g_qh + gofs);
                CPA16(st + SC_QT + row * 32 + off * 16, g_ql + gofs);
            }
            if (tid < 2 * NP) {
                const int row = tid >> 1, off = tid & 1;
                const size_t gofs = ((size_t)b * NP + row) * SSZ + kc * 16 + off * 8;
                CPA16(st + 2*SC_QT + row * 32 + off * 16,         g_kh + gofs);
                CPA16(st + 2*SC_QT + SC_KT + row * 32 + off * 16, g_kl + gofs);
            }
        };

        float acc[5][3][4] = {};
        load(0, 0); CPC();

        #pragma unroll 1
        for (int c = 0; c < 8; c++) {
            const int s = c & 1;
            if (c + 1 < 8) { load(c + 1, 1 - s); CPC(); CPW1(); }
            else           { CPW0(); }
            __syncthreads();

            const uint32_t qb = sb + s * SC_STG;
            const uint32_t kb = qb + 2 * SC_QT, klb = kb + SC_KT;

            uint32_t bh[6], bl[6];
            {
                const int br = wn + ((lane >> 4) & 1) * 8 + (lane & 7);
                const uint32_t bc = ((lane >> 3) & 1) * 16;
                ldsm4(bh, kb  + br * 32 + bc);
                ldsm4(bl, klb + br * 32 + bc);
                const int br2 = wn + 16 + (lane & 7);
                ldsm2(bh + 4, kb  + br2 * 32 + bc);
                ldsm2(bl + 4, klb + br2 * 32 + bc);
            }
            const int arow = wm + (lane & 15);
            const uint32_t acolb = (lane >> 4) * 16;
            #pragma unroll
            for (int mi = 0; mi < 5; mi++) {
                uint32_t ah[4], al[4];
                const uint32_t aa = qb + (arow + mi * 16) * 32 + acolb;
                ldsm4(ah, aa); ldsm4(al, aa + SC_QT);
                #pragma unroll
                for (int nb = 0; nb < 3; nb++)
                    mma16816(acc[mi][nb], ah, bh[2 * nb], bh[2 * nb + 1]);
                #pragma unroll
                for (int nb = 0; nb < 3; nb++)
                    mma16816(acc[mi][nb], ah, bl[2 * nb], bl[2 * nb + 1]);
                #pragma unroll
                for (int nb = 0; nb < 3; nb++)
                    mma16816(acc[mi][nb], al, bh[2 * nb], bh[2 * nb + 1]);
            }
            __syncthreads();
        }

        /* epilogue -> smem P limbs */
        #pragma unroll
        for (int mi = 0; mi < 5; mi++) {
            #pragma unroll
            for (int nb = 0; nb < 3; nb++) {
                const int j = wn + nb * 8 + (lane & 3) * 2;
                #pragma unroll
                for (int rr = 0; rr < 2; rr++) {
                    const int i = wm + mi * 16 + (lane >> 2) + rr * 8;
                    float s0 = fmaxf(acc[mi][nb][rr * 2]     * INV_SQRT_S, 0.f);
                    float s1 = fmaxf(acc[mi][nb][rr * 2 + 1] * INV_SQRT_S, 0.f);
                    s0 *= s0; s1 *= s1;
                    uint32_t lo, hi = fsplit2(s0, s1, lo);
                    const uint32_t po = i * FA_PROW + j * 2;
                    asm volatile("st.shared.b32 [%0], %1;" :: "r"(P0 + po), "r"(hi) : "memory");
                    asm volatile("st.shared.b32 [%0], %1;" :: "r"(P1 + po), "r"(lo) : "memory");
                }
            }
        }
    }
    __syncthreads();

    /* ------------- phase 2: w = u * (P @ v), N=256 per pass ------------- */
    {
        const int wm = (wid >> 3) * 80, wn = (wid & 7) * 32;

        #pragma unroll 1
        for (int ep = 0; ep < 2; ep++) {
            const int e0 = ep * 256;

            /* V tile per stage: 16 k-rows x 256 e-cols, hi+lo limbs.
             * Each thread issues 2 cp.async (one per limb). */
            auto loadv = [&](int kc, int s) {
                const uint32_t st = sb + s * FA_VSTG;
                const int row = tid >> 5, ch = tid & 31;
                const size_t gofs = ((size_t)b * NP + kc * 16 + row) * EE + e0 + ch * 8;
                CPA16(st + row * FA_VROW + ch * 16,         g_vh + gofs);
                CPA16(st + FA_VT + row * FA_VROW + ch * 16, g_vl + gofs);
            };

            float acc[5][4][4] = {};
            loadv(0, 0); CPC();

            #pragma unroll 1
            for (int c = 0; c < 12; c++) {
                const int s = c & 1;
                if (c + 1 < 12) { loadv(c + 1, 1 - s); CPC(); CPW1(); }
                else            { CPW0(); }
                __syncthreads();

                const uint32_t vbh = sb + s * FA_VSTG, vbl = vbh + FA_VT;
                uint32_t bh[4][2], bl[4][2];
                const int l16 = lane & 15;
                #pragma unroll
                for (int nb = 0; nb < 4; nb++) {
                    const uint32_t va = l16 * FA_VROW + (wn + nb * 8) * 2;
                    ldsm2t(bh[nb], vbh + va);
                    ldsm2t(bl[nb], vbl + va);
                }
                const int arow = wm + (lane & 15);
                const uint32_t ac = (c * 16 + (lane >> 4) * 8) * 2;
                #pragma unroll
                for (int mi = 0; mi < 5; mi++) {
                    uint32_t ah[4], al[4];
                    const uint32_t pa = (arow + mi * 16) * FA_PROW + ac;
                    ldsm4(ah, P0 + pa); ldsm4(al, P1 + pa);
                    #pragma unroll
                    for (int nb = 0; nb < 4; nb++)
                        mma16816(acc[mi][nb], ah, bh[nb][0], bh[nb][1]);
                    #pragma unroll
                    for (int nb = 0; nb < 4; nb++)
                        mma16816(acc[mi][nb], ah, bl[nb][0], bl[nb][1]);
                    #pragma unroll
                    for (int nb = 0; nb < 4; nb++)
                        mma16816(acc[mi][nb], al, bh[nb][0], bh[nb][1]);
                }
                __syncthreads();
            }

            /* epilogue: w = u * attn -> global limbs */
            #pragma unroll
            for (int mi = 0; mi < 5; mi++) {
                #pragma unroll
                for (int nb = 0; nb < 4; nb++) {
                    const int e = e0 + wn + nb * 8 + (lane & 3) * 2;
                    #pragma unroll
                    for (int rr = 0; rr < 2; rr++) {
                        const int i = wm + mi * 16 + (lane >> 2) + rr * 8;
                        if (i < TT) {
                            const size_t m = (size_t)b * TT + i;
                            float2 uu = *(const float2*)(g_u + m * EE + e);
                            const float w0 = uu.x * acc[mi][nb][rr * 2];
                            const float w1 = uu.y * acc[mi][nb][rr * 2 + 1];
                            uint32_t lo, hi = fsplit2(w0, w1, lo);
                            *(uint32_t*)(g_wwh + m * EE + e) = hi;
                            *(uint32_t*)(g_wwl + m * EE + e) = lo;
                        }
                    }
                }
            }
        }
    }
}

/* ===================== K4: out GEMM; grid (2, 1064) ===================== */
__global__ __launch_bounds__(256, 2) void k_out_mma(
    const float* __restrict__ x, const float* __restrict__ res_scale,
    float* __restrict__ out)
{
    extern __shared__ char sm[];
    const int m0 = blockIdx.y * 128, by = blockIdx.x;
    float acc[4][4][4] = {};
    gemm_core32<16>(g_wwh + (size_t)m0 * EE, g_wwl + (size_t)m0 * EE,
                    g_woh + (size_t)by * 128 * EE, g_wol + (size_t)by * 128 * EE,
                    EE, EE, sm, acc);

    const int tid = threadIdx.x, wid = tid >> 5, lane = tid & 31;
    const int wm = (wid >> 2) * 64, wn = (wid & 3) * 32;
    const int gid2 = lane >> 2, tig = lane & 3;
    #pragma unroll
    for (int mi = 0; mi < 4; mi++) {
        #pragma unroll
        for (int ni = 0; ni < 4; ni++) {
            const float* a = acc[mi][ni];
            const int col = by * 128 + wn + ni * 8 + tig * 2;
            const int mr = m0 + wm + mi * 16 + gid2;
            float2 rv = *(const float2*)(res_scale + col);
            float2 x0 = *(const float2*)(x + (size_t)mr * DD + col);
            float2 x1 = *(const float2*)(x + (size_t)(mr + 8) * DD + col);
            float2 o0 = {fmaf(x0.x, rv.x, a[0]), fmaf(x0.y, rv.y, a[1])};
            float2 o1 = {fmaf(x1.x, rv.x, a[2]), fmaf(x1.y, rv.y, a[3])};
            *(float2*)(out + (size_t)mr * DD + col)       = o0;
            *(float2*)(out + (size_t)(mr + 8) * DD + col) = o1;
        }
    }
}

/* ===================== launch ===================== */
extern "C" void kernel_launch(void* const* d_in, const int* in_sizes, int n_in,
                              void* d_out, int out_size)
{
    const float* x         = (const float*)d_in[0];
    const float* W_uv      = (const float*)d_in[1];
    const float* W_o       = (const float*)d_in[2];
    const float* gamma     = (const float*)d_in[3];
    const float* beta      = (const float*)d_in[4];
    const float* g         = (const float*)d_in[5];
    const float* res_scale = (const float*)d_in[6];
    float* out = (float*)d_out;

    const int gsm = 2 * STAGEB;   /* 81920 */
    cudaFuncSetAttribute(k_uv_mma,  cudaFuncAttributeMaxDynamicSharedMemorySize, gsm);
    cudaFuncSetAttribute(k_out_mma, cudaFuncAttributeMaxDynamicSharedMemorySize, gsm);
    cudaFuncSetAttribute(k_fa,      cudaFuncAttributeMaxDynamicSharedMemorySize, FA_SMEM);

    k_norm_cvt<<<MTOT / 8, 256>>>(x, g);
    k_cvt_sel<<<(1152 * DD / 4 + 255) / 256, 256>>>(W_uv, 0, 1152 * DD / 4);
    k_cvt_sel<<<(DD * EE / 4 + 255) / 256, 256>>>(W_o, 1, DD * EE / 4);
    k_uv_mma<<<dim3(9, MTOT / 128), 256, gsm>>>(gamma, beta);
    k_fa<<<BB, 512, FA_SMEM>>>();
    k_out_mma<<<dim3(2, MTOT / 128), 256, gsm>>>(x, res_scale, out);
}

// round 12
// speedup vs baseline: 2.8018x; 1.1054x over previous
#include <cuda_runtime.h>
#include <cuda_fp16.h>
#include <cstdint>
#include <math.h>

#define BB   1024
#define TT   133
#define DD   256
#define EE   512
#define SSZ  128
#define MTOT (BB*TT)          /* 136192 */
#define MP   160
#define NP   192
#define EPSV 1e-5f
#define INV_SQRT_S 0.08838834764831845f

/* -------- scratch (device globals, 16B-aligned). Pad regions stay BSS-zero. */
__device__ __align__(16) float  g_u[(size_t)MTOT * EE];
__device__ __align__(16) __half g_xh[(size_t)MTOT * DD];
__device__ __align__(16) __half g_xl[(size_t)MTOT * DD];
__device__ __align__(16) __half g_ww[(size_t)MTOT * EE];    /* w, single fp16 */
__device__ __align__(16) __half g_wuvh[1152 * DD];
__device__ __align__(16) __half g_wuvl[1152 * DD];
__device__ __align__(16) __half g_woh[DD * EE];
__device__ __align__(16) __half g_wol[DD * EE];
__device__ __align__(16) __half g_qh[(size_t)BB * MP * SSZ];
__device__ __align__(16) __half g_ql[(size_t)BB * MP * SSZ];
__device__ __align__(16) __half g_kh[(size_t)BB * NP * SSZ];
__device__ __align__(16) __half g_kl[(size_t)BB * NP * SSZ];
__device__ __align__(16) __half g_vh[(size_t)BB * NP * EE];
__device__ __align__(16) __half g_vl[(size_t)BB * NP * EE];

/* ================= helpers ================= */
__device__ __forceinline__ uint32_t smem_u32(const void* p) {
    uint32_t a;
    asm("{ .reg .u64 t; cvta.to.shared.u64 t, %1; cvt.u32.u64 %0, t; }" : "=r"(a) : "l"(p));
    return a;
}
#define CPA16(dst, src) asm volatile("cp.async.cg.shared.global [%0], [%1], 16;" \
    :: "r"(dst), "l"(__cvta_generic_to_global(src)))
#define CPC()  asm volatile("cp.async.commit_group;")
#define CPW1() asm volatile("cp.async.wait_group 1;")
#define CPW0() asm volatile("cp.async.wait_group 0;")

__device__ __forceinline__ void ldsm4(uint32_t* r, uint32_t addr) {
    asm volatile("ldmatrix.sync.aligned.m8n8.x4.shared.b16 {%0,%1,%2,%3}, [%4];"
                 : "=r"(r[0]), "=r"(r[1]), "=r"(r[2]), "=r"(r[3]) : "r"(addr));
}
__device__ __forceinline__ void ldsm2(uint32_t* r, uint32_t addr) {
    asm volatile("ldmatrix.sync.aligned.m8n8.x2.shared.b16 {%0,%1}, [%2];"
                 : "=r"(r[0]), "=r"(r[1]) : "r"(addr));
}
__device__ __forceinline__ void ldsm2t(uint32_t* r, uint32_t addr) {
    asm volatile("ldmatrix.sync.aligned.m8n8.x2.trans.shared.b16 {%0,%1}, [%2];"
                 : "=r"(r[0]), "=r"(r[1]) : "r"(addr));
}
__device__ __forceinline__ void mma16816(float* d, const uint32_t* a,
                                         uint32_t b0, uint32_t b1) {
    asm volatile("mma.sync.aligned.m16n8k16.row.col.f32.f16.f16.f32 "
                 "{%0,%1,%2,%3}, {%4,%5,%6,%7}, {%8,%9}, {%0,%1,%2,%3};"
                 : "+f"(d[0]), "+f"(d[1]), "+f"(d[2]), "+f"(d[3])
                 : "r"(a[0]), "r"(a[1]), "r"(a[2]), "r"(a[3]), "r"(b0), "r"(b1));
}
__device__ __forceinline__ float silu(float v) { return v / (1.f + __expf(-v)); }

__device__ __forceinline__ uint32_t fsplit2(float a, float b, uint32_t& lo) {
    __half ha = __float2half(a), hb = __float2half(b);
    __half la = __float2half(a - __half2float(ha));
    __half lb = __float2half(b - __half2float(hb));
    __half2 hh = __halves2half2(ha, hb);
    __half2 ll = __halves2half2(la, lb);
    lo = reinterpret_cast<uint32_t&>(ll);
    return reinterpret_cast<uint32_t&>(hh);
}
__device__ __forceinline__ uint32_t fpack2(float a, float b) {
    __half2 h = __halves2half2(__float2half(a), __float2half(b));
    return reinterpret_cast<uint32_t&>(h);
}

/* ===================== BK=32 dense GEMM cores (dynamic smem) ============= */
#define ROWB   80
#define TILEB  10240
#define STAGEB 40960          /* 4 tiles: Ah Al Bh Bl (k_uv) */
#define STAGEB3 30720         /* 3 tiles: Ah Bh Bl (k_out)  */

template<int NCH>
__device__ __forceinline__ void gemm_core32(
    const __half* gAh, const __half* gAl, const __half* gBh, const __half* gBl,
    int lda, int ldb, char* sm, float acc[4][4][4])
{
    const int tid = threadIdx.x, wid = tid >> 5, lane = tid & 31;
    const int wm = (wid >> 2) * 64, wn = (wid & 3) * 32;
    const int r = tid >> 1, qp = (tid & 1) * 2;
    const uint32_t s0 = smem_u32(sm);

    auto load = [&](int kc, int s) {
        const uint32_t da = s0 + s * STAGEB + r * ROWB + qp * 16;
        const int kofs = kc * 32 + qp * 8;
        const __half* pa = gAh + (size_t)r * lda + kofs;
        const __half* pl = gAl + (size_t)r * lda + kofs;
        const __half* pb = gBh + (size_t)r * ldb + kofs;
        const __half* pc = gBl + (size_t)r * ldb + kofs;
        CPA16(da,                pa); CPA16(da + 16,                pa + 8);
        CPA16(da + TILEB,        pl); CPA16(da + TILEB + 16,        pl + 8);
        CPA16(da + 2*TILEB,      pb); CPA16(da + 2*TILEB + 16,      pb + 8);
        CPA16(da + 3*TILEB,      pc); CPA16(da + 3*TILEB + 16,      pc + 8);
    };

    load(0, 0); CPC();

    #pragma unroll 1
    for (int c = 0; c < NCH; c++) {
        const int s = c & 1;
        if (c + 1 < NCH) { load(c + 1, 1 - s); CPC(); CPW1(); }
        else             { CPW0(); }
        __syncthreads();

        const uint32_t base = s0 + s * STAGEB;
        const uint32_t boff = base + 2 * TILEB;
        #pragma unroll
        for (int ks = 0; ks < 2; ks++) {
            uint32_t bh[8], bl[8];
            const int brow = wn + ((lane >> 4) & 1) * 8 + (lane & 7);
            const uint32_t bcolb = ks * 32 + ((lane >> 3) & 1) * 16;
            const uint32_t ba0 = boff + brow * ROWB + bcolb;
            const uint32_t ba1 = ba0 + 16 * ROWB;
            ldsm4(bh,     ba0);          ldsm4(bh + 4, ba1);
            ldsm4(bl,     ba0 + TILEB);  ldsm4(bl + 4, ba1 + TILEB);

            const int arow = wm + (lane & 15);
            const uint32_t acolb = ks * 32 + (lane >> 4) * 16;
            #pragma unroll
            for (int mi = 0; mi < 4; mi++) {
                uint32_t ah[4], al[4];
                const uint32_t aa = base + (arow + mi * 16) * ROWB + acolb;
                ldsm4(ah, aa); ldsm4(al, aa + TILEB);
                #pragma unroll
                for (int ni = 0; ni < 4; ni++)
                    mma16816(acc[mi][ni], ah, bh[2 * ni], bh[2 * ni + 1]);
                #pragma unroll
                for (int ni = 0; ni < 4; ni++)
                    mma16816(acc[mi][ni], ah, bl[2 * ni], bl[2 * ni + 1]);
                #pragma unroll
                for (int ni = 0; ni < 4; ni++)
                    mma16816(acc[mi][ni], al, bh[2 * ni], bh[2 * ni + 1]);
            }
        }
        __syncthreads();
    }
}

/* A single-limb variant: D = A(Bh+Bl); stage = 3 tiles. */
template<int NCH>
__device__ __forceinline__ void gemm_core_a1(
    const __half* gA, const __half* gBh, const __half* gBl,
    int lda, int ldb, char* sm, float acc[4][4][4])
{
    const int tid = threadIdx.x, wid = tid >> 5, lane = tid & 31;
    const int wm = (wid >> 2) * 64, wn = (wid & 3) * 32;
    const int r = tid >> 1, qp = (tid & 1) * 2;
    const uint32_t s0 = smem_u32(sm);

    auto load = [&](int kc, int s) {
        const uint32_t da = s0 + s * STAGEB3 + r * ROWB + qp * 16;
        const int kofs = kc * 32 + qp * 8;
        const __half* pa = gA  + (size_t)r * lda + kofs;
        const __half* pb = gBh + (size_t)r * ldb + kofs;
        const __half* pc = gBl + (size_t)r * ldb + kofs;
        CPA16(da,                pa); CPA16(da + 16,                pa + 8);
        CPA16(da + TILEB,        pb); CPA16(da + TILEB + 16,        pb + 8);
        CPA16(da + 2*TILEB,      pc); CPA16(da + 2*TILEB + 16,      pc + 8);
    };

    load(0, 0); CPC();

    #pragma unroll 1
    for (int c = 0; c < NCH; c++) {
        const int s = c & 1;
        if (c + 1 < NCH) { load(c + 1, 1 - s); CPC(); CPW1(); }
        else             { CPW0(); }
        __syncthreads();

        const uint32_t base = s0 + s * STAGEB3;
        const uint32_t boff = base + TILEB;
        #pragma unroll
        for (int ks = 0; ks < 2; ks++) {
            uint32_t bh[8], bl[8];
            const int brow = wn + ((lane >> 4) & 1) * 8 + (lane & 7);
            const uint32_t bcolb = ks * 32 + ((lane >> 3) & 1) * 16;
            const uint32_t ba0 = boff + brow * ROWB + bcolb;
            const uint32_t ba1 = ba0 + 16 * ROWB;
            ldsm4(bh,     ba0);          ldsm4(bh + 4, ba1);
            ldsm4(bl,     ba0 + TILEB);  ldsm4(bl + 4, ba1 + TILEB);

            const int arow = wm + (lane & 15);
            const uint32_t acolb = ks * 32 + (lane >> 4) * 16;
            #pragma unroll
            for (int mi = 0; mi < 4; mi++) {
                uint32_t ah[4];
                const uint32_t aa = base + (arow + mi * 16) * ROWB + acolb;
                ldsm4(ah, aa);
                #pragma unroll
                for (int ni = 0; ni < 4; ni++)
                    mma16816(acc[mi][ni], ah, bh[2 * ni], bh[2 * ni + 1]);
                #pragma unroll
                for (int ni = 0; ni < 4; ni++)
                    mma16816(acc[mi][ni], ah, bl[2 * ni], bl[2 * ni + 1]);
            }
        }
        __syncthreads();
    }
}

/* ===================== K0: fused norm + fp16 split of xn ===================== */
__global__ __launch_bounds__(256) void k_norm_cvt(
    const float* __restrict__ x, const float* __restrict__ g)
{
    const int token = blockIdx.x * 8 + (threadIdx.x >> 5);
    const int lane  = threadIdx.x & 31;
    const float4* xp = (const float4*)(x + (size_t)token * DD);
    float4 v0 = xp[lane], v1 = xp[lane + 32];
    float sum = v0.x * v0.x + v0.y * v0.y + v0.z * v0.z + v0.w * v0.w
              + v1.x * v1.x + v1.y * v1.y + v1.z * v1.z + v1.w * v1.w;
    #pragma unroll
    for (int o = 16; o; o >>= 1) sum += __shfl_xor_sync(0xFFFFFFFFu, sum, o);
    float norm = sqrtf(sum * (1.f / (float)DD));
    float s = g[0] / fmaxf(norm, EPSV);

    uint2 h0, l0, h1, l1;
    h0.x = fsplit2(v0.x * s, v0.y * s, l0.x);
    h0.y = fsplit2(v0.z * s, v0.w * s, l0.y);
    h1.x = fsplit2(v1.x * s, v1.y * s, l1.x);
    h1.y = fsplit2(v1.z * s, v1.w * s, l1.y);
    const size_t base = (size_t)token * DD + lane * 4;
    *(uint2*)(g_xh + base)       = h0;
    *(uint2*)(g_xl + base)       = l0;
    *(uint2*)(g_xh + base + 128) = h1;
    *(uint2*)(g_xl + base + 128) = l1;
}

/* ===================== weight fp16 split (device-side dest select) ======== */
__global__ __launch_bounds__(256) void k_cvt_sel(
    const float* __restrict__ src, int which, int n4)
{
    __half* hi; __half* lo;
    if (which == 0) { hi = g_wuvh; lo = g_wuvl; }
    else            { hi = g_woh;  lo = g_wol;  }
    const int i = blockIdx.x * 256 + threadIdx.x;
    if (i >= n4) return;
    float4 v = ((const float4*)src)[i];
    uint2 h, l;
    h.x = fsplit2(v.x, v.y, l.x);
    h.y = fsplit2(v.z, v.w, l.y);
    *(uint2*)(hi + (size_t)i * 4) = h;
    *(uint2*)(lo + (size_t)i * 4) = l;
}

/* ===================== K1: uv GEMM; grid (9, 1064) ===================== */
__global__ __launch_bounds__(256, 2) void k_uv_mma(
    const float* __restrict__ gamma, const float* __restrict__ beta)
{
    extern __shared__ char sm[];
    const int m0 = blockIdx.y * 128, by = blockIdx.x;
    float acc[4][4][4] = {};
    gemm_core32<8>(g_xh + (size_t)m0 * DD, g_xl + (size_t)m0 * DD,
                   g_wuvh + (size_t)by * 128 * DD, g_wuvl + (size_t)by * 128 * DD,
                   DD, DD, sm, acc);

    const int tid = threadIdx.x, wid = tid >> 5, lane = tid & 31;
    const int wm = (wid >> 2) * 64, wn = (wid & 3) * 32;
    const int gid2 = lane >> 2, tig = lane & 3;
    #pragma unroll
    for (int mi = 0; mi < 4; mi++) {
        #pragma unroll
        for (int ni = 0; ni < 4; ni++) {
            const float* a = acc[mi][ni];
            const int nl = wn + ni * 8 + tig * 2;
            #pragma unroll
            for (int rr = 0; rr < 2; rr++) {
                const int mr = m0 + wm + mi * 16 + gid2 + rr * 8;
                const float sv0 = silu(a[rr * 2]), sv1 = silu(a[rr * 2 + 1]);
                const int b = mr / TT, t = mr - b * TT;
                if (by < 4) {
                    float2 o = {sv0, sv1};
                    *(float2*)(g_u + (size_t)mr * EE + by * 128 + nl) = o;
                } else if (by < 8) {
                    const int col = (by - 4) * 128 + nl;
                    uint32_t lo, hi = fsplit2(sv0, sv1, lo);
                    const size_t vofs = ((size_t)b * NP + t) * EE + col;
                    *(uint32_t*)(g_vh + vofs) = hi;
                    *(uint32_t*)(g_vl + vofs) = lo;
                } else {
                    const float q0 = fmaf(sv0, gamma[nl],     beta[nl]);
                    const float q1 = fmaf(sv1, gamma[nl + 1], beta[nl + 1]);
                    const float k0 = fmaf(sv0, gamma[SSZ + nl],     beta[SSZ + nl]);
                    const float k1 = fmaf(sv1, gamma[SSZ + nl + 1], beta[SSZ + nl + 1]);
                    uint32_t lo, hi;
                    hi = fsplit2(q0, q1, lo);
                    const size_t qofs = ((size_t)b * MP + t) * SSZ + nl;
                    *(uint32_t*)(g_qh + qofs) = hi;
                    *(uint32_t*)(g_ql + qofs) = lo;
                    hi = fsplit2(k0, k1, lo);
                    const size_t kofs = ((size_t)b * NP + t) * SSZ + nl;
                    *(uint32_t*)(g_kh + kofs) = hi;
                    *(uint32_t*)(g_kl + kofs) = lo;
                }
            }
        }
    }
}

/* ===================== K2+K3 fused: per-batch attention =====================
 * Phase 1: S = q k^T (3-term limbs), P = relu(S/sqrt)^2 -> SMEM single fp16.
 * Phase 2: 2 passes of N=256: attn = P(vh+vl), w = u*attn -> single fp16. */
#define SC_QT   (MP * 32)               /* 5120  */
#define SC_KT   (NP * 32)               /* 6144  */
#define SC_STG  (2*SC_QT + 2*SC_KT)     /* 22528 */
#define FA_PH   (2 * SC_STG)            /* 45056: P offset */
#define FA_PROW 400
#define FA_PSZ  (MP * FA_PROW)          /* 64000 */
#define FA_VROW 528
#define FA_VT   (16 * FA_VROW)          /* 8448 */
#define FA_VSTG (2 * FA_VT)             /* 16896 */
#define FA_SMEM (FA_PH + FA_PSZ)        /* 109056 */

__global__ __launch_bounds__(512, 1) void k_fa()
{
    extern __shared__ char fsm[];
    const uint32_t sb = smem_u32(fsm);
    const uint32_t P0 = sb + FA_PH;
    const int b = blockIdx.x;
    const int tid = threadIdx.x, wid = tid >> 5, lane = tid & 31;

    /* ------------- phase 1: scores ------------- */
    {
        const int wm = (wid >> 3) * 80, wn = (wid & 7) * 24;

        auto load = [&](int kc, int s) {
            const uint32_t st = sb + s * SC_STG;
            if (tid < 2 * MP) {
                const int row = tid >> 1, off = tid & 1;
                const size_t gofs = ((size_t)b * MP + row) * SSZ + kc * 16 + off * 8;
                CPA16(st + row * 32 + off * 16,         g_qh + gofs);
                CPA16(st + SC_QT + row * 32 + off * 16, g_ql + gofs);
            }
            if (tid < 2 * NP) {
                const int row = tid >> 1, off = tid & 1;
                const size_t gofs = ((size_t)b * NP + row) * SSZ + kc * 16 + off * 8;
                CPA16(st + 2*SC_QT + row * 32 + off * 16,         g_kh + gofs);
                CPA16(st + 2*SC_QT + SC_KT + row * 32 + off * 16, g_kl + gofs);
            }
        };

        float acc[5][3][4] = {};
        load(0, 0); CPC();

        #pragma unroll 1
        for (int c = 0; c < 8; c++) {
            const int s = c & 1;
            if (c + 1 < 8) { load(c + 1, 1 - s); CPC(); CPW1(); }
            else           { CPW0(); }
            __syncthreads();

            const uint32_t qb = sb + s * SC_STG;
            const uint32_t kb = qb + 2 * SC_QT, klb = kb + SC_KT;

            uint32_t bh[6], bl[6];
            {
                const int br = wn + ((lane >> 4) & 1) * 8 + (lane & 7);
                const uint32_t bc = ((lane >> 3) & 1) * 16;
                ldsm4(bh, kb  + br * 32 + bc);
                ldsm4(bl, klb + br * 32 + bc);
                const int br2 = wn + 16 + (lane & 7);
                ldsm2(bh + 4, kb  + br2 * 32 + bc);
                ldsm2(bl + 4, klb + br2 * 32 + bc);
            }
            const int arow = wm + (lane & 15);
            const uint32_t acolb = (lane >> 4) * 16;
            #pragma unroll
            for (int mi = 0; mi < 5; mi++) {
                uint32_t ah[4], al[4];
                const uint32_t aa = qb + (arow + mi * 16) * 32 + acolb;
                ldsm4(ah, aa); ldsm4(al, aa + SC_QT);
                #pragma unroll
                for (int nb = 0; nb < 3; nb++)
                    mma16816(acc[mi][nb], ah, bh[2 * nb], bh[2 * nb + 1]);
                #pragma unroll
                for (int nb = 0; nb < 3; nb++)
                    mma16816(acc[mi][nb], ah, bl[2 * nb], bl[2 * nb + 1]);
                #pragma unroll
                for (int nb = 0; nb < 3; nb++)
                    mma16816(acc[mi][nb], al, bh[2 * nb], bh[2 * nb + 1]);
            }
            __syncthreads();
        }

        /* epilogue -> smem P (single fp16) */
        #pragma unroll
        for (int mi = 0; mi < 5; mi++) {
            #pragma unroll
            for (int nb = 0; nb < 3; nb++) {
                const int j = wn + nb * 8 + (lane & 3) * 2;
                #pragma unroll
                for (int rr = 0; rr < 2; rr++) {
                    const int i = wm + mi * 16 + (lane >> 2) + rr * 8;
                    float s0 = fmaxf(acc[mi][nb][rr * 2]     * INV_SQRT_S, 0.f);
                    float s1 = fmaxf(acc[mi][nb][rr * 2 + 1] * INV_SQRT_S, 0.f);
                    uint32_t hi = fpack2(s0 * s0, s1 * s1);
                    asm volatile("st.shared.b32 [%0], %1;"
                                 :: "r"(P0 + i * FA_PROW + j * 2), "r"(hi) : "memory");
                }
            }
        }
    }
    __syncthreads();

    /* ------------- phase 2: w = u * (P @ v), N=256 per pass ------------- */
    {
        const int wm = (wid >> 3) * 80, wn = (wid & 7) * 32;

        #pragma unroll 1
        for (int ep = 0; ep < 2; ep++) {
            const int e0 = ep * 256;

            auto loadv = [&](int kc, int s) {
                const uint32_t st = sb + s * FA_VSTG;
                const int row = tid >> 5, ch = tid & 31;
                const size_t gofs = ((size_t)b * NP + kc * 16 + row) * EE + e0 + ch * 8;
                CPA16(st + row * FA_VROW + ch * 16,         g_vh + gofs);
                CPA16(st + FA_VT + row * FA_VROW + ch * 16, g_vl + gofs);
            };

            float acc[5][4][4] = {};
            loadv(0, 0); CPC();

            #pragma unroll 1
            for (int c = 0; c < 12; c++) {
                const int s = c & 1;
                if (c + 1 < 12) { loadv(c + 1, 1 - s); CPC(); CPW1(); }
                else            { CPW0(); }
                __syncthreads();

                const uint32_t vbh = sb + s * FA_VSTG, vbl = vbh + FA_VT;
                uint32_t bh[4][2], bl[4][2];
                const int l16 = lane & 15;
                #pragma unroll
                for (int nb = 0; nb < 4; nb++) {
                    const uint32_t va = l16 * FA_VROW + (wn + nb * 8) * 2;
                    ldsm2t(bh[nb], vbh + va);
                    ldsm2t(bl[nb], vbl + va);
                }
                const int arow = wm + (lane & 15);
                const uint32_t ac = (c * 16 + (lane >> 4) * 8) * 2;
                #pragma unroll
                for (int mi = 0; mi < 5; mi++) {
                    uint32_t ah[4];
                    ldsm4(ah, P0 + (arow + mi * 16) * FA_PROW + ac);
                    #pragma unroll
                    for (int nb = 0; nb < 4; nb++)
                        mma16816(acc[mi][nb], ah, bh[nb][0], bh[nb][1]);
                    #pragma unroll
                    for (int nb = 0; nb < 4; nb++)
                        mma16816(acc[mi][nb], ah, bl[nb][0], bl[nb][1]);
                }
                __syncthreads();
            }

            /* epilogue: w = u * attn -> single fp16 */
            #pragma unroll
            for (int mi = 0; mi < 5; mi++) {
                #pragma unroll
                for (int nb = 0; nb < 4; nb++) {
                    const int e = e0 + wn + nb * 8 + (lane & 3) * 2;
                    #pragma unroll
                    for (int rr = 0; rr < 2; rr++) {
                        const int i = wm + mi * 16 + (lane >> 2) + rr * 8;
                        if (i < TT) {
                            const size_t m = (size_t)b * TT + i;
                            float2 uu = *(const float2*)(g_u + m * EE + e);
                            *(uint32_t*)(g_ww + m * EE + e) =
                                fpack2(uu.x * acc[mi][nb][rr * 2],
                                       uu.y * acc[mi][nb][rr * 2 + 1]);
                        }
                    }
                }
            }
        }
    }
}

/* ===================== K4: out GEMM (A 1-limb); grid (2, 1064) =========== */
__global__ __launch_bounds__(256, 2) void k_out_mma(
    const float* __restrict__ x, const float* __restrict__ res_scale,
    float* __restrict__ out)
{
    extern __shared__ char sm[];
    const int m0 = blockIdx.y * 128, by = blockIdx.x;
    float acc[4][4][4] = {};
    gemm_core_a1<16>(g_ww + (size_t)m0 * EE,
                     g_woh + (size_t)by * 128 * EE, g_wol + (size_t)by * 128 * EE,
                     EE, EE, sm, acc);

    const int tid = threadIdx.x, wid = tid >> 5, lane = tid & 31;
    const int wm = (wid >> 2) * 64, wn = (wid & 3) * 32;
    const int gid2 = lane >> 2, tig = lane & 3;
    #pragma unroll
    for (int mi = 0; mi < 4; mi++) {
        #pragma unroll
        for (int ni = 0; ni < 4; ni++) {
            const float* a = acc[mi][ni];
            const int col = by * 128 + wn + ni * 8 + tig * 2;
            const int mr = m0 + wm + mi * 16 + gid2;
            float2 rv = *(const float2*)(res_scale + col);
            float2 x0 = *(const float2*)(x + (size_t)mr * DD + col);
            float2 x1 = *(const float2*)(x + (size_t)(mr + 8) * DD + col);
            float2 o0 = {fmaf(x0.x, rv.x, a[0]), fmaf(x0.y, rv.y, a[1])};
            float2 o1 = {fmaf(x1.x, rv.x, a[2]), fmaf(x1.y, rv.y, a[3])};
            *(float2*)(out + (size_t)mr * DD + col)       = o0;
            *(float2*)(out + (size_t)(mr + 8) * DD + col) = o1;
        }
    }
}

/* ===================== launch ===================== */
extern "C" void kernel_launch(void* const* d_in, const int* in_sizes, int n_in,
                              void* d_out, int out_size)
{
    const float* x         = (const float*)d_in[0];
    const float* W_uv      = (const float*)d_in[1];
    const float* W_o       = (const float*)d_in[2];
    const float* gamma     = (const float*)d_in[3];
    const float* beta      = (const float*)d_in[4];
    const float* g         = (const float*)d_in[5];
    const float* res_scale = (const float*)d_in[6];
    float* out = (float*)d_out;

    const int gsm  = 2 * STAGEB;    /* 81920 */
    const int gsm3 = 2 * STAGEB3;   /* 61440 */
    cudaFuncSetAttribute(k_uv_mma,  cudaFuncAttributeMaxDynamicSharedMemorySize, gsm);
    cudaFuncSetAttribute(k_out_mma, cudaFuncAttributeMaxDynamicSharedMemorySize, gsm3);
    cudaFuncSetAttribute(k_fa,      cudaFuncAttributeMaxDynamicSharedMemorySize, FA_SMEM);

    k_norm_cvt<<<MTOT / 8, 256>>>(x, g);
    k_cvt_sel<<<(1152 * DD / 4 + 255) / 256, 256>>>(W_uv, 0, 1152 * DD / 4);
    k_cvt_sel<<<(DD * EE / 4 + 255) / 256, 256>>>(W_o, 1, DD * EE / 4);
    k_uv_mma<<<dim3(9, MTOT / 128), 256, gsm>>>(gamma, beta);
    k_fa<<<BB, 512, FA_SMEM>>>();
    k_out_mma<<<dim3(2, MTOT / 128), 256, gsm3>>>(x, res_scale, out);
}

// round 14
// speedup vs baseline: 3.1243x; 1.1151x over previous
#include <cuda_runtime.h>
#include <cuda_fp16.h>
#include <cstdint>
#include <math.h>

#define BB   1024
#define TT   133
#define DD   256
#define EE   512
#define SSZ  128
#define MTOT (BB*TT)          /* 136192 */
#define MP   160
#define NP   192
#define EPSV 1e-5f
#define INV_SQRT_S 0.08838834764831845f

/* -------- scratch (device globals, 16B-aligned). Pad regions stay BSS-zero. */
__device__ __align__(16) float  g_u[(size_t)MTOT * EE];
__device__ __align__(16) __half g_xh[(size_t)MTOT * DD];
__device__ __align__(16) __half g_xl[(size_t)MTOT * DD];
__device__ __align__(16) __half g_ww[(size_t)MTOT * EE];
__device__ __align__(16) __half g_wuvh[1152 * DD];
__device__ __align__(16) __half g_wuvl[1152 * DD];
__device__ __align__(16) __half g_woh[DD * EE];
__device__ __align__(16) __half g_wol[DD * EE];
__device__ __align__(16) __half g_qh[(size_t)BB * MP * SSZ];
__device__ __align__(16) __half g_ql[(size_t)BB * MP * SSZ];
__device__ __align__(16) __half g_kh[(size_t)BB * NP * SSZ];
__device__ __align__(16) __half g_kl[(size_t)BB * NP * SSZ];
__device__ __align__(16) __half g_vh[(size_t)BB * NP * EE];
__device__ __align__(16) __half g_vl[(size_t)BB * NP * EE];

/* ================= helpers ================= */
__device__ __forceinline__ uint32_t smem_u32(const void* p) {
    uint32_t a;
    asm("{ .reg .u64 t; cvta.to.shared.u64 t, %1; cvt.u32.u64 %0, t; }" : "=r"(a) : "l"(p));
    return a;
}
#define CPA16(dst, src) asm volatile("cp.async.cg.shared.global [%0], [%1], 16;" \
    :: "r"(dst), "l"(__cvta_generic_to_global(src)))
#define CPC()  asm volatile("cp.async.commit_group;")
#define CPW1() asm volatile("cp.async.wait_group 1;")
#define CPW0() asm volatile("cp.async.wait_group 0;")

__device__ __forceinline__ void ldsm4(uint32_t* r, uint32_t addr) {
    asm volatile("ldmatrix.sync.aligned.m8n8.x4.shared.b16 {%0,%1,%2,%3}, [%4];"
                 : "=r"(r[0]), "=r"(r[1]), "=r"(r[2]), "=r"(r[3]) : "r"(addr));
}
__device__ __forceinline__ void ldsm2(uint32_t* r, uint32_t addr) {
    asm volatile("ldmatrix.sync.aligned.m8n8.x2.shared.b16 {%0,%1}, [%2];"
                 : "=r"(r[0]), "=r"(r[1]) : "r"(addr));
}
__device__ __forceinline__ void ldsm2t(uint32_t* r, uint32_t addr) {
    asm volatile("ldmatrix.sync.aligned.m8n8.x2.trans.shared.b16 {%0,%1}, [%2];"
                 : "=r"(r[0]), "=r"(r[1]) : "r"(addr));
}
__device__ __forceinline__ void mma16816(float* d, const uint32_t* a,
                                         uint32_t b0, uint32_t b1) {
    asm volatile("mma.sync.aligned.m16n8k16.row.col.f32.f16.f16.f32 "
                 "{%0,%1,%2,%3}, {%4,%5,%6,%7}, {%8,%9}, {%0,%1,%2,%3};"
                 : "+f"(d[0]), "+f"(d[1]), "+f"(d[2]), "+f"(d[3])
                 : "r"(a[0]), "r"(a[1]), "r"(a[2]), "r"(a[3]), "r"(b0), "r"(b1));
}
__device__ __forceinline__ float silu(float v) { return v / (1.f + __expf(-v)); }

__device__ __forceinline__ uint32_t fsplit2(float a, float b, uint32_t& lo) {
    __half ha = __float2half(a), hb = __float2half(b);
    __half la = __float2half(a - __half2float(ha));
    __half lb = __float2half(b - __half2float(hb));
    __half2 hh = __halves2half2(ha, hb);
    __half2 ll = __halves2half2(la, lb);
    lo = reinterpret_cast<uint32_t&>(ll);
    return reinterpret_cast<uint32_t&>(hh);
}
__device__ __forceinline__ uint32_t fpack2(float a, float b) {
    __half2 h = __halves2half2(__float2half(a), __float2half(b));
    return reinterpret_cast<uint32_t&>(h);
}

/* ===================== BK=32 dense GEMM cores (dynamic smem) ============= */
#define ROWB   80
#define TILEB  10240
#define STAGEB 40960          /* 4 tiles: Ah Al Bh Bl */
#define STAGEB3 30720         /* 3 tiles: A Bh Bl     */

template<int NCH>
__device__ __forceinline__ void gemm_core32(
    const __half* gAh, const __half* gAl, const __half* gBh, const __half* gBl,
    int lda, int ldb, char* sm, float acc[4][4][4])
{
    const int tid = threadIdx.x, wid = tid >> 5, lane = tid & 31;
    const int wm = (wid >> 2) * 64, wn = (wid & 3) * 32;
    const int r = tid >> 1, qp = (tid & 1) * 2;
    const uint32_t s0 = smem_u32(sm);

    auto load = [&](int kc, int s) {
        const uint32_t da = s0 + s * STAGEB + r * ROWB + qp * 16;
        const int kofs = kc * 32 + qp * 8;
        const __half* pa = gAh + (size_t)r * lda + kofs;
        const __half* pl = gAl + (size_t)r * lda + kofs;
        const __half* pb = gBh + (size_t)r * ldb + kofs;
        const __half* pc = gBl + (size_t)r * ldb + kofs;
        CPA16(da,                pa); CPA16(da + 16,                pa + 8);
        CPA16(da + TILEB,        pl); CPA16(da + TILEB + 16,        pl + 8);
        CPA16(da + 2*TILEB,      pb); CPA16(da + 2*TILEB + 16,      pb + 8);
        CPA16(da + 3*TILEB,      pc); CPA16(da + 3*TILEB + 16,      pc + 8);
    };

    load(0, 0); CPC();

    #pragma unroll 1
    for (int c = 0; c < NCH; c++) {
        const int s = c & 1;
        if (c + 1 < NCH) { load(c + 1, 1 - s); CPC(); CPW1(); }
        else             { CPW0(); }
        __syncthreads();

        const uint32_t base = s0 + s * STAGEB;
        const uint32_t boff = base + 2 * TILEB;
        #pragma unroll
        for (int ks = 0; ks < 2; ks++) {
            uint32_t bh[8], bl[8];
            const int brow = wn + ((lane >> 4) & 1) * 8 + (lane & 7);
            const uint32_t bcolb = ks * 32 + ((lane >> 3) & 1) * 16;
            const uint32_t ba0 = boff + brow * ROWB + bcolb;
            const uint32_t ba1 = ba0 + 16 * ROWB;
            ldsm4(bh,     ba0);          ldsm4(bh + 4, ba1);
            ldsm4(bl,     ba0 + TILEB);  ldsm4(bl + 4, ba1 + TILEB);

            const int arow = wm + (lane & 15);
            const uint32_t acolb = ks * 32 + (lane >> 4) * 16;
            #pragma unroll
            for (int mi = 0; mi < 4; mi++) {
                uint32_t ah[4], al[4];
                const uint32_t aa = base + (arow + mi * 16) * ROWB + acolb;
                ldsm4(ah, aa); ldsm4(al, aa + TILEB);
                #pragma unroll
                for (int ni = 0; ni < 4; ni++)
                    mma16816(acc[mi][ni], ah, bh[2 * ni], bh[2 * ni + 1]);
                #pragma unroll
                for (int ni = 0; ni < 4; ni++)
                    mma16816(acc[mi][ni], ah, bl[2 * ni], bl[2 * ni + 1]);
                #pragma unroll
                for (int ni = 0; ni < 4; ni++)
                    mma16816(acc[mi][ni], al, bh[2 * ni], bh[2 * ni + 1]);
            }
        }
        __syncthreads();
    }
}

/* A single-limb variant: D = A(Bh+Bl); stage = 3 tiles. */
template<int NCH>
__device__ __forceinline__ void gemm_core_a1(
    const __half* gA, const __half* gBh, const __half* gBl,
    int lda, int ldb, char* sm, float acc[4][4][4])
{
    const int tid = threadIdx.x, wid = tid >> 5, lane = tid & 31;
    const int wm = (wid >> 2) * 64, wn = (wid & 3) * 32;
    const int r = tid >> 1, qp = (tid & 1) * 2;
    const uint32_t s0 = smem_u32(sm);

    auto load = [&](int kc, int s) {
        const uint32_t da = s0 + s * STAGEB3 + r * ROWB + qp * 16;
        const int kofs = kc * 32 + qp * 8;
        const __half* pa = gA  + (size_t)r * lda + kofs;
        const __half* pb = gBh + (size_t)r * ldb + kofs;
        const __half* pc = gBl + (size_t)r * ldb + kofs;
        CPA16(da,                pa); CPA16(da + 16,                pa + 8);
        CPA16(da + TILEB,        pb); CPA16(da + TILEB + 16,        pb + 8);
        CPA16(da + 2*TILEB,      pc); CPA16(da + 2*TILEB + 16,      pc + 8);
    };

    load(0, 0); CPC();

    #pragma unroll 1
    for (int c = 0; c < NCH; c++) {
        const int s = c & 1;
        if (c + 1 < NCH) { load(c + 1, 1 - s); CPC(); CPW1(); }
        else             { CPW0(); }
        __syncthreads();

        const uint32_t base = s0 + s * STAGEB3;
        const uint32_t boff = base + TILEB;
        #pragma unroll
        for (int ks = 0; ks < 2; ks++) {
            uint32_t bh[8], bl[8];
            const int brow = wn + ((lane >> 4) & 1) * 8 + (lane & 7);
            const uint32_t bcolb = ks * 32 + ((lane >> 3) & 1) * 16;
            const uint32_t ba0 = boff + brow * ROWB + bcolb;
            const uint32_t ba1 = ba0 + 16 * ROWB;
            ldsm4(bh,     ba0);          ldsm4(bh + 4, ba1);
            ldsm4(bl,     ba0 + TILEB);  ldsm4(bl + 4, ba1 + TILEB);

            const int arow = wm + (lane & 15);
            const uint32_t acolb = ks * 32 + (lane >> 4) * 16;
            #pragma unroll
            for (int mi = 0; mi < 4; mi++) {
                uint32_t ah[4];
                const uint32_t aa = base + (arow + mi * 16) * ROWB + acolb;
                ldsm4(ah, aa);
                #pragma unroll
                for (int ni = 0; ni < 4; ni++)
                    mma16816(acc[mi][ni], ah, bh[2 * ni], bh[2 * ni + 1]);
                #pragma unroll
                for (int ni = 0; ni < 4; ni++)
                    mma16816(acc[mi][ni], ah, bl[2 * ni], bl[2 * ni + 1]);
            }
        }
        __syncthreads();
    }
}

/* ===================== K0: fused norm + fp16 split of xn ===================== */
__global__ __launch_bounds__(256) void k_norm_cvt(
    const float* __restrict__ x, const float* __restrict__ g)
{
    const int token = blockIdx.x * 8 + (threadIdx.x >> 5);
    const int lane  = threadIdx.x & 31;
    const float4* xp = (const float4*)(x + (size_t)token * DD);
    float4 v0 = xp[lane], v1 = xp[lane + 32];
    float sum = v0.x * v0.x + v0.y * v0.y + v0.z * v0.z + v0.w * v0.w
              + v1.x * v1.x + v1.y * v1.y + v1.z * v1.z + v1.w * v1.w;
    #pragma unroll
    for (int o = 16; o; o >>= 1) sum += __shfl_xor_sync(0xFFFFFFFFu, sum, o);
    float norm = sqrtf(sum * (1.f / (float)DD));
    float s = g[0] / fmaxf(norm, EPSV);

    uint2 h0, l0, h1, l1;
    h0.x = fsplit2(v0.x * s, v0.y * s, l0.x);
    h0.y = fsplit2(v0.z * s, v0.w * s, l0.y);
    h1.x = fsplit2(v1.x * s, v1.y * s, l1.x);
    h1.y = fsplit2(v1.z * s, v1.w * s, l1.y);
    const size_t base = (size_t)token * DD + lane * 4;
    *(uint2*)(g_xh + base)       = h0;
    *(uint2*)(g_xl + base)       = l0;
    *(uint2*)(g_xh + base + 128) = h1;
    *(uint2*)(g_xl + base + 128) = l1;
}

/* ===================== weight fp16 split (device-side dest select) ======== */
__global__ __launch_bounds__(256) void k_cvt_sel(
    const float* __restrict__ src, int which, int n4)
{
    __half* hi; __half* lo;
    if (which == 0) { hi = g_wuvh; lo = g_wuvl; }
    else            { hi = g_woh;  lo = g_wol;  }
    const int i = blockIdx.x * 256 + threadIdx.x;
    if (i >= n4) return;
    float4 v = ((const float4*)src)[i];
    uint2 h, l;
    h.x = fsplit2(v.x, v.y, l.x);
    h.y = fsplit2(v.z, v.w, l.y);
    *(uint2*)(hi + (size_t)i * 4) = h;
    *(uint2*)(lo + (size_t)i * 4) = l;
}

/* ===================== K1a: u/v GEMM, 2-term; grid (8, 1064) ============== */
__global__ __launch_bounds__(256, 2) void k_uv2_mma()
{
    extern __shared__ char sm[];
    const int m0 = blockIdx.y * 128, by = blockIdx.x;     /* by in 0..7 */
    float acc[4][4][4] = {};
    gemm_core_a1<8>(g_xh + (size_t)m0 * DD,
                    g_wuvh + (size_t)by * 128 * DD, g_wuvl + (size_t)by * 128 * DD,
                    DD, DD, sm, acc);

    const int tid = threadIdx.x, wid = tid >> 5, lane = tid & 31;
    const int wm = (wid >> 2) * 64, wn = (wid & 3) * 32;
    const int gid2 = lane >> 2, tig = lane & 3;
    #pragma unroll
    for (int mi = 0; mi < 4; mi++) {
        #pragma unroll
        for (int ni = 0; ni < 4; ni++) {
            const float* a = acc[mi][ni];
            const int nl = wn + ni * 8 + tig * 2;
            #pragma unroll
            for (int rr = 0; rr < 2; rr++) {
                const int mr = m0 + wm + mi * 16 + gid2 + rr * 8;
                const float sv0 = silu(a[rr * 2]), sv1 = silu(a[rr * 2 + 1]);
                if (by < 4) {
                    float2 o = {sv0, sv1};
                    *(float2*)(g_u + (size_t)mr * EE + by * 128 + nl) = o;
                } else {
                    const int b = mr / TT, t = mr - b * TT;
                    const int col = (by - 4) * 128 + nl;
                    uint32_t lo, hi = fsplit2(sv0, sv1, lo);
                    const size_t vofs = ((size_t)b * NP + t) * EE + col;
                    *(uint32_t*)(g_vh + vofs) = hi;
                    *(uint32_t*)(g_vl + vofs) = lo;
                }
            }
        }
    }
}

/* ===================== K1b: q/k GEMM, 3-term; grid (1064) ================= */
__global__ __launch_bounds__(256, 2) void k_uv3_mma(
    const float* __restrict__ gamma, const float* __restrict__ beta)
{
    extern __shared__ char sm[];
    const int m0 = blockIdx.x * 128;
    float acc[4][4][4] = {};
    gemm_core32<8>(g_xh + (size_t)m0 * DD, g_xl + (size_t)m0 * DD,
                   g_wuvh + (size_t)8 * 128 * DD, g_wuvl + (size_t)8 * 128 * DD,
                   DD, DD, sm, acc);

    const int tid = threadIdx.x, wid = tid >> 5, lane = tid & 31;
    const int wm = (wid >> 2) * 64, wn = (wid & 3) * 32;
    const int gid2 = lane >> 2, tig = lane & 3;
    #pragma unroll
    for (int mi = 0; mi < 4; mi++) {
        #pragma unroll
        for (int ni = 0; ni < 4; ni++) {
            const float* a = acc[mi][ni];
            const int nl = wn + ni * 8 + tig * 2;
            #pragma unroll
            for (int rr = 0; rr < 2; rr++) {
                const int mr = m0 + wm + mi * 16 + gid2 + rr * 8;
                const float sv0 = silu(a[rr * 2]), sv1 = silu(a[rr * 2 + 1]);
                const int b = mr / TT, t = mr - b * TT;
                const float q0 = fmaf(sv0, gamma[nl],     beta[nl]);
                const float q1 = fmaf(sv1, gamma[nl + 1], beta[nl + 1]);
                const float k0 = fmaf(sv0, gamma[SSZ + nl],     beta[SSZ + nl]);
                const float k1 = fmaf(sv1, gamma[SSZ + nl + 1], beta[SSZ + nl + 1]);
                uint32_t lo, hi;
                hi = fsplit2(q0, q1, lo);
                const size_t qofs = ((size_t)b * MP + t) * SSZ + nl;
                *(uint32_t*)(g_qh + qofs) = hi;
                *(uint32_t*)(g_ql + qofs) = lo;
                hi = fsplit2(k0, k1, lo);
                const size_t kofs = ((size_t)b * NP + t) * SSZ + nl;
                *(uint32_t*)(g_kh + kofs) = hi;
                *(uint32_t*)(g_kl + kofs) = lo;
            }
        }
    }
}

/* ===================== K2+K3 fused: per-batch attention ===================== */
#define SC_QT   (MP * 32)
#define SC_KT   (NP * 32)
#define SC_STG  (2*SC_QT + 2*SC_KT)
#define FA_PH   (2 * SC_STG)
#define FA_PROW 400
#define FA_PSZ  (MP * FA_PROW)
#define FA_VROW 528
#define FA_VT   (16 * FA_VROW)
#define FA_VSTG (2 * FA_VT)
#define FA_SMEM (FA_PH + FA_PSZ)        /* 109056 */

__global__ __launch_bounds__(512, 1) void k_fa()
{
    extern __shared__ char fsm[];
    const uint32_t sb = smem_u32(fsm);
    const uint32_t P0 = sb + FA_PH;
    const int b = blockIdx.x;
    const int tid = threadIdx.x, wid = tid >> 5, lane = tid & 31;

    /* ------------- phase 1: scores ------------- */
    {
        const int wm = (wid >> 3) * 80, wn = (wid & 7) * 24;

        auto load = [&](int kc, int s) {
            const uint32_t st = sb + s * SC_STG;
            if (tid < 2 * MP) {
                const int row = tid >> 1, off = tid & 1;
                const size_t gofs = ((size_t)b * MP + row) * SSZ + kc * 16 + off * 8;
                CPA16(st + row * 32 + off * 16,         g_qh + gofs);
                CPA16(st + SC_QT + row * 32 + off * 16, g_ql + gofs);
            }
            if (tid < 2 * NP) {
                const int row = tid >> 1, off = tid & 1;
                const size_t gofs = ((size_t)b * NP + row) * SSZ + kc * 16 + off * 8;
                CPA16(st + 2*SC_QT + row * 32 + off * 16,         g_kh + gofs);
                CPA16(st + 2*SC_QT + SC_KT + row * 32 + off * 16, g_kl + gofs);
            }
        };

        float acc[5][3][4] = {};
        load(0, 0); CPC();

        #pragma unroll 1
        for (int c = 0; c < 8; c++) {
            const int s = c & 1;
            if (c + 1 < 8) { load(c + 1, 1 - s); CPC(); CPW1(); }
            else           { CPW0(); }
            __syncthreads();

            const uint32_t qb = sb + s * SC_STG;
            const uint32_t kb = qb + 2 * SC_QT, klb = kb + SC_KT;

            uint32_t bh[6], bl[6];
            {
                const int br = wn + ((lane >> 4) & 1) * 8 + (lane & 7);
                const uint32_t bc = ((lane >> 3) & 1) * 16;
                ldsm4(bh, kb  + br * 32 + bc);
                ldsm4(bl, klb + br * 32 + bc);
                const int br2 = wn + 16 + (lane & 7);
                ldsm2(bh + 4, kb  + br2 * 32 + bc);
                ldsm2(bl + 4, klb + br2 * 32 + bc);
            }
            const int arow = wm + (lane & 15);
            const uint32_t acolb = (lane >> 4) * 16;
            #pragma unroll
            for (int mi = 0; mi < 5; mi++) {
                uint32_t ah[4], al[4];
                const uint32_t aa = qb + (arow + mi * 16) * 32 + acolb;
                ldsm4(ah, aa); ldsm4(al, aa + SC_QT);
                #pragma unroll
                for (int nb = 0; nb < 3; nb++)
                    mma16816(acc[mi][nb], ah, bh[2 * nb], bh[2 * nb + 1]);
                #pragma unroll
                for (int nb = 0; nb < 3; nb++)
                    mma16816(acc[mi][nb], ah, bl[2 * nb], bl[2 * nb + 1]);
                #pragma unroll
                for (int nb = 0; nb < 3; nb++)
                    mma16816(acc[mi][nb], al, bh[2 * nb], bh[2 * nb + 1]);
            }
            __syncthreads();
        }

        #pragma unroll
        for (int mi = 0; mi < 5; mi++) {
            #pragma unroll
            for (int nb = 0; nb < 3; nb++) {
                const int j = wn + nb * 8 + (lane & 3) * 2;
                #pragma unroll
                for (int rr = 0; rr < 2; rr++) {
                    const int i = wm + mi * 16 + (lane >> 2) + rr * 8;
                    float s0 = fmaxf(acc[mi][nb][rr * 2]     * INV_SQRT_S, 0.f);
                    float s1 = fmaxf(acc[mi][nb][rr * 2 + 1] * INV_SQRT_S, 0.f);
                    uint32_t hi = fpack2(s0 * s0, s1 * s1);
                    asm volatile("st.shared.b32 [%0], %1;"
                                 :: "r"(P0 + i * FA_PROW + j * 2), "r"(hi) : "memory");
                }
            }
        }
    }
    __syncthreads();

    /* ------------- phase 2: w = u * (P @ v), N=256 per pass ------------- */
    {
        const int wm = (wid >> 3) * 80, wn = (wid & 7) * 32;

        #pragma unroll 1
        for (int ep = 0; ep < 2; ep++) {
            const int e0 = ep * 256;

            auto loadv = [&](int kc, int s) {
                const uint32_t st = sb + s * FA_VSTG;
                const int row = tid >> 5, ch = tid & 31;
                const size_t gofs = ((size_t)b * NP + kc * 16 + row) * EE + e0 + ch * 8;
                CPA16(st + row * FA_VROW + ch * 16,         g_vh + gofs);
                CPA16(st + FA_VT + row * FA_VROW + ch * 16, g_vl + gofs);
            };

            float acc[5][4][4] = {};
            loadv(0, 0); CPC();

            #pragma unroll 1
            for (int c = 0; c < 12; c++) {
                const int s = c & 1;
                if (c + 1 < 12) { loadv(c + 1, 1 - s); CPC(); CPW1(); }
                else            { CPW0(); }
                __syncthreads();

                const uint32_t vbh = sb + s * FA_VSTG, vbl = vbh + FA_VT;
                uint32_t bh[4][2], bl[4][2];
                const int l16 = lane & 15;
                #pragma unroll
                for (int nb = 0; nb < 4; nb++) {
                    const uint32_t va = l16 * FA_VROW + (wn + nb * 8) * 2;
                    ldsm2t(bh[nb], vbh + va);
                    ldsm2t(bl[nb], vbl + va);
                }
                const int arow = wm + (lane & 15);
                const uint32_t ac = (c * 16 + (lane >> 4) * 8) * 2;
                #pragma unroll
                for (int mi = 0; mi < 5; mi++) {
                    uint32_t ah[4];
                    ldsm4(ah, P0 + (arow + mi * 16) * FA_PROW + ac);
                    #pragma unroll
                    for (int nb = 0; nb < 4; nb++)
                        mma16816(acc[mi][nb], ah, bh[nb][0], bh[nb][1]);
                    #pragma unroll
                    for (int nb = 0; nb < 4; nb++)
                        mma16816(acc[mi][nb], ah, bl[nb][0], bl[nb][1]);
                }
                __syncthreads();
            }

            #pragma unroll
            for (int mi = 0; mi < 5; mi++) {
                #pragma unroll
                for (int nb = 0; nb < 4; nb++) {
                    const int e = e0 + wn + nb * 8 + (lane & 3) * 2;
                    #pragma unroll
                    for (int rr = 0; rr < 2; rr++) {
                        const int i = wm + mi * 16 + (lane >> 2) + rr * 8;
                        if (i < TT) {
                            const size_t m = (size_t)b * TT + i;
                            float2 uu = *(const float2*)(g_u + m * EE + e);
                            *(uint32_t*)(g_ww + m * EE + e) =
                                fpack2(uu.x * acc[mi][nb][rr * 2],
                                       uu.y * acc[mi][nb][rr * 2 + 1]);
                        }
                    }
                }
            }
        }
    }
}

/* ===================== K4: out GEMM (A 1-limb); grid (2, 1064) =========== */
__global__ __launch_bounds__(256, 2) void k_out_mma(
    const float* __restrict__ x, const float* __restrict__ res_scale,
    float* __restrict__ out)
{
    extern __shared__ char sm[];
    const int m0 = blockIdx.y * 128, by = blockIdx.x;
    float acc[4][4][4] = {};
    gemm_core_a1<16>(g_ww + (size_t)m0 * EE,
                     g_woh + (size_t)by * 128 * EE, g_wol + (size_t)by * 128 * EE,
                     EE, EE, sm, acc);

    const int tid = threadIdx.x, wid = tid >> 5, lane = tid & 31;
    const int wm = (wid >> 2) * 64, wn = (wid & 3) * 32;
    const int gid2 = lane >> 2, tig = lane & 3;
    #pragma unroll
    for (int mi = 0; mi < 4; mi++) {
        #pragma unroll
        for (int ni = 0; ni < 4; ni++) {
            const float* a = acc[mi][ni];
            const int col = by * 128 + wn + ni * 8 + tig * 2;
            const int mr = m0 + wm + mi * 16 + gid2;
            float2 rv = *(const float2*)(res_scale + col);
            float2 x0 = *(const float2*)(x + (size_t)mr * DD + col);
            float2 x1 = *(const float2*)(x + (size_t)(mr + 8) * DD + col);
            float2 o0 = {fmaf(x0.x, rv.x, a[0]), fmaf(x0.y, rv.y, a[1])};
            float2 o1 = {fmaf(x1.x, rv.x, a[2]), fmaf(x1.y, rv.y, a[3])};
            *(float2*)(out + (size_t)mr * DD + col)       = o0;
            *(float2*)(out + (size_t)(mr + 8) * DD + col) = o1;
        }
    }
}

/* ===================== launch ===================== */
extern "C" void kernel_launch(void* const* d_in, const int* in_sizes, int n_in,
                              void* d_out, int out_size)
{
    const float* x         = (const float*)d_in[0];
    const float* W_uv      = (const float*)d_in[1];
    const float* W_o       = (const float*)d_in[2];
    const float* gamma     = (const float*)d_in[3];
    const float* beta      = (const float*)d_in[4];
    const float* g         = (const float*)d_in[5];
    const float* res_scale = (const float*)d_in[6];
    float* out = (float*)d_out;

    const int gsm  = 2 * STAGEB;    /* 81920 */
    const int gsm3 = 2 * STAGEB3;   /* 61440 */
    cudaFuncSetAttribute(k_uv2_mma, cudaFuncAttributeMaxDynamicSharedMemorySize, gsm3);
    cudaFuncSetAttribute(k_uv3_mma, cudaFuncAttributeMaxDynamicSharedMemorySize, gsm);
    cudaFuncSetAttribute(k_out_mma, cudaFuncAttributeMaxDynamicSharedMemorySize, gsm3);
    cudaFuncSetAttribute(k_fa,      cudaFuncAttributeMaxDynamicSharedMemorySize, FA_SMEM);

    k_norm_cvt<<<MTOT / 8, 256>>>(x, g);
    k_cvt_sel<<<(1152 * DD / 4 + 255) / 256, 256>>>(W_uv, 0, 1152 * DD / 4);
    k_cvt_sel<<<(DD * EE / 4 + 255) / 256, 256>>>(W_o, 1, DD * EE / 4);
    k_uv2_mma<<<dim3(8, MTOT / 128), 256, gsm3>>>();
    k_uv3_mma<<<MTOT / 128, 256, gsm>>>(gamma, beta);
    k_fa<<<BB, 512, FA_SMEM>>>();
    k_out_mma<<<dim3(2, MTOT / 128), 256, gsm3>>>(x, res_scale, out);
}

// round 15
// speedup vs baseline: 3.5193x; 1.1264x over previous
#include <cuda_runtime.h>
#include <cuda_fp16.h>
#include <cstdint>
#include <math.h>

#define BB   1024
#define TT   133
#define DD   256
#define EE   512
#define SSZ  128
#define MTOT (BB*TT)          /* 136192 */
#define MP   160
#define NP   192
#define EPSV 1e-5f
#define INV_SQRT_S 0.08838834764831845f

/* -------- scratch (device globals, 16B-aligned). Pad regions stay BSS-zero. */
__device__ __align__(16) float  g_u[(size_t)MTOT * EE];
__device__ __align__(16) __half g_xh[(size_t)MTOT * DD];
__device__ __align__(16) __half g_xl[(size_t)MTOT * DD];
__device__ __align__(16) __half g_ww[(size_t)MTOT * EE];
__device__ __align__(16) __half g_wuvh[1152 * DD];
__device__ __align__(16) __half g_wuvl[1152 * DD];
__device__ __align__(16) __half g_wo[DD * EE];              /* single fp16 */
__device__ __align__(16) __half g_qh[(size_t)BB * MP * SSZ];
__device__ __align__(16) __half g_ql[(size_t)BB * MP * SSZ];
__device__ __align__(16) __half g_kh[(size_t)BB * NP * SSZ];
__device__ __align__(16) __half g_kl[(size_t)BB * NP * SSZ];
__device__ __align__(16) __half g_vh[(size_t)BB * NP * EE]; /* single fp16 */

/* ================= helpers ================= */
__device__ __forceinline__ uint32_t smem_u32(const void* p) {
    uint32_t a;
    asm("{ .reg .u64 t; cvta.to.shared.u64 t, %1; cvt.u32.u64 %0, t; }" : "=r"(a) : "l"(p));
    return a;
}
#define CPA16(dst, src) asm volatile("cp.async.cg.shared.global [%0], [%1], 16;" \
    :: "r"(dst), "l"(__cvta_generic_to_global(src)))
#define CPC()  asm volatile("cp.async.commit_group;")
#define CPW1() asm volatile("cp.async.wait_group 1;")
#define CPW0() asm volatile("cp.async.wait_group 0;")

__device__ __forceinline__ void ldsm4(uint32_t* r, uint32_t addr) {
    asm volatile("ldmatrix.sync.aligned.m8n8.x4.shared.b16 {%0,%1,%2,%3}, [%4];"
                 : "=r"(r[0]), "=r"(r[1]), "=r"(r[2]), "=r"(r[3]) : "r"(addr));
}
__device__ __forceinline__ void ldsm2(uint32_t* r, uint32_t addr) {
    asm volatile("ldmatrix.sync.aligned.m8n8.x2.shared.b16 {%0,%1}, [%2];"
                 : "=r"(r[0]), "=r"(r[1]) : "r"(addr));
}
__device__ __forceinline__ void ldsm2t(uint32_t* r, uint32_t addr) {
    asm volatile("ldmatrix.sync.aligned.m8n8.x2.trans.shared.b16 {%0,%1}, [%2];"
                 : "=r"(r[0]), "=r"(r[1]) : "r"(addr));
}
__device__ __forceinline__ void mma16816(float* d, const uint32_t* a,
                                         uint32_t b0, uint32_t b1) {
    asm volatile("mma.sync.aligned.m16n8k16.row.col.f32.f16.f16.f32 "
                 "{%0,%1,%2,%3}, {%4,%5,%6,%7}, {%8,%9}, {%0,%1,%2,%3};"
                 : "+f"(d[0]), "+f"(d[1]), "+f"(d[2]), "+f"(d[3])
                 : "r"(a[0]), "r"(a[1]), "r"(a[2]), "r"(a[3]), "r"(b0), "r"(b1));
}
__device__ __forceinline__ float silu(float v) { return v / (1.f + __expf(-v)); }

__device__ __forceinline__ uint32_t fsplit2(float a, float b, uint32_t& lo) {
    __half ha = __float2half(a), hb = __float2half(b);
    __half la = __float2half(a - __half2float(ha));
    __half lb = __float2half(b - __half2float(hb));
    __half2 hh = __halves2half2(ha, hb);
    __half2 ll = __halves2half2(la, lb);
    lo = reinterpret_cast<uint32_t&>(ll);
    return reinterpret_cast<uint32_t&>(hh);
}
__device__ __forceinline__ uint32_t fpack2(float a, float b) {
    __half2 h = __halves2half2(__float2half(a), __float2half(b));
    return reinterpret_cast<uint32_t&>(h);
}

/* ===================== BK=32 dense GEMM cores (dynamic smem) ============= */
#define ROWB   80
#define TILEB  10240
#define STAGEB  40960         /* 4 tiles: Ah Al Bh Bl (k_uv3) */
#define STAGEB3 30720         /* 3 tiles: A Bh Bl (k_uv2)     */
#define STAGEB2 20480         /* 2 tiles: A B     (k_out)     */

template<int NCH>
__device__ __forceinline__ void gemm_core32(
    const __half* gAh, const __half* gAl, const __half* gBh, const __half* gBl,
    int lda, int ldb, char* sm, float acc[4][4][4])
{
    const int tid = threadIdx.x, wid = tid >> 5, lane = tid & 31;
    const int wm = (wid >> 2) * 64, wn = (wid & 3) * 32;
    const int r = tid >> 1, qp = (tid & 1) * 2;
    const uint32_t s0 = smem_u32(sm);

    auto load = [&](int kc, int s) {
        const uint32_t da = s0 + s * STAGEB + r * ROWB + qp * 16;
        const int kofs = kc * 32 + qp * 8;
        const __half* pa = gAh + (size_t)r * lda + kofs;
        const __half* pl = gAl + (size_t)r * lda + kofs;
        const __half* pb = gBh + (size_t)r * ldb + kofs;
        const __half* pc = gBl + (size_t)r * ldb + kofs;
        CPA16(da,                pa); CPA16(da + 16,                pa + 8);
        CPA16(da + TILEB,        pl); CPA16(da + TILEB + 16,        pl + 8);
        CPA16(da + 2*TILEB,      pb); CPA16(da + 2*TILEB + 16,      pb + 8);
        CPA16(da + 3*TILEB,      pc); CPA16(da + 3*TILEB + 16,      pc + 8);
    };

    load(0, 0); CPC();

    #pragma unroll 1
    for (int c = 0; c < NCH; c++) {
        const int s = c & 1;
        if (c + 1 < NCH) { load(c + 1, 1 - s); CPC(); CPW1(); }
        else             { CPW0(); }
        __syncthreads();

        const uint32_t base = s0 + s * STAGEB;
        const uint32_t boff = base + 2 * TILEB;
        #pragma unroll
        for (int ks = 0; ks < 2; ks++) {
            uint32_t bh[8], bl[8];
            const int brow = wn + ((lane >> 4) & 1) * 8 + (lane & 7);
            const uint32_t bcolb = ks * 32 + ((lane >> 3) & 1) * 16;
            const uint32_t ba0 = boff + brow * ROWB + bcolb;
            const uint32_t ba1 = ba0 + 16 * ROWB;
            ldsm4(bh,     ba0);          ldsm4(bh + 4, ba1);
            ldsm4(bl,     ba0 + TILEB);  ldsm4(bl + 4, ba1 + TILEB);

            const int arow = wm + (lane & 15);
            const uint32_t acolb = ks * 32 + (lane >> 4) * 16;
            #pragma unroll
            for (int mi = 0; mi < 4; mi++) {
                uint32_t ah[4], al[4];
                const uint32_t aa = base + (arow + mi * 16) * ROWB + acolb;
                ldsm4(ah, aa); ldsm4(al, aa + TILEB);
                #pragma unroll
                for (int ni = 0; ni < 4; ni++)
                    mma16816(acc[mi][ni], ah, bh[2 * ni], bh[2 * ni + 1]);
                #pragma unroll
                for (int ni = 0; ni < 4; ni++)
                    mma16816(acc[mi][ni], ah, bl[2 * ni], bl[2 * ni + 1]);
                #pragma unroll
                for (int ni = 0; ni < 4; ni++)
                    mma16816(acc[mi][ni], al, bh[2 * ni], bh[2 * ni + 1]);
            }
        }
        __syncthreads();
    }
}

/* A 1-limb, B 2-limb: D = A(Bh+Bl); stage = 3 tiles. */
template<int NCH>
__device__ __forceinline__ void gemm_core_a1(
    const __half* gA, const __half* gBh, const __half* gBl,
    int lda, int ldb, char* sm, float acc[4][4][4])
{
    const int tid = threadIdx.x, wid = tid >> 5, lane = tid & 31;
    const int wm = (wid >> 2) * 64, wn = (wid & 3) * 32;
    const int r = tid >> 1, qp = (tid & 1) * 2;
    const uint32_t s0 = smem_u32(sm);

    auto load = [&](int kc, int s) {
        const uint32_t da = s0 + s * STAGEB3 + r * ROWB + qp * 16;
        const int kofs = kc * 32 + qp * 8;
        const __half* pa = gA  + (size_t)r * lda + kofs;
        const __half* pb = gBh + (size_t)r * ldb + kofs;
        const __half* pc = gBl + (size_t)r * ldb + kofs;
        CPA16(da,                pa); CPA16(da + 16,                pa + 8);
        CPA16(da + TILEB,        pb); CPA16(da + TILEB + 16,        pb + 8);
        CPA16(da + 2*TILEB,      pc); CPA16(da + 2*TILEB + 16,      pc + 8);
    };

    load(0, 0); CPC();

    #pragma unroll 1
    for (int c = 0; c < NCH; c++) {
        const int s = c & 1;
        if (c + 1 < NCH) { load(c + 1, 1 - s); CPC(); CPW1(); }
        else             { CPW0(); }
        __syncthreads();

        const uint32_t base = s0 + s * STAGEB3;
        const uint32_t boff = base + TILEB;
        #pragma unroll
        for (int ks = 0; ks < 2; ks++) {
            uint32_t bh[8], bl[8];
            const int brow = wn + ((lane >> 4) & 1) * 8 + (lane & 7);
            const uint32_t bcolb = ks * 32 + ((lane >> 3) & 1) * 16;
            const uint32_t ba0 = boff + brow * ROWB + bcolb;
            const uint32_t ba1 = ba0 + 16 * ROWB;
            ldsm4(bh,     ba0);          ldsm4(bh + 4, ba1);
            ldsm4(bl,     ba0 + TILEB);  ldsm4(bl + 4, ba1 + TILEB);

            const int arow = wm + (lane & 15);
            const uint32_t acolb = ks * 32 + (lane >> 4) * 16;
            #pragma unroll
            for (int mi = 0; mi < 4; mi++) {
                uint32_t ah[4];
                const uint32_t aa = base + (arow + mi * 16) * ROWB + acolb;
                ldsm4(ah, aa);
                #pragma unroll
                for (int ni = 0; ni < 4; ni++)
                    mma16816(acc[mi][ni], ah, bh[2 * ni], bh[2 * ni + 1]);
                #pragma unroll
                for (int ni = 0; ni < 4; ni++)
                    mma16816(acc[mi][ni], ah, bl[2 * ni], bl[2 * ni + 1]);
            }
        }
        __syncthreads();
    }
}

/* Pure fp16: D = A B; stage = 2 tiles. */
template<int NCH>
__device__ __forceinline__ void gemm_core_ff(
    const __half* gA, const __half* gB,
    int lda, int ldb, char* sm, float acc[4][4][4])
{
    const int tid = threadIdx.x, wid = tid >> 5, lane = tid & 31;
    const int wm = (wid >> 2) * 64, wn = (wid & 3) * 32;
    const int r = tid >> 1, qp = (tid & 1) * 2;
    const uint32_t s0 = smem_u32(sm);

    auto load = [&](int kc, int s) {
        const uint32_t da = s0 + s * STAGEB2 + r * ROWB + qp * 16;
        const int kofs = kc * 32 + qp * 8;
        const __half* pa = gA + (size_t)r * lda + kofs;
        const __half* pb = gB + (size_t)r * ldb + kofs;
        CPA16(da,            pa); CPA16(da + 16,            pa + 8);
        CPA16(da + TILEB,    pb); CPA16(da + TILEB + 16,    pb + 8);
    };

    load(0, 0); CPC();

    #pragma unroll 1
    for (int c = 0; c < NCH; c++) {
        const int s = c & 1;
        if (c + 1 < NCH) { load(c + 1, 1 - s); CPC(); CPW1(); }
        else             { CPW0(); }
        __syncthreads();

        const uint32_t base = s0 + s * STAGEB2;
        const uint32_t boff = base + TILEB;
        #pragma unroll
        for (int ks = 0; ks < 2; ks++) {
            uint32_t bh[8];
            const int brow = wn + ((lane >> 4) & 1) * 8 + (lane & 7);
            const uint32_t bcolb = ks * 32 + ((lane >> 3) & 1) * 16;
            const uint32_t ba0 = boff + brow * ROWB + bcolb;
            ldsm4(bh, ba0); ldsm4(bh + 4, ba0 + 16 * ROWB);

            const int arow = wm + (lane & 15);
            const uint32_t acolb = ks * 32 + (lane >> 4) * 16;
            #pragma unroll
            for (int mi = 0; mi < 4; mi++) {
                uint32_t ah[4];
                ldsm4(ah, base + (arow + mi * 16) * ROWB + acolb);
                #pragma unroll
                for (int ni = 0; ni < 4; ni++)
                    mma16816(acc[mi][ni], ah, bh[2 * ni], bh[2 * ni + 1]);
            }
        }
        __syncthreads();
    }
}

/* ===================== K0: fused norm + fp16 split of xn ===================== */
__global__ __launch_bounds__(256) void k_norm_cvt(
    const float* __restrict__ x, const float* __restrict__ g)
{
    const int token = blockIdx.x * 8 + (threadIdx.x >> 5);
    const int lane  = threadIdx.x & 31;
    const float4* xp = (const float4*)(x + (size_t)token * DD);
    float4 v0 = xp[lane], v1 = xp[lane + 32];
    float sum = v0.x * v0.x + v0.y * v0.y + v0.z * v0.z + v0.w * v0.w
              + v1.x * v1.x + v1.y * v1.y + v1.z * v1.z + v1.w * v1.w;
    #pragma unroll
    for (int o = 16; o; o >>= 1) sum += __shfl_xor_sync(0xFFFFFFFFu, sum, o);
    float norm = sqrtf(sum * (1.f / (float)DD));
    float s = g[0] / fmaxf(norm, EPSV);

    uint2 h0, l0, h1, l1;
    h0.x = fsplit2(v0.x * s, v0.y * s, l0.x);
    h0.y = fsplit2(v0.z * s, v0.w * s, l0.y);
    h1.x = fsplit2(v1.x * s, v1.y * s, l1.x);
    h1.y = fsplit2(v1.z * s, v1.w * s, l1.y);
    const size_t base = (size_t)token * DD + lane * 4;
    *(uint2*)(g_xh + base)       = h0;
    *(uint2*)(g_xl + base)       = l0;
    *(uint2*)(g_xh + base + 128) = h1;
    *(uint2*)(g_xl + base + 128) = l1;
}

/* ===================== weight conversions (device-side dest) ======== */
__global__ __launch_bounds__(256) void k_cvt_wuv(
    const float* __restrict__ src, int n4)
{
    const int i = blockIdx.x * 256 + threadIdx.x;
    if (i >= n4) return;
    float4 v = ((const float4*)src)[i];
    uint2 h, l;
    h.x = fsplit2(v.x, v.y, l.x);
    h.y = fsplit2(v.z, v.w, l.y);
    *(uint2*)(g_wuvh + (size_t)i * 4) = h;
    *(uint2*)(g_wuvl + (size_t)i * 4) = l;
}
__global__ __launch_bounds__(256) void k_cvt_wo(
    const float* __restrict__ src, int n4)
{
    const int i = blockIdx.x * 256 + threadIdx.x;
    if (i >= n4) return;
    float4 v = ((const float4*)src)[i];
    uint2 h;
    h.x = fpack2(v.x, v.y);
    h.y = fpack2(v.z, v.w);
    *(uint2*)(g_wo + (size_t)i * 4) = h;
}

/* ===================== K1a: u/v GEMM, 2-term; grid (8, 1064) ============== */
__global__ __launch_bounds__(256, 2) void k_uv2_mma()
{
    extern __shared__ char sm[];
    const int m0 = blockIdx.y * 128, by = blockIdx.x;
    float acc[4][4][4] = {};
    gemm_core_a1<8>(g_xh + (size_t)m0 * DD,
                    g_wuvh + (size_t)by * 128 * DD, g_wuvl + (size_t)by * 128 * DD,
                    DD, DD, sm, acc);

    const int tid = threadIdx.x, wid = tid >> 5, lane = tid & 31;
    const int wm = (wid >> 2) * 64, wn = (wid & 3) * 32;
    const int gid2 = lane >> 2, tig = lane & 3;
    #pragma unroll
    for (int mi = 0; mi < 4; mi++) {
        #pragma unroll
        for (int ni = 0; ni < 4; ni++) {
            const float* a = acc[mi][ni];
            const int nl = wn + ni * 8 + tig * 2;
            #pragma unroll
            for (int rr = 0; rr < 2; rr++) {
                const int mr = m0 + wm + mi * 16 + gid2 + rr * 8;
                const float sv0 = silu(a[rr * 2]), sv1 = silu(a[rr * 2 + 1]);
                if (by < 4) {
                    float2 o = {sv0, sv1};
                    *(float2*)(g_u + (size_t)mr * EE + by * 128 + nl) = o;
                } else {
                    const int b = mr / TT, t = mr - b * TT;
                    const int col = (by - 4) * 128 + nl;
                    *(uint32_t*)(g_vh + ((size_t)b * NP + t) * EE + col) =
                        fpack2(sv0, sv1);
                }
            }
        }
    }
}

/* ===================== K1b: q/k GEMM, 3-term; grid (1064) ================= */
__global__ __launch_bounds__(256, 2) void k_uv3_mma(
    const float* __restrict__ gamma, const float* __restrict__ beta)
{
    extern __shared__ char sm[];
    const int m0 = blockIdx.x * 128;
    float acc[4][4][4] = {};
    gemm_core32<8>(g_xh + (size_t)m0 * DD, g_xl + (size_t)m0 * DD,
                   g_wuvh + (size_t)8 * 128 * DD, g_wuvl + (size_t)8 * 128 * DD,
                   DD, DD, sm, acc);

    const int tid = threadIdx.x, wid = tid >> 5, lane = tid & 31;
    const int wm = (wid >> 2) * 64, wn = (wid & 3) * 32;
    const int gid2 = lane >> 2, tig = lane & 3;
    #pragma unroll
    for (int mi = 0; mi < 4; mi++) {
        #pragma unroll
        for (int ni = 0; ni < 4; ni++) {
            const float* a = acc[mi][ni];
            const int nl = wn + ni * 8 + tig * 2;
            #pragma unroll
            for (int rr = 0; rr < 2; rr++) {
                const int mr = m0 + wm + mi * 16 + gid2 + rr * 8;
                const float sv0 = silu(a[rr * 2]), sv1 = silu(a[rr * 2 + 1]);
                const int b = mr / TT, t = mr - b * TT;
                const float q0 = fmaf(sv0, gamma[nl],     beta[nl]);
                const float q1 = fmaf(sv1, gamma[nl + 1], beta[nl + 1]);
                const float k0 = fmaf(sv0, gamma[SSZ + nl],     beta[SSZ + nl]);
                const float k1 = fmaf(sv1, gamma[SSZ + nl + 1], beta[SSZ + nl + 1]);
                uint32_t lo, hi;
                hi = fsplit2(q0, q1, lo);
                const size_t qofs = ((size_t)b * MP + t) * SSZ + nl;
                *(uint32_t*)(g_qh + qofs) = hi;
                *(uint32_t*)(g_ql + qofs) = lo;
                hi = fsplit2(k0, k1, lo);
                const size_t kofs = ((size_t)b * NP + t) * SSZ + nl;
                *(uint32_t*)(g_kh + kofs) = hi;
                *(uint32_t*)(g_kl + kofs) = lo;
            }
        }
    }
}

/* ===================== K2+K3 fused: per-batch attention ===================== */
#define SC_QT   (MP * 32)
#define SC_KT   (NP * 32)
#define SC_STG  (2*SC_QT + 2*SC_KT)
#define FA_PH   (2 * SC_STG)
#define FA_PROW 400
#define FA_PSZ  (MP * FA_PROW)
#define FA_VROW 528
#define FA_VT   (16 * FA_VROW)          /* 8448: single-limb V stage */
#define FA_SMEM (FA_PH + FA_PSZ)        /* 109056 */

__global__ __launch_bounds__(512, 1) void k_fa()
{
    extern __shared__ char fsm[];
    const uint32_t sb = smem_u32(fsm);
    const uint32_t P0 = sb + FA_PH;
    const int b = blockIdx.x;
    const int tid = threadIdx.x, wid = tid >> 5, lane = tid & 31;

    /* ------------- phase 1: scores (3-term) ------------- */
    {
        const int wm = (wid >> 3) * 80, wn = (wid & 7) * 24;

        auto load = [&](int kc, int s) {
            const uint32_t st = sb + s * SC_STG;
            if (tid < 2 * MP) {
                const int row = tid >> 1, off = tid & 1;
                const size_t gofs = ((size_t)b * MP + row) * SSZ + kc * 16 + off * 8;
                CPA16(st + row * 32 + off * 16,         g_qh + gofs);
                CPA16(st + SC_QT + row * 32 + off * 16, g_ql + gofs);
            }
            if (tid < 2 * NP) {
                const int row = tid >> 1, off = tid & 1;
                const size_t gofs = ((size_t)b * NP + row) * SSZ + kc * 16 + off * 8;
                CPA16(st + 2*SC_QT + row * 32 + off * 16,         g_kh + gofs);
                CPA16(st + 2*SC_QT + SC_KT + row * 32 + off * 16, g_kl + gofs);
            }
        };

        float acc[5][3][4] = {};
        load(0, 0); CPC();

        #pragma unroll 1
        for (int c = 0; c < 8; c++) {
            const int s = c & 1;
            if (c + 1 < 8) { load(c + 1, 1 - s); CPC(); CPW1(); }
            else           { CPW0(); }
            __syncthreads();

            const uint32_t qb = sb + s * SC_STG;
            const uint32_t kb = qb + 2 * SC_QT, klb = kb + SC_KT;

            uint32_t bh[6], bl[6];
            {
                const int br = wn + ((lane >> 4) & 1) * 8 + (lane & 7);
                const uint32_t bc = ((lane >> 3) & 1) * 16;
                ldsm4(bh, kb  + br * 32 + bc);
                ldsm4(bl, klb + br * 32 + bc);
                const int br2 = wn + 16 + (lane & 7);
                ldsm2(bh + 4, kb  + br2 * 32 + bc);
                ldsm2(bl + 4, klb + br2 * 32 + bc);
            }
            const int arow = wm + (lane & 15);
            const uint32_t acolb = (lane >> 4) * 16;
            #pragma unroll
            for (int mi = 0; mi < 5; mi++) {
                uint32_t ah[4], al[4];
                const uint32_t aa = qb + (arow + mi * 16) * 32 + acolb;
                ldsm4(ah, aa); ldsm4(al, aa + SC_QT);
                #pragma unroll
                for (int nb = 0; nb < 3; nb++)
                    mma16816(acc[mi][nb], ah, bh[2 * nb], bh[2 * nb + 1]);
                #pragma unroll
                for (int nb = 0; nb < 3; nb++)
                    mma16816(acc[mi][nb], ah, bl[2 * nb], bl[2 * nb + 1]);
                #pragma unroll
                for (int nb = 0; nb < 3; nb++)
                    mma16816(acc[mi][nb], al, bh[2 * nb], bh[2 * nb + 1]);
            }
            __syncthreads();
        }

        #pragma unroll
        for (int mi = 0; mi < 5; mi++) {
            #pragma unroll
            for (int nb = 0; nb < 3; nb++) {
                const int j = wn + nb * 8 + (lane & 3) * 2;
                #pragma unroll
                for (int rr = 0; rr < 2; rr++) {
                    const int i = wm + mi * 16 + (lane >> 2) + rr * 8;
                    float s0 = fmaxf(acc[mi][nb][rr * 2]     * INV_SQRT_S, 0.f);
                    float s1 = fmaxf(acc[mi][nb][rr * 2 + 1] * INV_SQRT_S, 0.f);
                    uint32_t hi = fpack2(s0 * s0, s1 * s1);
                    asm volatile("st.shared.b32 [%0], %1;"
                                 :: "r"(P0 + i * FA_PROW + j * 2), "r"(hi) : "memory");
                }
            }
        }
    }
    __syncthreads();

    /* ------------- phase 2: w = u * (P @ v), N=256, V single fp16 ------- */
    {
        const int wm = (wid >> 3) * 80, wn = (wid & 7) * 32;

        #pragma unroll 1
        for (int ep = 0; ep < 2; ep++) {
            const int e0 = ep * 256;

            /* V tile per stage: 16 rows x 256 cols x 2B = 8192B; 512 thr x 1 cp */
            auto loadv = [&](int kc, int s) {
                const uint32_t st = sb + s * FA_VT;
                const int row = tid >> 5, ch = tid & 31;
                const size_t gofs = ((size_t)b * NP + kc * 16 + row) * EE + e0 + ch * 8;
                CPA16(st + row * FA_VROW + ch * 16, g_vh + gofs);
            };

            float acc[5][4][4] = {};
            loadv(0, 0); CPC();

            #pragma unroll 1
            for (int c = 0; c < 12; c++) {
                const int s = c & 1;
                if (c + 1 < 12) { loadv(c + 1, 1 - s); CPC(); CPW1(); }
                else            { CPW0(); }
                __syncthreads();

                const uint32_t vbh = sb + s * FA_VT;
                uint32_t bh[4][2];
                const int l16 = lane & 15;
                #pragma unroll
                for (int nb = 0; nb < 4; nb++)
                    ldsm2t(bh[nb], vbh + l16 * FA_VROW + (wn + nb * 8) * 2);
                const int arow = wm + (lane & 15);
                const uint32_t ac = (c * 16 + (lane >> 4) * 8) * 2;
                #pragma unroll
                for (int mi = 0; mi < 5; mi++) {
                    uint32_t ah[4];
                    ldsm4(ah, P0 + (arow + mi * 16) * FA_PROW + ac);
                    #pragma unroll
                    for (int nb = 0; nb < 4; nb++)
                        mma16816(acc[mi][nb], ah, bh[nb][0], bh[nb][1]);
                }
                __syncthreads();
            }

            #pragma unroll
            for (int mi = 0; mi < 5; mi++) {
                #pragma unroll
                for (int nb = 0; nb < 4; nb++) {
                    const int e = e0 + wn + nb * 8 + (lane & 3) * 2;
                    #pragma unroll
                    for (int rr = 0; rr < 2; rr++) {
                        const int i = wm + mi * 16 + (lane >> 2) + rr * 8;
                        if (i < TT) {
                            const size_t m = (size_t)b * TT + i;
                            float2 uu = *(const float2*)(g_u + m * EE + e);
                            *(uint32_t*)(g_ww + m * EE + e) =
                                fpack2(uu.x * acc[mi][nb][rr * 2],
                                       uu.y * acc[mi][nb][rr * 2 + 1]);
                        }
                    }
                }
            }
        }
    }
}

/* ===================== K4: out GEMM (pure fp16); grid (2, 1064) =========== */
__global__ __launch_bounds__(256, 2) void k_out_mma(
    const float* __restrict__ x, const float* __restrict__ res_scale,
    float* __restrict__ out)
{
    extern __shared__ char sm[];
    const int m0 = blockIdx.y * 128, by = blockIdx.x;
    float acc[4][4][4] = {};
    gemm_core_ff<16>(g_ww + (size_t)m0 * EE,
                     g_wo + (size_t)by * 128 * EE,
                     EE, EE, sm, acc);

    const int tid = threadIdx.x, wid = tid >> 5, lane = tid & 31;
    const int wm = (wid >> 2) * 64, wn = (wid & 3) * 32;
    const int gid2 = lane >> 2, tig = lane & 3;
    #pragma unroll
    for (int mi = 0; mi < 4; mi++) {
        #pragma unroll
        for (int ni = 0; ni < 4; ni++) {
            const float* a = acc[mi][ni];
            const int col = by * 128 + wn + ni * 8 + tig * 2;
            const int mr = m0 + wm + mi * 16 + gid2;
            float2 rv = *(const float2*)(res_scale + col);
            float2 x0 = *(const float2*)(x + (size_t)mr * DD + col);
            float2 x1 = *(const float2*)(x + (size_t)(mr + 8) * DD + col);
            float2 o0 = {fmaf(x0.x, rv.x, a[0]), fmaf(x0.y, rv.y, a[1])};
            float2 o1 = {fmaf(x1.x, rv.x, a[2]), fmaf(x1.y, rv.y, a[3])};
            *(float2*)(out + (size_t)mr * DD + col)       = o0;
            *(float2*)(out + (size_t)(mr + 8) * DD + col) = o1;
        }
    }
}

/* ===================== launch ===================== */
extern "C" void kernel_launch(void* const* d_in, const int* in_sizes, int n_in,
                              void* d_out, int out_size)
{
    const float* x         = (const float*)d_in[0];
    const float* W_uv      = (const float*)d_in[1];
    const float* W_o       = (const float*)d_in[2];
    const float* gamma     = (const float*)d_in[3];
    const float* beta      = (const float*)d_in[4];
    const float* g         = (const float*)d_in[5];
    const float* res_scale = (const float*)d_in[6];
    float* out = (float*)d_out;

    const int gsm  = 2 * STAGEB;    /* 81920 */
    const int gsm3 = 2 * STAGEB3;   /* 61440 */
    const int gsm2 = 2 * STAGEB2;   /* 40960 */
    cudaFuncSetAttribute(k_uv2_mma, cudaFuncAttributeMaxDynamicSharedMemorySize, gsm3);
    cudaFuncSetAttribute(k_uv3_mma, cudaFuncAttributeMaxDynamicSharedMemorySize, gsm);
    cudaFuncSetAttribute(k_out_mma, cudaFuncAttributeMaxDynamicSharedMemorySize, gsm2);
    cudaFuncSetAttribute(k_fa,      cudaFuncAttributeMaxDynamicSharedMemorySize, FA_SMEM);

    k_norm_cvt<<<MTOT / 8, 256>>>(x, g);
    k_cvt_wuv<<<(1152 * DD / 4 + 255) / 256, 256>>>(W_uv, 1152 * DD / 4);
    k_cvt_wo<<<(DD * EE / 4 + 255) / 256, 256>>>(W_o, DD * EE / 4);
    k_uv2_mma<<<dim3(8, MTOT / 128), 256, gsm3>>>();
    k_uv3_mma<<<MTOT / 128, 256, gsm>>>(gamma, beta);
    k_fa<<<BB, 512, FA_SMEM>>>();
    k_out_mma<<<dim3(2, MTOT / 128), 256, gsm2>>>(x, res_scale, out);
}

// round 16
// speedup vs baseline: 4.0096x; 1.1393x over previous
#include <cuda_runtime.h>
#include <cuda_fp16.h>
#include <cstdint>
#include <math.h>

#define BB   1024
#define TT   133
#define DD   256
#define EE   512
#define SSZ  128
#define MTOT (BB*TT)          /* 136192 */
#define MP   160
#define NP   192
#define EPSV 1e-5f
#define INV_SQRT_S 0.08838834764831845f

/* -------- scratch (device globals, 16B-aligned). Pad regions stay BSS-zero. */
__device__ __align__(16) float  g_u[(size_t)MTOT * EE];
__device__ __align__(16) __half g_xh[(size_t)MTOT * DD];
__device__ __align__(16) __half g_xl[(size_t)MTOT * DD];
__device__ __align__(16) __half g_ww[(size_t)MTOT * EE];
__device__ __align__(16) __half g_wuvh[1152 * DD];
__device__ __align__(16) __half g_wuvl[128 * DD];           /* lo limb: q/k block only */
__device__ __align__(16) __half g_wo[DD * EE];
__device__ __align__(16) __half g_qh[(size_t)BB * MP * SSZ];
__device__ __align__(16) __half g_ql[(size_t)BB * MP * SSZ];
__device__ __align__(16) __half g_kh[(size_t)BB * NP * SSZ];
__device__ __align__(16) __half g_kl[(size_t)BB * NP * SSZ];
__device__ __align__(16) __half g_vh[(size_t)BB * NP * EE];

/* ================= helpers ================= */
__device__ __forceinline__ uint32_t smem_u32(const void* p) {
    uint32_t a;
    asm("{ .reg .u64 t; cvta.to.shared.u64 t, %1; cvt.u32.u64 %0, t; }" : "=r"(a) : "l"(p));
    return a;
}
#define CPA16(dst, src) asm volatile("cp.async.cg.shared.global [%0], [%1], 16;" \
    :: "r"(dst), "l"(__cvta_generic_to_global(src)))
#define CPC()  asm volatile("cp.async.commit_group;")
#define CPW1() asm volatile("cp.async.wait_group 1;")
#define CPW0() asm volatile("cp.async.wait_group 0;")

__device__ __forceinline__ void ldsm4(uint32_t* r, uint32_t addr) {
    asm volatile("ldmatrix.sync.aligned.m8n8.x4.shared.b16 {%0,%1,%2,%3}, [%4];"
                 : "=r"(r[0]), "=r"(r[1]), "=r"(r[2]), "=r"(r[3]) : "r"(addr));
}
__device__ __forceinline__ void ldsm2(uint32_t* r, uint32_t addr) {
    asm volatile("ldmatrix.sync.aligned.m8n8.x2.shared.b16 {%0,%1}, [%2];"
                 : "=r"(r[0]), "=r"(r[1]) : "r"(addr));
}
__device__ __forceinline__ void ldsm2t(uint32_t* r, uint32_t addr) {
    asm volatile("ldmatrix.sync.aligned.m8n8.x2.trans.shared.b16 {%0,%1}, [%2];"
                 : "=r"(r[0]), "=r"(r[1]) : "r"(addr));
}
__device__ __forceinline__ void mma16816(float* d, const uint32_t* a,
                                         uint32_t b0, uint32_t b1) {
    asm volatile("mma.sync.aligned.m16n8k16.row.col.f32.f16.f16.f32 "
                 "{%0,%1,%2,%3}, {%4,%5,%6,%7}, {%8,%9}, {%0,%1,%2,%3};"
                 : "+f"(d[0]), "+f"(d[1]), "+f"(d[2]), "+f"(d[3])
                 : "r"(a[0]), "r"(a[1]), "r"(a[2]), "r"(a[3]), "r"(b0), "r"(b1));
}
__device__ __forceinline__ float silu(float v) { return v / (1.f + __expf(-v)); }

__device__ __forceinline__ uint32_t fsplit2(float a, float b, uint32_t& lo) {
    __half ha = __float2half(a), hb = __float2half(b);
    __half la = __float2half(a - __half2float(ha));
    __half lb = __float2half(b - __half2float(hb));
    __half2 hh = __halves2half2(ha, hb);
    __half2 ll = __halves2half2(la, lb);
    lo = reinterpret_cast<uint32_t&>(ll);
    return reinterpret_cast<uint32_t&>(hh);
}
__device__ __forceinline__ uint32_t fpack2(float a, float b) {
    __half2 h = __halves2half2(__float2half(a), __float2half(b));
    return reinterpret_cast<uint32_t&>(h);
}

/* ===================== BK=32 dense GEMM cores (dynamic smem) ============= */
#define ROWB   80
#define TILEB  10240
#define STAGEB  40960         /* 4 tiles: Ah Al Bh Bl (k_uv3) */
#define STAGEB2 20480         /* 2 tiles: A B (k_uv2, k_out)  */

template<int NCH>
__device__ __forceinline__ void gemm_core32(
    const __half* gAh, const __half* gAl, const __half* gBh, const __half* gBl,
    int lda, int ldb, char* sm, float acc[4][4][4])
{
    const int tid = threadIdx.x, wid = tid >> 5, lane = tid & 31;
    const int wm = (wid >> 2) * 64, wn = (wid & 3) * 32;
    const int r = tid >> 1, qp = (tid & 1) * 2;
    const uint32_t s0 = smem_u32(sm);

    auto load = [&](int kc, int s) {
        const uint32_t da = s0 + s * STAGEB + r * ROWB + qp * 16;
        const int kofs = kc * 32 + qp * 8;
        const __half* pa = gAh + (size_t)r * lda + kofs;
        const __half* pl = gAl + (size_t)r * lda + kofs;
        const __half* pb = gBh + (size_t)r * ldb + kofs;
        const __half* pc = gBl + (size_t)r * ldb + kofs;
        CPA16(da,                pa); CPA16(da + 16,                pa + 8);
        CPA16(da + TILEB,        pl); CPA16(da + TILEB + 16,        pl + 8);
        CPA16(da + 2*TILEB,      pb); CPA16(da + 2*TILEB + 16,      pb + 8);
        CPA16(da + 3*TILEB,      pc); CPA16(da + 3*TILEB + 16,      pc + 8);
    };

    load(0, 0); CPC();

    #pragma unroll 1
    for (int c = 0; c < NCH; c++) {
        const int s = c & 1;
        if (c + 1 < NCH) { load(c + 1, 1 - s); CPC(); CPW1(); }
        else             { CPW0(); }
        __syncthreads();

        const uint32_t base = s0 + s * STAGEB;
        const uint32_t boff = base + 2 * TILEB;
        #pragma unroll
        for (int ks = 0; ks < 2; ks++) {
            uint32_t bh[8], bl[8];
            const int brow = wn + ((lane >> 4) & 1) * 8 + (lane & 7);
            const uint32_t bcolb = ks * 32 + ((lane >> 3) & 1) * 16;
            const uint32_t ba0 = boff + brow * ROWB + bcolb;
            const uint32_t ba1 = ba0 + 16 * ROWB;
            ldsm4(bh,     ba0);          ldsm4(bh + 4, ba1);
            ldsm4(bl,     ba0 + TILEB);  ldsm4(bl + 4, ba1 + TILEB);

            const int arow = wm + (lane & 15);
            const uint32_t acolb = ks * 32 + (lane >> 4) * 16;
            #pragma unroll
            for (int mi = 0; mi < 4; mi++) {
                uint32_t ah[4], al[4];
                const uint32_t aa = base + (arow + mi * 16) * ROWB + acolb;
                ldsm4(ah, aa); ldsm4(al, aa + TILEB);
                #pragma unroll
                for (int ni = 0; ni < 4; ni++)
                    mma16816(acc[mi][ni], ah, bh[2 * ni], bh[2 * ni + 1]);
                #pragma unroll
                for (int ni = 0; ni < 4; ni++)
                    mma16816(acc[mi][ni], ah, bl[2 * ni], bl[2 * ni + 1]);
                #pragma unroll
                for (int ni = 0; ni < 4; ni++)
                    mma16816(acc[mi][ni], al, bh[2 * ni], bh[2 * ni + 1]);
            }
        }
        __syncthreads();
    }
}

/* Pure fp16: D = A B; stage = 2 tiles. */
template<int NCH>
__device__ __forceinline__ void gemm_core_ff(
    const __half* gA, const __half* gB,
    int lda, int ldb, char* sm, float acc[4][4][4])
{
    const int tid = threadIdx.x, wid = tid >> 5, lane = tid & 31;
    const int wm = (wid >> 2) * 64, wn = (wid & 3) * 32;
    const int r = tid >> 1, qp = (tid & 1) * 2;
    const uint32_t s0 = smem_u32(sm);

    auto load = [&](int kc, int s) {
        const uint32_t da = s0 + s * STAGEB2 + r * ROWB + qp * 16;
        const int kofs = kc * 32 + qp * 8;
        const __half* pa = gA + (size_t)r * lda + kofs;
        const __half* pb = gB + (size_t)r * ldb + kofs;
        CPA16(da,            pa); CPA16(da + 16,            pa + 8);
        CPA16(da + TILEB,    pb); CPA16(da + TILEB + 16,    pb + 8);
    };

    load(0, 0); CPC();

    #pragma unroll 1
    for (int c = 0; c < NCH; c++) {
        const int s = c & 1;
        if (c + 1 < NCH) { load(c + 1, 1 - s); CPC(); CPW1(); }
        else             { CPW0(); }
        __syncthreads();

        const uint32_t base = s0 + s * STAGEB2;
        const uint32_t boff = base + TILEB;
        #pragma unroll
        for (int ks = 0; ks < 2; ks++) {
            uint32_t bh[8];
            const int brow = wn + ((lane >> 4) & 1) * 8 + (lane & 7);
            const uint32_t bcolb = ks * 32 + ((lane >> 3) & 1) * 16;
            const uint32_t ba0 = boff + brow * ROWB + bcolb;
            ldsm4(bh, ba0); ldsm4(bh + 4, ba0 + 16 * ROWB);

            const int arow = wm + (lane & 15);
            const uint32_t acolb = ks * 32 + (lane >> 4) * 16;
            #pragma unroll
            for (int mi = 0; mi < 4; mi++) {
                uint32_t ah[4];
                ldsm4(ah, base + (arow + mi * 16) * ROWB + acolb);
                #pragma unroll
                for (int ni = 0; ni < 4; ni++)
                    mma16816(acc[mi][ni], ah, bh[2 * ni], bh[2 * ni + 1]);
            }
        }
        __syncthreads();
    }
}

/* ===================== K0: fused norm + fp16 split of xn ===================== */
__global__ __launch_bounds__(256) void k_norm_cvt(
    const float* __restrict__ x, const float* __restrict__ g)
{
    const int token = blockIdx.x * 8 + (threadIdx.x >> 5);
    const int lane  = threadIdx.x & 31;
    const float4* xp = (const float4*)(x + (size_t)token * DD);
    float4 v0 = xp[lane], v1 = xp[lane + 32];
    float sum = v0.x * v0.x + v0.y * v0.y + v0.z * v0.z + v0.w * v0.w
              + v1.x * v1.x + v1.y * v1.y + v1.z * v1.z + v1.w * v1.w;
    #pragma unroll
    for (int o = 16; o; o >>= 1) sum += __shfl_xor_sync(0xFFFFFFFFu, sum, o);
    float norm = sqrtf(sum * (1.f / (float)DD));
    float s = g[0] / fmaxf(norm, EPSV);

    uint2 h0, l0, h1, l1;
    h0.x = fsplit2(v0.x * s, v0.y * s, l0.x);
    h0.y = fsplit2(v0.z * s, v0.w * s, l0.y);
    h1.x = fsplit2(v1.x * s, v1.y * s, l1.x);
    h1.y = fsplit2(v1.z * s, v1.w * s, l1.y);
    const size_t base = (size_t)token * DD + lane * 4;
    *(uint2*)(g_xh + base)       = h0;
    *(uint2*)(g_xl + base)       = l0;
    *(uint2*)(g_xh + base + 128) = h1;
    *(uint2*)(g_xl + base + 128) = l1;
}

/* ===================== weight conversions (device-side dest) ======== */
/* W_uv: hi limb for all 1152 rows; lo limb only for rows [1024,1152) (q/k). */
__global__ __launch_bounds__(256) void k_cvt_wuv(
    const float* __restrict__ src, int n4)
{
    const int i = blockIdx.x * 256 + threadIdx.x;
    if (i >= n4) return;
    float4 v = ((const float4*)src)[i];
    uint2 h, l;
    h.x = fsplit2(v.x, v.y, l.x);
    h.y = fsplit2(v.z, v.w, l.y);
    *(uint2*)(g_wuvh + (size_t)i * 4) = h;
    const int qk0 = 1024 * DD / 4;          /* first q/k element /4 */
    if (i >= qk0) *(uint2*)(g_wuvl + (size_t)(i - qk0) * 4) = l;
}
__global__ __launch_bounds__(256) void k_cvt_wo(
    const float* __restrict__ src, int n4)
{
    const int i = blockIdx.x * 256 + threadIdx.x;
    if (i >= n4) return;
    float4 v = ((const float4*)src)[i];
    uint2 h;
    h.x = fpack2(v.x, v.y);
    h.y = fpack2(v.z, v.w);
    *(uint2*)(g_wo + (size_t)i * 4) = h;
}

/* ===================== K1a: u/v GEMM, pure fp16; grid (8, 1064) =========== */
__global__ __launch_bounds__(256, 2) void k_uv2_mma()
{
    extern __shared__ char sm[];
    const int m0 = blockIdx.y * 128, by = blockIdx.x;
    float acc[4][4][4] = {};
    gemm_core_ff<8>(g_xh + (size_t)m0 * DD,
                    g_wuvh + (size_t)by * 128 * DD,
                    DD, DD, sm, acc);

    const int tid = threadIdx.x, wid = tid >> 5, lane = tid & 31;
    const int wm = (wid >> 2) * 64, wn = (wid & 3) * 32;
    const int gid2 = lane >> 2, tig = lane & 3;
    #pragma unroll
    for (int mi = 0; mi < 4; mi++) {
        #pragma unroll
        for (int ni = 0; ni < 4; ni++) {
            const float* a = acc[mi][ni];
            const int nl = wn + ni * 8 + tig * 2;
            #pragma unroll
            for (int rr = 0; rr < 2; rr++) {
                const int mr = m0 + wm + mi * 16 + gid2 + rr * 8;
                const float sv0 = silu(a[rr * 2]), sv1 = silu(a[rr * 2 + 1]);
                if (by < 4) {
                    float2 o = {sv0, sv1};
                    *(float2*)(g_u + (size_t)mr * EE + by * 128 + nl) = o;
                } else {
                    const int b = mr / TT, t = mr - b * TT;
                    const int col = (by - 4) * 128 + nl;
                    *(uint32_t*)(g_vh + ((size_t)b * NP + t) * EE + col) =
                        fpack2(sv0, sv1);
                }
            }
        }
    }
}

/* ===================== K1b: q/k GEMM, 3-term; grid (1064) ================= */
__global__ __launch_bounds__(256, 2) void k_uv3_mma(
    const float* __restrict__ gamma, const float* __restrict__ beta)
{
    extern __shared__ char sm[];
    const int m0 = blockIdx.x * 128;
    float acc[4][4][4] = {};
    gemm_core32<8>(g_xh + (size_t)m0 * DD, g_xl + (size_t)m0 * DD,
                   g_wuvh + (size_t)8 * 128 * DD, g_wuvl,
                   DD, DD, sm, acc);

    const int tid = threadIdx.x, wid = tid >> 5, lane = tid & 31;
    const int wm = (wid >> 2) * 64, wn = (wid & 3) * 32;
    const int gid2 = lane >> 2, tig = lane & 3;
    #pragma unroll
    for (int mi = 0; mi < 4; mi++) {
        #pragma unroll
        for (int ni = 0; ni < 4; ni++) {
            const float* a = acc[mi][ni];
            const int nl = wn + ni * 8 + tig * 2;
            #pragma unroll
            for (int rr = 0; rr < 2; rr++) {
                const int mr = m0 + wm + mi * 16 + gid2 + rr * 8;
                const float sv0 = silu(a[rr * 2]), sv1 = silu(a[rr * 2 + 1]);
                const int b = mr / TT, t = mr - b * TT;
                const float q0 = fmaf(sv0, gamma[nl],     beta[nl]);
                const float q1 = fmaf(sv1, gamma[nl + 1], beta[nl + 1]);
                const float k0 = fmaf(sv0, gamma[SSZ + nl],     beta[SSZ + nl]);
                const float k1 = fmaf(sv1, gamma[SSZ + nl + 1], beta[SSZ + nl + 1]);
                uint32_t lo, hi;
                hi = fsplit2(q0, q1, lo);
                const size_t qofs = ((size_t)b * MP + t) * SSZ + nl;
                *(uint32_t*)(g_qh + qofs) = hi;
                *(uint32_t*)(g_ql + qofs) = lo;
                hi = fsplit2(k0, k1, lo);
                const size_t kofs = ((size_t)b * NP + t) * SSZ + nl;
                *(uint32_t*)(g_kh + kofs) = hi;
                *(uint32_t*)(g_kl + kofs) = lo;
            }
        }
    }
}

/* ===================== K2+K3 fused: per-batch attention ===================== */
#define SC_QT   (MP * 32)
#define SC_KT   (NP * 32)
#define SC_STG  (2*SC_QT + 2*SC_KT)
#define FA_PH   (2 * SC_STG)
#define FA_PROW 400
#define FA_PSZ  (MP * FA_PROW)
#define FA_VROW 528
#define FA_VT   (16 * FA_VROW)
#define FA_SMEM (FA_PH + FA_PSZ)        /* 109056 */

__global__ __launch_bounds__(512, 1) void k_fa()
{
    extern __shared__ char fsm[];
    const uint32_t sb = smem_u32(fsm);
    const uint32_t P0 = sb + FA_PH;
    const int b = blockIdx.x;
    const int tid = threadIdx.x, wid = tid >> 5, lane = tid & 31;

    /* ------------- phase 1: scores (3-term) ------------- */
    {
        const int wm = (wid >> 3) * 80, wn = (wid & 7) * 24;

        auto load = [&](int kc, int s) {
            const uint32_t st = sb + s * SC_STG;
            if (tid < 2 * MP) {
                const int row = tid >> 1, off = tid & 1;
                const size_t gofs = ((size_t)b * MP + row) * SSZ + kc * 16 + off * 8;
                CPA16(st + row * 32 + off * 16,         g_qh + gofs);
                CPA16(st + SC_QT + row * 32 + off * 16, g_ql + gofs);
            }
            if (tid < 2 * NP) {
                const int row = tid >> 1, off = tid & 1;
                const size_t gofs = ((size_t)b * NP + row) * SSZ + kc * 16 + off * 8;
                CPA16(st + 2*SC_QT + row * 32 + off * 16,         g_kh + gofs);
                CPA16(st + 2*SC_QT + SC_KT + row * 32 + off * 16, g_kl + gofs);
            }
        };

        float acc[5][3][4] = {};
        load(0, 0); CPC();

        #pragma unroll 1
        for (int c = 0; c < 8; c++) {
            const int s = c & 1;
            if (c + 1 < 8) { load(c + 1, 1 - s); CPC(); CPW1(); }
            else           { CPW0(); }
            __syncthreads();

            const uint32_t qb = sb + s * SC_STG;
            const uint32_t kb = qb + 2 * SC_QT, klb = kb + SC_KT;

            uint32_t bh[6], bl[6];
            {
                const int br = wn + ((lane >> 4) & 1) * 8 + (lane & 7);
                const uint32_t bc = ((lane >> 3) & 1) * 16;
                ldsm4(bh, kb  + br * 32 + bc);
                ldsm4(bl, klb + br * 32 + bc);
                const int br2 = wn + 16 + (lane & 7);
                ldsm2(bh + 4, kb  + br2 * 32 + bc);
                ldsm2(bl + 4, klb + br2 * 32 + bc);
            }
            const int arow = wm + (lane & 15);
            const uint32_t acolb = (lane >> 4) * 16;
            #pragma unroll
            for (int mi = 0; mi < 5; mi++) {
                uint32_t ah[4], al[4];
                const uint32_t aa = qb + (arow + mi * 16) * 32 + acolb;
                ldsm4(ah, aa); ldsm4(al, aa + SC_QT);
                #pragma unroll
                for (int nb = 0; nb < 3; nb++)
                    mma16816(acc[mi][nb], ah, bh[2 * nb], bh[2 * nb + 1]);
                #pragma unroll
                for (int nb = 0; nb < 3; nb++)
                    mma16816(acc[mi][nb], ah, bl[2 * nb], bl[2 * nb + 1]);
                #pragma unroll
                for (int nb = 0; nb < 3; nb++)
                    mma16816(acc[mi][nb], al, bh[2 * nb], bh[2 * nb + 1]);
            }
            __syncthreads();
        }

        #pragma unroll
        for (int mi = 0; mi < 5; mi++) {
            #pragma unroll
            for (int nb = 0; nb < 3; nb++) {
                const int j = wn + nb * 8 + (lane & 3) * 2;
                #pragma unroll
                for (int rr = 0; rr < 2; rr++) {
                    const int i = wm + mi * 16 + (lane >> 2) + rr * 8;
                    float s0 = fmaxf(acc[mi][nb][rr * 2]     * INV_SQRT_S, 0.f);
                    float s1 = fmaxf(acc[mi][nb][rr * 2 + 1] * INV_SQRT_S, 0.f);
                    uint32_t hi = fpack2(s0 * s0, s1 * s1);
                    asm volatile("st.shared.b32 [%0], %1;"
                                 :: "r"(P0 + i * FA_PROW + j * 2), "r"(hi) : "memory");
                }
            }
        }
    }
    __syncthreads();

    /* ------------- phase 2: w = u * (P @ v), N=256, V single fp16 ------- */
    {
        const int wm = (wid >> 3) * 80, wn = (wid & 7) * 32;

        #pragma unroll 1
        for (int ep = 0; ep < 2; ep++) {
            const int e0 = ep * 256;

            auto loadv = [&](int kc, int s) {
                const uint32_t st = sb + s * FA_VT;
                const int row = tid >> 5, ch = tid & 31;
                const size_t gofs = ((size_t)b * NP + kc * 16 + row) * EE + e0 + ch * 8;
                CPA16(st + row * FA_VROW + ch * 16, g_vh + gofs);
            };

            float acc[5][4][4] = {};
            loadv(0, 0); CPC();

            #pragma unroll 1
            for (int c = 0; c < 12; c++) {
                const int s = c & 1;
                if (c + 1 < 12) { loadv(c + 1, 1 - s); CPC(); CPW1(); }
                else            { CPW0(); }
                __syncthreads();

                const uint32_t vbh = sb + s * FA_VT;
                uint32_t bh[4][2];
                const int l16 = lane & 15;
                #pragma unroll
                for (int nb = 0; nb < 4; nb++)
                    ldsm2t(bh[nb], vbh + l16 * FA_VROW + (wn + nb * 8) * 2);
                const int arow = wm + (lane & 15);
                const uint32_t ac = (c * 16 + (lane >> 4) * 8) * 2;
                #pragma unroll
                for (int mi = 0; mi < 5; mi++) {
                    uint32_t ah[4];
                    ldsm4(ah, P0 + (arow + mi * 16) * FA_PROW + ac);
                    #pragma unroll
                    for (int nb = 0; nb < 4; nb++)
                        mma16816(acc[mi][nb], ah, bh[nb][0], bh[nb][1]);
                }
                __syncthreads();
            }

            #pragma unroll
            for (int mi = 0; mi < 5; mi++) {
                #pragma unroll
                for (int nb = 0; nb < 4; nb++) {
                    const int e = e0 + wn + nb * 8 + (lane & 3) * 2;
                    #pragma unroll
                    for (int rr = 0; rr < 2; rr++) {
                        const int i = wm + mi * 16 + (lane >> 2) + rr * 8;
                        if (i < TT) {
                            const size_t m = (size_t)b * TT + i;
                            float2 uu = *(const float2*)(g_u + m * EE + e);
                            *(uint32_t*)(g_ww + m * EE + e) =
                                fpack2(uu.x * acc[mi][nb][rr * 2],
                                       uu.y * acc[mi][nb][rr * 2 + 1]);
                        }
                    }
                }
            }
        }
    }
}

/* ===================== K4: out GEMM (pure fp16); grid (2, 1064) =========== */
__global__ __launch_bounds__(256, 2) void k_out_mma(
    const float* __restrict__ x, const float* __restrict__ res_scale,
    float* __restrict__ out)
{
    extern __shared__ char sm[];
    const int m0 = blockIdx.y * 128, by = blockIdx.x;
    float acc[4][4][4] = {};
    gemm_core_ff<16>(g_ww + (size_t)m0 * EE,
                     g_wo + (size_t)by * 128 * EE,
                     EE, EE, sm, acc);

    const int tid = threadIdx.x, wid = tid >> 5, lane = tid & 31;
    const int wm = (wid >> 2) * 64, wn = (wid & 3) * 32;
    const int gid2 = lane >> 2, tig = lane & 3;
    #pragma unroll
    for (int mi = 0; mi < 4; mi++) {
        #pragma unroll
        for (int ni = 0; ni < 4; ni++) {
            const float* a = acc[mi][ni];
            const int col = by * 128 + wn + ni * 8 + tig * 2;
            const int mr = m0 + wm + mi * 16 + gid2;
            float2 rv = *(const float2*)(res_scale + col);
            float2 x0 = *(const float2*)(x + (size_t)mr * DD + col);
            float2 x1 = *(const float2*)(x + (size_t)(mr + 8) * DD + col);
            float2 o0 = {fmaf(x0.x, rv.x, a[0]), fmaf(x0.y, rv.y, a[1])};
            float2 o1 = {fmaf(x1.x, rv.x, a[2]), fmaf(x1.y, rv.y, a[3])};
            *(float2*)(out + (size_t)mr * DD + col)       = o0;
            *(float2*)(out + (size_t)(mr + 8) * DD + col) = o1;
        }
    }
}

/* ===================== launch ===================== */
extern "C" void kernel_launch(void* const* d_in, const int* in_sizes, int n_in,
                              void* d_out, int out_size)
{
    const float* x         = (const float*)d_in[0];
    const float* W_uv      = (const float*)d_in[1];
    const float* W_o       = (const float*)d_in[2];
    const float* gamma     = (const float*)d_in[3];
    const float* beta      = (const float*)d_in[4];
    const float* g         = (const float*)d_in[5];
    const float* res_scale = (const float*)d_in[6];
    float* out = (float*)d_out;

    const int gsm  = 2 * STAGEB;    /* 81920 */
    const int gsm2 = 2 * STAGEB2;   /* 40960 */
    cudaFuncSetAttribute(k_uv2_mma, cudaFuncAttributeMaxDynamicSharedMemorySize, gsm2);
    cudaFuncSetAttribute(k_uv3_mma, cudaFuncAttributeMaxDynamicSharedMemorySize, gsm);
    cudaFuncSetAttribute(k_out_mma, cudaFuncAttributeMaxDynamicSharedMemorySize, gsm2);
    cudaFuncSetAttribute(k_fa,      cudaFuncAttributeMaxDynamicSharedMemorySize, FA_SMEM);

    k_norm_cvt<<<MTOT / 8, 256>>>(x, g);
    k_cvt_wuv<<<(1152 * DD / 4 + 255) / 256, 256>>>(W_uv, 1152 * DD / 4);
    k_cvt_wo<<<(DD * EE / 4 + 255) / 256, 256>>>(W_o, DD * EE / 4);
    k_uv2_mma<<<dim3(8, MTOT / 128), 256, gsm2>>>();
    k_uv3_mma<<<MTOT / 128, 256, gsm>>>(gamma, beta);
    k_fa<<<BB, 512, FA_SMEM>>>();
    k_out_mma<<<dim3(2, MTOT / 128), 256, gsm2>>>(x, res_scale, out);
}

// round 17
// speedup vs baseline: 4.3937x; 1.0958x over previous
#include <cuda_runtime.h>
#include <cuda_fp16.h>
#include <cstdint>
#include <math.h>

#define BB   1024
#define TT   133
#define DD   256
#define EE   512
#define SSZ  128
#define MTOT (BB*TT)          /* 136192 */
#define MP   160
#define NP   192
#define EPSV 1e-5f
#define INV_SQRT_S 0.08838834764831845f

/* -------- scratch (device globals, 16B-aligned). Pad regions stay BSS-zero. */
__device__ __align__(16) float  g_u[(size_t)MTOT * EE];
__device__ __align__(16) __half g_xh[(size_t)MTOT * DD];
__device__ __align__(16) __half g_ww[(size_t)MTOT * EE];
__device__ __align__(16) __half g_wuv[1152 * DD];
__device__ __align__(16) __half g_wo[DD * EE];
__device__ __align__(16) __half g_q[(size_t)BB * MP * SSZ];
__device__ __align__(16) __half g_k[(size_t)BB * NP * SSZ];
__device__ __align__(16) __half g_vh[(size_t)BB * NP * EE];

/* ================= helpers ================= */
__device__ __forceinline__ uint32_t smem_u32(const void* p) {
    uint32_t a;
    asm("{ .reg .u64 t; cvta.to.shared.u64 t, %1; cvt.u32.u64 %0, t; }" : "=r"(a) : "l"(p));
    return a;
}
#define CPA16(dst, src) asm volatile("cp.async.cg.shared.global [%0], [%1], 16;" \
    :: "r"(dst), "l"(__cvta_generic_to_global(src)))
#define CPC()  asm volatile("cp.async.commit_group;")
#define CPW1() asm volatile("cp.async.wait_group 1;")
#define CPW0() asm volatile("cp.async.wait_group 0;")

__device__ __forceinline__ void ldsm4(uint32_t* r, uint32_t addr) {
    asm volatile("ldmatrix.sync.aligned.m8n8.x4.shared.b16 {%0,%1,%2,%3}, [%4];"
                 : "=r"(r[0]), "=r"(r[1]), "=r"(r[2]), "=r"(r[3]) : "r"(addr));
}
__device__ __forceinline__ void ldsm2(uint32_t* r, uint32_t addr) {
    asm volatile("ldmatrix.sync.aligned.m8n8.x2.shared.b16 {%0,%1}, [%2];"
                 : "=r"(r[0]), "=r"(r[1]) : "r"(addr));
}
__device__ __forceinline__ void ldsm2t(uint32_t* r, uint32_t addr) {
    asm volatile("ldmatrix.sync.aligned.m8n8.x2.trans.shared.b16 {%0,%1}, [%2];"
                 : "=r"(r[0]), "=r"(r[1]) : "r"(addr));
}
__device__ __forceinline__ void mma16816(float* d, const uint32_t* a,
                                         uint32_t b0, uint32_t b1) {
    asm volatile("mma.sync.aligned.m16n8k16.row.col.f32.f16.f16.f32 "
                 "{%0,%1,%2,%3}, {%4,%5,%6,%7}, {%8,%9}, {%0,%1,%2,%3};"
                 : "+f"(d[0]), "+f"(d[1]), "+f"(d[2]), "+f"(d[3])
                 : "r"(a[0]), "r"(a[1]), "r"(a[2]), "r"(a[3]), "r"(b0), "r"(b1));
}
__device__ __forceinline__ float silu(float v) { return v / (1.f + __expf(-v)); }
__device__ __forceinline__ uint32_t fpack2(float a, float b) {
    __half2 h = __halves2half2(__float2half(a), __float2half(b));
    return reinterpret_cast<uint32_t&>(h);
}

/* ===================== BK=32 pure-fp16 GEMM core (dynamic smem) ========== */
#define ROWB   80
#define TILEB  10240
#define STAGEB2 20480         /* 2 tiles: A B */

template<int NCH>
__device__ __forceinline__ void gemm_core_ff(
    const __half* gA, const __half* gB,
    int lda, int ldb, char* sm, float acc[4][4][4])
{
    const int tid = threadIdx.x, wid = tid >> 5, lane = tid & 31;
    const int wm = (wid >> 2) * 64, wn = (wid & 3) * 32;
    const int r = tid >> 1, qp = (tid & 1) * 2;
    const uint32_t s0 = smem_u32(sm);

    auto load = [&](int kc, int s) {
        const uint32_t da = s0 + s * STAGEB2 + r * ROWB + qp * 16;
        const int kofs = kc * 32 + qp * 8;
        const __half* pa = gA + (size_t)r * lda + kofs;
        const __half* pb = gB + (size_t)r * ldb + kofs;
        CPA16(da,            pa); CPA16(da + 16,            pa + 8);
        CPA16(da + TILEB,    pb); CPA16(da + TILEB + 16,    pb + 8);
    };

    load(0, 0); CPC();

    #pragma unroll 1
    for (int c = 0; c < NCH; c++) {
        const int s = c & 1;
        if (c + 1 < NCH) { load(c + 1, 1 - s); CPC(); CPW1(); }
        else             { CPW0(); }
        __syncthreads();

        const uint32_t base = s0 + s * STAGEB2;
        const uint32_t boff = base + TILEB;
        #pragma unroll
        for (int ks = 0; ks < 2; ks++) {
            uint32_t bh[8];
            const int brow = wn + ((lane >> 4) & 1) * 8 + (lane & 7);
            const uint32_t bcolb = ks * 32 + ((lane >> 3) & 1) * 16;
            const uint32_t ba0 = boff + brow * ROWB + bcolb;
            ldsm4(bh, ba0); ldsm4(bh + 4, ba0 + 16 * ROWB);

            const int arow = wm + (lane & 15);
            const uint32_t acolb = ks * 32 + (lane >> 4) * 16;
            #pragma unroll
            for (int mi = 0; mi < 4; mi++) {
                uint32_t ah[4];
                ldsm4(ah, base + (arow + mi * 16) * ROWB + acolb);
                #pragma unroll
                for (int ni = 0; ni < 4; ni++)
                    mma16816(acc[mi][ni], ah, bh[2 * ni], bh[2 * ni + 1]);
            }
        }
        __syncthreads();
    }
}

/* ===================== K0: fused norm + fp16 pack of xn ===================== */
__global__ __launch_bounds__(256) void k_norm_cvt(
    const float* __restrict__ x, const float* __restrict__ g)
{
    const int token = blockIdx.x * 8 + (threadIdx.x >> 5);
    const int lane  = threadIdx.x & 31;
    const float4* xp = (const float4*)(x + (size_t)token * DD);
    float4 v0 = xp[lane], v1 = xp[lane + 32];
    float sum = v0.x * v0.x + v0.y * v0.y + v0.z * v0.z + v0.w * v0.w
              + v1.x * v1.x + v1.y * v1.y + v1.z * v1.z + v1.w * v1.w;
    #pragma unroll
    for (int o = 16; o; o >>= 1) sum += __shfl_xor_sync(0xFFFFFFFFu, sum, o);
    float norm = sqrtf(sum * (1.f / (float)DD));
    float s = g[0] / fmaxf(norm, EPSV);

    uint2 h0, h1;
    h0.x = fpack2(v0.x * s, v0.y * s);
    h0.y = fpack2(v0.z * s, v0.w * s);
    h1.x = fpack2(v1.x * s, v1.y * s);
    h1.y = fpack2(v1.z * s, v1.w * s);
    const size_t base = (size_t)token * DD + lane * 4;
    *(uint2*)(g_xh + base)       = h0;
    *(uint2*)(g_xh + base + 128) = h1;
}

/* ===================== weight fp16 pack (device-side dest) ======== */
__global__ __launch_bounds__(256) void k_cvt_w(
    const float* __restrict__ src, int which, int n4)
{
    __half* dst = which ? g_wo : g_wuv;
    const int i = blockIdx.x * 256 + threadIdx.x;
    if (i >= n4) return;
    float4 v = ((const float4*)src)[i];
    uint2 h;
    h.x = fpack2(v.x, v.y);
    h.y = fpack2(v.z, v.w);
    *(uint2*)(dst + (size_t)i * 4) = h;
}

/* ===================== K1: uv GEMM (pure fp16); grid (9, 1064) ============ */
__global__ __launch_bounds__(256, 2) void k_uv_mma(
    const float* __restrict__ gamma, const float* __restrict__ beta)
{
    extern __shared__ char sm[];
    const int m0 = blockIdx.y * 128, by = blockIdx.x;
    float acc[4][4][4] = {};
    gemm_core_ff<8>(g_xh + (size_t)m0 * DD,
                    g_wuv + (size_t)by * 128 * DD,
                    DD, DD, sm, acc);

    const int tid = threadIdx.x, wid = tid >> 5, lane = tid & 31;
    const int wm = (wid >> 2) * 64, wn = (wid & 3) * 32;
    const int gid2 = lane >> 2, tig = lane & 3;
    #pragma unroll
    for (int mi = 0; mi < 4; mi++) {
        #pragma unroll
        for (int ni = 0; ni < 4; ni++) {
            const float* a = acc[mi][ni];
            const int nl = wn + ni * 8 + tig * 2;
            #pragma unroll
            for (int rr = 0; rr < 2; rr++) {
                const int mr = m0 + wm + mi * 16 + gid2 + rr * 8;
                const float sv0 = silu(a[rr * 2]), sv1 = silu(a[rr * 2 + 1]);
                if (by < 4) {
                    float2 o = {sv0, sv1};
                    *(float2*)(g_u + (size_t)mr * EE + by * 128 + nl) = o;
                } else if (by < 8) {
                    const int b = mr / TT, t = mr - b * TT;
                    const int col = (by - 4) * 128 + nl;
                    *(uint32_t*)(g_vh + ((size_t)b * NP + t) * EE + col) =
                        fpack2(sv0, sv1);
                } else {
                    const int b = mr / TT, t = mr - b * TT;
                    const float q0 = fmaf(sv0, gamma[nl],     beta[nl]);
                    const float q1 = fmaf(sv1, gamma[nl + 1], beta[nl + 1]);
                    const float k0 = fmaf(sv0, gamma[SSZ + nl],     beta[SSZ + nl]);
                    const float k1 = fmaf(sv1, gamma[SSZ + nl + 1], beta[SSZ + nl + 1]);
                    *(uint32_t*)(g_q + ((size_t)b * MP + t) * SSZ + nl) = fpack2(q0, q1);
                    *(uint32_t*)(g_k + ((size_t)b * NP + t) * SSZ + nl) = fpack2(k0, k1);
                }
            }
        }
    }
}

/* ===================== K2+K3 fused: per-batch attention =====================
 * Phase 1: S = q k^T (pure fp16, BK=32, 4 chunks), P = relu(S/sqrt)^2 -> SMEM.
 * Phase 2: 2 passes of N=256: attn = P v, w = u*attn -> fp16. */
#define SC_QT   (MP * 80)               /* 12800 */
#define SC_KT   (NP * 80)               /* 15360 */
#define SC_STG  (SC_QT + SC_KT)         /* 28160 */
#define FA_PH   (2 * SC_STG)            /* 56320: P offset */
#define FA_PROW 400
#define FA_PSZ  (MP * FA_PROW)          /* 64000 */
#define FA_VROW 528
#define FA_VT   (16 * FA_VROW)          /* 8448 */
#define FA_SMEM (FA_PH + FA_PSZ)        /* 120320 */

__global__ __launch_bounds__(512, 1) void k_fa()
{
    extern __shared__ char fsm[];
    const uint32_t sb = smem_u32(fsm);
    const uint32_t P0 = sb + FA_PH;
    const int b = blockIdx.x;
    const int tid = threadIdx.x, wid = tid >> 5, lane = tid & 31;

    /* ------------- phase 1: scores (pure fp16, BK=32) ------------- */
    {
        const int wm = (wid >> 3) * 80, wn = (wid & 7) * 24;

        auto load = [&](int kc, int s) {
            const uint32_t st = sb + s * SC_STG;
            if (tid < 2 * MP) {
                const int row = tid >> 1, off = (tid & 1) * 16;   /* halves */
                const size_t gofs = ((size_t)b * MP + row) * SSZ + kc * 32 + off;
                const uint32_t d = st + row * ROWB + off * 2;
                CPA16(d, g_q + gofs); CPA16(d + 16, g_q + gofs + 8);
            }
            if (tid < 2 * NP) {
                const int row = tid >> 1, off = (tid & 1) * 16;
                const size_t gofs = ((size_t)b * NP + row) * SSZ + kc * 32 + off;
                const uint32_t d = st + SC_QT + row * ROWB + off * 2;
                CPA16(d, g_k + gofs); CPA16(d + 16, g_k + gofs + 8);
            }
        };

        float acc[5][3][4] = {};
        load(0, 0); CPC();

        #pragma unroll 1
        for (int c = 0; c < 4; c++) {
            const int s = c & 1;
            if (c + 1 < 4) { load(c + 1, 1 - s); CPC(); CPW1(); }
            else           { CPW0(); }
            __syncthreads();

            const uint32_t qb = sb + s * SC_STG;
            const uint32_t kb = qb + SC_QT;

            #pragma unroll
            for (int ks = 0; ks < 2; ks++) {
                uint32_t bh[6];
                {
                    const int br = wn + ((lane >> 4) & 1) * 8 + (lane & 7);
                    const uint32_t bc = ks * 32 + ((lane >> 3) & 1) * 16;
                    ldsm4(bh, kb + br * ROWB + bc);
                    const int br2 = wn + 16 + (lane & 7);
                    ldsm2(bh + 4, kb + br2 * ROWB + bc);
                }
                const int arow = wm + (lane & 15);
                const uint32_t acolb = ks * 32 + (lane >> 4) * 16;
                #pragma unroll
                for (int mi = 0; mi < 5; mi++) {
                    uint32_t ah[4];
                    ldsm4(ah, qb + (arow + mi * 16) * ROWB + acolb);
                    #pragma unroll
                    for (int nb = 0; nb < 3; nb++)
                        mma16816(acc[mi][nb], ah, bh[2 * nb], bh[2 * nb + 1]);
                }
            }
            __syncthreads();
        }

        /* epilogue -> smem P (fp16) */
        #pragma unroll
        for (int mi = 0; mi < 5; mi++) {
            #pragma unroll
            for (int nb = 0; nb < 3; nb++) {
                const int j = wn + nb * 8 + (lane & 3) * 2;
                #pragma unroll
                for (int rr = 0; rr < 2; rr++) {
                    const int i = wm + mi * 16 + (lane >> 2) + rr * 8;
                    float s0 = fmaxf(acc[mi][nb][rr * 2]     * INV_SQRT_S, 0.f);
                    float s1 = fmaxf(acc[mi][nb][rr * 2 + 1] * INV_SQRT_S, 0.f);
                    uint32_t hi = fpack2(s0 * s0, s1 * s1);
                    asm volatile("st.shared.b32 [%0], %1;"
                                 :: "r"(P0 + i * FA_PROW + j * 2), "r"(hi) : "memory");
                }
            }
        }
    }
    __syncthreads();

    /* ------------- phase 2: w = u * (P @ v), N=256 ------------- */
    {
        const int wm = (wid >> 3) * 80, wn = (wid & 7) * 32;

        #pragma unroll 1
        for (int ep = 0; ep < 2; ep++) {
            const int e0 = ep * 256;

            auto loadv = [&](int kc, int s) {
                const uint32_t st = sb + s * FA_VT;
                const int row = tid >> 5, ch = tid & 31;
                const size_t gofs = ((size_t)b * NP + kc * 16 + row) * EE + e0 + ch * 8;
                CPA16(st + row * FA_VROW + ch * 16, g_vh + gofs);
            };

            float acc[5][4][4] = {};
            loadv(0, 0); CPC();

            #pragma unroll 1
            for (int c = 0; c < 12; c++) {
                const int s = c & 1;
                if (c + 1 < 12) { loadv(c + 1, 1 - s); CPC(); CPW1(); }
                else            { CPW0(); }
                __syncthreads();

                const uint32_t vbh = sb + s * FA_VT;
                uint32_t bh[4][2];
                const int l16 = lane & 15;
                #pragma unroll
                for (int nb = 0; nb < 4; nb++)
                    ldsm2t(bh[nb], vbh + l16 * FA_VROW + (wn + nb * 8) * 2);
                const int arow = wm + (lane & 15);
                const uint32_t ac = (c * 16 + (lane >> 4) * 8) * 2;
                #pragma unroll
                for (int mi = 0; mi < 5; mi++) {
                    uint32_t ah[4];
                    ldsm4(ah, P0 + (arow + mi * 16) * FA_PROW + ac);
                    #pragma unroll
                    for (int nb = 0; nb < 4; nb++)
                        mma16816(acc[mi][nb], ah, bh[nb][0], bh[nb][1]);
                }
                __syncthreads();
            }

            #pragma unroll
            for (int mi = 0; mi < 5; mi++) {
                #pragma unroll
                for (int nb = 0; nb < 4; nb++) {
                    const int e = e0 + wn + nb * 8 + (lane & 3) * 2;
                    #pragma unroll
                    for (int rr = 0; rr < 2; rr++) {
                        const int i = wm + mi * 16 + (lane >> 2) + rr * 8;
                        if (i < TT) {
                            const size_t m = (size_t)b * TT + i;
                            float2 uu = *(const float2*)(g_u + m * EE + e);
                            *(uint32_t*)(g_ww + m * EE + e) =
                                fpack2(uu.x * acc[mi][nb][rr * 2],
                                       uu.y * acc[mi][nb][rr * 2 + 1]);
                        }
                    }
                }
            }
        }
    }
}

/* ===================== K4: out GEMM (pure fp16); grid (2, 1064) =========== */
__global__ __launch_bounds__(256, 2) void k_out_mma(
    const float* __restrict__ x, const float* __restrict__ res_scale,
    float* __restrict__ out)
{
    extern __shared__ char sm[];
    const int m0 = blockIdx.y * 128, by = blockIdx.x;
    float acc[4][4][4] = {};
    gemm_core_ff<16>(g_ww + (size_t)m0 * EE,
                     g_wo + (size_t)by * 128 * EE,
                     EE, EE, sm, acc);

    const int tid = threadIdx.x, wid = tid >> 5, lane = tid & 31;
    const int wm = (wid >> 2) * 64, wn = (wid & 3) * 32;
    const int gid2 = lane >> 2, tig = lane & 3;
    #pragma unroll
    for (int mi = 0; mi < 4; mi++) {
        #pragma unroll
        for (int ni = 0; ni < 4; ni++) {
            const float* a = acc[mi][ni];
            const int col = by * 128 + wn + ni * 8 + tig * 2;
            const int mr = m0 + wm + mi * 16 + gid2;
            float2 rv = *(const float2*)(res_scale + col);
            float2 x0 = *(const float2*)(x + (size_t)mr * DD + col);
            float2 x1 = *(const float2*)(x + (size_t)(mr + 8) * DD + col);
            float2 o0 = {fmaf(x0.x, rv.x, a[0]), fmaf(x0.y, rv.y, a[1])};
            float2 o1 = {fmaf(x1.x, rv.x, a[2]), fmaf(x1.y, rv.y, a[3])};
            *(float2*)(out + (size_t)mr * DD + col)       = o0;
            *(float2*)(out + (size_t)(mr + 8) * DD + col) = o1;
        }
    }
}

/* ===================== launch ===================== */
extern "C" void kernel_launch(void* const* d_in, const int* in_sizes, int n_in,
                              void* d_out, int out_size)
{
    const float* x         = (const float*)d_in[0];
    const float* W_uv      = (const float*)d_in[1];
    const float* W_o       = (const float*)d_in[2];
    const float* gamma     = (const float*)d_in[3];
    const float* beta      = (const float*)d_in[4];
    const float* g         = (const float*)d_in[5];
    const float* res_scale = (const float*)d_in[6];
    float* out = (float*)d_out;

    const int gsm2 = 2 * STAGEB2;   /* 40960 */
    cudaFuncSetAttribute(k_uv_mma,  cudaFuncAttributeMaxDynamicSharedMemorySize, gsm2);
    cudaFuncSetAttribute(k_out_mma, cudaFuncAttributeMaxDynamicSharedMemorySize, gsm2);
    cudaFuncSetAttribute(k_fa,      cudaFuncAttributeMaxDynamicSharedMemorySize, FA_SMEM);

    k_norm_cvt<<<MTOT / 8, 256>>>(x, g);
    k_cvt_w<<<(1152 * DD / 4 + 255) / 256, 256>>>(W_uv, 0, 1152 * DD / 4);
    k_cvt_w<<<(DD * EE / 4 + 255) / 256, 256>>>(W_o, 1, DD * EE / 4);
    k_uv_mma<<<dim3(9, MTOT / 128), 256, gsm2>>>(gamma, beta);
    k_fa<<<BB, 512, FA_SMEM>>>();
    k_out_mma<<<dim3(2, MTOT / 128), 256, gsm2>>>(x, res_scale, out);
}